// round 3
// baseline (speedup 1.0000x reference)
#include <cuda_runtime.h>
#include <math.h>

#define BB 2
#define NN 4096
#define DD 64
#define HH 256
#define KK 16
#define NPTS (BB*NN)
#define GRID3 148
#define PTS 8               // points per iteration
#define ROWS 128            // PTS * KK rows
#define RP 66               // padded row stride for h / s1

// ---------------- scratch ----------------------------------------------------
__device__ float g_qkv[NPTS*192];      // q|k|v per point
__device__ int   g_idx[NPTS*KK];       // knn indices
__device__ float g_y[NPTS*DD];         // pre-BN output of fc
__device__ float g_part[GRID3*2*DD];   // per-block partial sum / sumsq
__device__ float g_mv[2*DD];           // mean, rstd

// ---------------- kernel 1: QKV GEMM  (8192x64 @ 64x192) -------------------
__global__ void qkv_kernel(const float* __restrict__ x,
                           const float* __restrict__ w,
                           const float* __restrict__ bq) {
    extern __shared__ float sm[];
    float* ws = sm;             // 64*192
    float* xs = sm + 64*192;    // 64*64
    int tid = threadIdx.x;      // 192 threads
    for (int i = tid; i < 64*192; i += 192) ws[i] = w[i];
    int row0 = blockIdx.x * 64;
    for (int i = tid; i < 64*64; i += 192) xs[i] = x[row0*64 + i];
    __syncthreads();
    float bb = bq[tid];
    for (int r0 = 0; r0 < 64; r0 += 8) {
        float acc[8];
#pragma unroll
        for (int r = 0; r < 8; r++) acc[r] = bb;
        for (int i = 0; i < 64; i++) {
            float wv = ws[i*192 + tid];
#pragma unroll
            for (int r = 0; r < 8; r++) acc[r] = fmaf(xs[(r0+r)*64 + i], wv, acc[r]);
        }
#pragma unroll
        for (int r = 0; r < 8; r++) g_qkv[(row0 + r0 + r)*192 + tid] = acc[r];
    }
}

// ---------------- kernel 2: exact KNN (top-16 smallest (dist, idx)) --------
__device__ __forceinline__ bool lexless(float d1, int i1, float d2, int i2) {
    return (d1 < d2) || (d1 == d2 && i1 < i2);
}

__global__ void knn_kernel(const float* __restrict__ pos) {
    extern __shared__ float sm[];
    float* posX = sm;                 // NN
    float* posY = posX + NN;          // NN
    float* posZ = posY + NN;          // NN
    float* md   = posZ + NN;          // 8*512
    int*   mi   = (int*)(md + 8*512); // 8*512
    int tid = threadIdx.x;
    int warp = tid >> 5, lane = tid & 31;
    int b = blockIdx.x / (NN/8);
    int n = (blockIdx.x % (NN/8))*8 + warp;
    const float* posB = pos + (size_t)b*NN*3;
    for (int i = tid; i < NN; i += 256) {
        posX[i] = posB[i*3+0];
        posY[i] = posB[i*3+1];
        posZ[i] = posB[i*3+2];
    }
    __syncthreads();
    float px = posX[n], py = posY[n], pz = posZ[n];

    float bd[16]; int bi[16];
#pragma unroll
    for (int j = 0; j < 16; j++) { bd[j] = 3.0e38f; bi[j] = 0x7fff0000 + j; }
    float wd = 3.0e38f; int wi = 0x7fff000F;

    for (int c = lane; c < NN; c += 32) {
        float dx = px - posX[c];
        float dy = py - posY[c];
        float dz = pz - posZ[c];
        float d2 = __fadd_rn(__fadd_rn(__fmul_rn(dx,dx), __fmul_rn(dy,dy)),
                             __fmul_rn(dz,dz));
        float thr2 = __fmul_rn(__fmul_rn(wd, wd), 1.0000005f);
        if (d2 <= thr2) {
            float d = sqrtf(d2);
            if (lexless(d, c, wd, wi)) {
#pragma unroll
                for (int j = 0; j < 16; j++)
                    if (bd[j] == wd && bi[j] == wi) { bd[j] = d; bi[j] = c; }
                wd = bd[0]; wi = bi[0];
#pragma unroll
                for (int j = 1; j < 16; j++)
                    if (lexless(wd, wi, bd[j], bi[j])) { wd = bd[j]; wi = bi[j]; }
            }
        }
    }
    float* mdw = md + warp*512;
    int*   miw = mi + warp*512;
#pragma unroll
    for (int j = 0; j < 16; j++) { mdw[j*32 + lane] = bd[j]; miw[j*32 + lane] = bi[j]; }
    __syncwarp();
    int outbase = (b*NN + n)*KK;
    for (int r = 0; r < 16; r++) {
        float cd = 3.0e38f; int ci = 0x7fffffff; int cpos = 0;
#pragma unroll
        for (int j = 0; j < 16; j++) {
            float dv = mdw[j*32 + lane]; int iv = miw[j*32 + lane];
            if (lexless(dv, iv, cd, ci)) { cd = dv; ci = iv; cpos = j*32 + lane; }
        }
#pragma unroll
        for (int off = 16; off > 0; off >>= 1) {
            float od = __shfl_down_sync(0xffffffffu, cd, off);
            int   oi = __shfl_down_sync(0xffffffffu, ci, off);
            int   op = __shfl_down_sync(0xffffffffu, cpos, off);
            if (lexless(od, oi, cd, ci)) { cd = od; ci = oi; cpos = op; }
        }
        if (lane == 0) { g_idx[outbase + r] = ci; mdw[cpos] = 3.0e38f; }
        __syncwarp();
    }
}

// ---------------- kernel 3: fused gather + MLPs + softmax + fc -------------
// 8 points/iter => 128 GEMM rows; 4r x 8c register tiles (32 accumulators).
__global__ __launch_bounds__(256, 1)
void attn_kernel(const float* __restrict__ pos,
                 const float* __restrict__ w_p1, const float* __restrict__ b_p1,
                 const float* __restrict__ w_p2, const float* __restrict__ b_p2,
                 const float* __restrict__ w_a1, const float* __restrict__ b_a1,
                 const float* __restrict__ w_a2, const float* __restrict__ b_a2,
                 const float* __restrict__ w_fc, const float* __restrict__ b_fc) {
    extern __shared__ float sm[];
    float* w_a1s = sm;                 // 16384 [d][j]
    float* w_a2s = w_a1s + 16384;      // 16384 [j][d]
    float* w_p2s = w_a2s + 16384;      // 4096  [p][d]
    float* w_p1s = w_p2s + 4096;       // 192
    float* b_p1s = w_p1s + 192;        // 64
    float* b_p2s = b_p1s + 64;         // 64
    float* b_a1s = b_p2s + 64;         // 256
    float* b_a2s = b_a1s + 256;        // 64
    float* b_fcs = b_a2s + 64;         // 64
    float* qs    = b_fcs + 64;         // 512  (8 x 64)
    float* p0s   = qs + 512;           // 32   (8 x 4)
    float* rel   = p0s + 32;           // 384  (128 x 3)
    float* aggs  = rel + 384;          // 512
    float* h     = aggs + 512;         // 128*66
    float* s1    = h + ROWS*RP;        // 128*66  (t1 -> s1 chunk -> scores)
    int*   sidx  = (int*)(s1 + ROWS*RP); // 128

    int tid = threadIdx.x;
    for (int i = tid; i < 16384; i += 256) w_a1s[i] = w_a1[i];
    for (int i = tid; i < 16384; i += 256) w_a2s[i] = w_a2[i];
    for (int i = tid; i < 4096;  i += 256) w_p2s[i] = w_p2[i];
    if (tid < 192) w_p1s[tid] = w_p1[tid];
    b_a1s[tid] = b_a1[tid];
    if (tid < 64) {
        b_p1s[tid] = b_p1[tid]; b_p2s[tid] = b_p2[tid];
        b_a2s[tid] = b_a2[tid]; b_fcs[tid] = b_fc[tid];
    }
    float accY = 0.0f, accY2 = 0.0f;   // BN partials (d = tid & 63 fixed)

    const int rt = tid >> 3;            // 0..31
    const int ct = tid & 7;             // 0..7
    const int r0 = rt * 4;
    const int c0 = ct * 8;
    __syncthreads();

    for (int g = blockIdx.x; g < NPTS/PTS; g += gridDim.x) {
        int pbase = g * PTS;
        int bofs = (pbase >> 12) << 12;

        // ---- per-point loads
        if (tid < 128) sidx[tid] = g_idx[pbase*KK + tid];
#pragma unroll
        for (int e = 0; e < 2; e++) {
            int i = tid + e*256;
            int l = i >> 6, d = i & 63;
            qs[i] = g_qkv[(size_t)(pbase + l)*192 + d];
        }
        if (tid < 24) {
            int l = tid / 3, c = tid - l*3;
            p0s[l*4 + c] = pos[(size_t)(pbase + l)*3 + c];
        }
        __syncthreads();

        // ---- gather: h = q - k_nb
#pragma unroll
        for (int e = 0; e < 32; e++) {
            int i = tid + e*256;
            int r = i >> 6, d = i & 63;
            int l = r >> 4;
            h[r*RP + d] = qs[l*64 + d] -
                          g_qkv[(size_t)(bofs + sidx[r])*192 + 64 + d];
        }
        for (int i = tid; i < 384; i += 256) {
            int r = i / 3, c = i - r*3;
            int l = r >> 4;
            rel[i] = p0s[l*4 + c] - pos[(size_t)(bofs + sidx[r])*3 + c];
        }
        __syncthreads();

        // ---- pos-MLP hidden: t1 = relu(rel @ w_p1 + b_p1) -> s1[r][p]
#pragma unroll
        for (int e = 0; e < 32; e++) {
            int i = tid + e*256;
            int r = i >> 6, pp = i & 63;
            float a = b_p1s[pp];
            a = fmaf(rel[r*3+0], w_p1s[pp],       a);
            a = fmaf(rel[r*3+1], w_p1s[64 + pp],  a);
            a = fmaf(rel[r*3+2], w_p1s[128 + pp], a);
            s1[r*RP + pp] = fmaxf(a, 0.0f);
        }
        __syncthreads();

        // ---- h += t1 @ w_p2 + b_p2
        {
            float acc[32];
#pragma unroll
            for (int z = 0; z < 32; z++) acc[z] = 0.0f;
#pragma unroll 8
            for (int k = 0; k < 64; k++) {
                float4 wa = *(const float4*)&w_p2s[k*64 + c0];
                float4 wb = *(const float4*)&w_p2s[k*64 + c0 + 4];
                float t0 = s1[(r0+0)*RP + k];
                float t1v = s1[(r0+1)*RP + k];
                float t2 = s1[(r0+2)*RP + k];
                float t3 = s1[(r0+3)*RP + k];
                acc[0]  = fmaf(t0, wa.x, acc[0]);  acc[1]  = fmaf(t0, wa.y, acc[1]);
                acc[2]  = fmaf(t0, wa.z, acc[2]);  acc[3]  = fmaf(t0, wa.w, acc[3]);
                acc[4]  = fmaf(t0, wb.x, acc[4]);  acc[5]  = fmaf(t0, wb.y, acc[5]);
                acc[6]  = fmaf(t0, wb.z, acc[6]);  acc[7]  = fmaf(t0, wb.w, acc[7]);
                acc[8]  = fmaf(t1v, wa.x, acc[8]); acc[9]  = fmaf(t1v, wa.y, acc[9]);
                acc[10] = fmaf(t1v, wa.z, acc[10]);acc[11] = fmaf(t1v, wa.w, acc[11]);
                acc[12] = fmaf(t1v, wb.x, acc[12]);acc[13] = fmaf(t1v, wb.y, acc[13]);
                acc[14] = fmaf(t1v, wb.z, acc[14]);acc[15] = fmaf(t1v, wb.w, acc[15]);
                acc[16] = fmaf(t2, wa.x, acc[16]); acc[17] = fmaf(t2, wa.y, acc[17]);
                acc[18] = fmaf(t2, wa.z, acc[18]); acc[19] = fmaf(t2, wa.w, acc[19]);
                acc[20] = fmaf(t2, wb.x, acc[20]); acc[21] = fmaf(t2, wb.y, acc[21]);
                acc[22] = fmaf(t2, wb.z, acc[22]); acc[23] = fmaf(t2, wb.w, acc[23]);
                acc[24] = fmaf(t3, wa.x, acc[24]); acc[25] = fmaf(t3, wa.y, acc[25]);
                acc[26] = fmaf(t3, wa.z, acc[26]); acc[27] = fmaf(t3, wa.w, acc[27]);
                acc[28] = fmaf(t3, wb.x, acc[28]); acc[29] = fmaf(t3, wb.y, acc[29]);
                acc[30] = fmaf(t3, wb.z, acc[30]); acc[31] = fmaf(t3, wb.w, acc[31]);
            }
            __syncthreads();   // s1 (t1) fully consumed before h update races? h distinct — but next phase overwrites s1
#pragma unroll
            for (int i = 0; i < 4; i++)
#pragma unroll
                for (int j = 0; j < 8; j++)
                    h[(r0+i)*RP + c0 + j] += acc[i*8+j] + b_p2s[c0 + j];
        }
        __syncthreads();

        // ---- attn MLP, 4 chunks of 64 hidden cols; scores accumulate in regs
        float sacc[32];
#pragma unroll
        for (int z = 0; z < 32; z++) sacc[z] = 0.0f;

        for (int jc = 0; jc < 4; jc++) {
            // GEMM1 chunk: s1 = relu(h @ w_a1[:, jc*64+..] + b)
            float acc[32];
#pragma unroll
            for (int z = 0; z < 32; z++) acc[z] = 0.0f;
#pragma unroll 8
            for (int d = 0; d < 64; d++) {
                float4 wa = *(const float4*)&w_a1s[d*256 + jc*64 + c0];
                float4 wb = *(const float4*)&w_a1s[d*256 + jc*64 + c0 + 4];
                float h0 = h[(r0+0)*RP + d];
                float h1 = h[(r0+1)*RP + d];
                float h2 = h[(r0+2)*RP + d];
                float h3 = h[(r0+3)*RP + d];
                acc[0]  = fmaf(h0, wa.x, acc[0]);  acc[1]  = fmaf(h0, wa.y, acc[1]);
                acc[2]  = fmaf(h0, wa.z, acc[2]);  acc[3]  = fmaf(h0, wa.w, acc[3]);
                acc[4]  = fmaf(h0, wb.x, acc[4]);  acc[5]  = fmaf(h0, wb.y, acc[5]);
                acc[6]  = fmaf(h0, wb.z, acc[6]);  acc[7]  = fmaf(h0, wb.w, acc[7]);
                acc[8]  = fmaf(h1, wa.x, acc[8]);  acc[9]  = fmaf(h1, wa.y, acc[9]);
                acc[10] = fmaf(h1, wa.z, acc[10]); acc[11] = fmaf(h1, wa.w, acc[11]);
                acc[12] = fmaf(h1, wb.x, acc[12]); acc[13] = fmaf(h1, wb.y, acc[13]);
                acc[14] = fmaf(h1, wb.z, acc[14]); acc[15] = fmaf(h1, wb.w, acc[15]);
                acc[16] = fmaf(h2, wa.x, acc[16]); acc[17] = fmaf(h2, wa.y, acc[17]);
                acc[18] = fmaf(h2, wa.z, acc[18]); acc[19] = fmaf(h2, wa.w, acc[19]);
                acc[20] = fmaf(h2, wb.x, acc[20]); acc[21] = fmaf(h2, wb.y, acc[21]);
                acc[22] = fmaf(h2, wb.z, acc[22]); acc[23] = fmaf(h2, wb.w, acc[23]);
                acc[24] = fmaf(h3, wa.x, acc[24]); acc[25] = fmaf(h3, wa.y, acc[25]);
                acc[26] = fmaf(h3, wa.z, acc[26]); acc[27] = fmaf(h3, wa.w, acc[27]);
                acc[28] = fmaf(h3, wb.x, acc[28]); acc[29] = fmaf(h3, wb.y, acc[29]);
                acc[30] = fmaf(h3, wb.z, acc[30]); acc[31] = fmaf(h3, wb.w, acc[31]);
            }
#pragma unroll
            for (int i = 0; i < 4; i++)
#pragma unroll
                for (int j = 0; j < 8; j++)
                    s1[(r0+i)*RP + c0 + j] =
                        fmaxf(acc[i*8+j] + b_a1s[jc*64 + c0 + j], 0.0f);
            __syncthreads();

            // GEMM2 chunk: sacc += s1 @ w_a2[jc*64+..][:]
#pragma unroll 8
            for (int j = 0; j < 64; j++) {
                float4 wa = *(const float4*)&w_a2s[(jc*64 + j)*64 + c0];
                float4 wb = *(const float4*)&w_a2s[(jc*64 + j)*64 + c0 + 4];
                float s0 = s1[(r0+0)*RP + j];
                float s1v = s1[(r0+1)*RP + j];
                float s2 = s1[(r0+2)*RP + j];
                float s3 = s1[(r0+3)*RP + j];
                sacc[0]  = fmaf(s0, wa.x, sacc[0]);  sacc[1]  = fmaf(s0, wa.y, sacc[1]);
                sacc[2]  = fmaf(s0, wa.z, sacc[2]);  sacc[3]  = fmaf(s0, wa.w, sacc[3]);
                sacc[4]  = fmaf(s0, wb.x, sacc[4]);  sacc[5]  = fmaf(s0, wb.y, sacc[5]);
                sacc[6]  = fmaf(s0, wb.z, sacc[6]);  sacc[7]  = fmaf(s0, wb.w, sacc[7]);
                sacc[8]  = fmaf(s1v, wa.x, sacc[8]); sacc[9]  = fmaf(s1v, wa.y, sacc[9]);
                sacc[10] = fmaf(s1v, wa.z, sacc[10]);sacc[11] = fmaf(s1v, wa.w, sacc[11]);
                sacc[12] = fmaf(s1v, wb.x, sacc[12]);sacc[13] = fmaf(s1v, wb.y, sacc[13]);
                sacc[14] = fmaf(s1v, wb.z, sacc[14]);sacc[15] = fmaf(s1v, wb.w, sacc[15]);
                sacc[16] = fmaf(s2, wa.x, sacc[16]); sacc[17] = fmaf(s2, wa.y, sacc[17]);
                sacc[18] = fmaf(s2, wa.z, sacc[18]); sacc[19] = fmaf(s2, wa.w, sacc[19]);
                sacc[20] = fmaf(s2, wb.x, sacc[20]); sacc[21] = fmaf(s2, wb.y, sacc[21]);
                sacc[22] = fmaf(s2, wb.z, sacc[22]); sacc[23] = fmaf(s2, wb.w, sacc[23]);
                sacc[24] = fmaf(s3, wa.x, sacc[24]); sacc[25] = fmaf(s3, wa.y, sacc[25]);
                sacc[26] = fmaf(s3, wa.z, sacc[26]); sacc[27] = fmaf(s3, wa.w, sacc[27]);
                sacc[28] = fmaf(s3, wb.x, sacc[28]); sacc[29] = fmaf(s3, wb.y, sacc[29]);
                sacc[30] = fmaf(s3, wb.z, sacc[30]); sacc[31] = fmaf(s3, wb.w, sacc[31]);
            }
            __syncthreads();
        }

        // ---- scores (+bias) -> s1[r][d]
#pragma unroll
        for (int i = 0; i < 4; i++)
#pragma unroll
            for (int j = 0; j < 8; j++)
                s1[(r0+i)*RP + c0 + j] = sacc[i*8+j] + b_a2s[c0 + j];
        __syncthreads();

        // ---- softmax over K + weighted v-sum (v reloaded from L2)
        for (int s = tid; s < 512; s += 256) {
            int l = s >> 6, d = s & 63;
            float vreg[16];
#pragma unroll
            for (int k = 0; k < 16; k++)
                vreg[k] = g_qkv[(size_t)(bofs + sidx[l*16 + k])*192 + 128 + d];
            float mx = -3.0e38f;
#pragma unroll
            for (int k = 0; k < 16; k++)
                mx = fmaxf(mx, s1[(l*16 + k)*RP + d]);
            float ssum = 0.0f, a = 0.0f;
#pragma unroll
            for (int k = 0; k < 16; k++) {
                float e = expf(s1[(l*16 + k)*RP + d] - mx);
                ssum += e;
                a = fmaf(e, vreg[k], a);
            }
            aggs[s] = a / ssum;
        }
        __syncthreads();

        // ---- fc (w_fc streamed from L1/L2) + BN partials
        for (int s = tid; s < 512; s += 256) {
            int l = s >> 6, d = s & 63;
            float y = b_fcs[d];
#pragma unroll 8
            for (int c = 0; c < 64; c++)
                y = fmaf(aggs[l*64 + c], w_fc[c*64 + d], y);
            g_y[(size_t)(pbase + l)*64 + d] = y;
            accY += y;
            accY2 = fmaf(y, y, accY2);
        }
        __syncthreads();
    }

    // ---- reduce BN partials across the 4 d-groups (reuse h as scratch)
    float* red = h;
    red[tid] = accY;
    __syncthreads();
    if (tid < 64) {
        g_part[blockIdx.x*128 + tid] =
            red[tid] + red[64 + tid] + red[128 + tid] + red[192 + tid];
    }
    __syncthreads();
    red[tid] = accY2;
    __syncthreads();
    if (tid < 64) {
        g_part[blockIdx.x*128 + 64 + tid] =
            red[tid] + red[64 + tid] + red[128 + tid] + red[192 + tid];
    }
}

// ---------------- kernel 4: finish BN statistics ----------------------------
__global__ void bnstats_kernel() {
    __shared__ float sred[512];
    int tid = threadIdx.x;            // 256
    int d = tid & 63, q = tid >> 6;
    float s = 0.0f, s2 = 0.0f;
    for (int blk = q; blk < GRID3; blk += 4) {
        s  += g_part[blk*128 + d];
        s2 += g_part[blk*128 + 64 + d];
    }
    sred[tid] = s; sred[256 + tid] = s2;
    __syncthreads();
    if (tid < 64) {
        float ts  = sred[d] + sred[64+d] + sred[128+d] + sred[192+d];
        float ts2 = sred[256+d] + sred[320+d] + sred[384+d] + sred[448+d];
        float mean = ts / (float)NPTS;
        float var  = ts2 / (float)NPTS - mean*mean;
        g_mv[d]      = mean;
        g_mv[64 + d] = rsqrtf(var + 1e-5f);
    }
}

// ---------------- kernel 5: BN apply + relu + residual ----------------------
__global__ void final_kernel(const float* __restrict__ x,
                             const float* __restrict__ gamma,
                             const float* __restrict__ beta,
                             float* __restrict__ out) {
    int i = blockIdx.x * blockDim.x + threadIdx.x;
    if (i < NPTS*DD) {
        int d = i & 63;
        float yv = (g_y[i] - g_mv[d]) * g_mv[64 + d] * gamma[d] + beta[d];
        out[i] = fmaxf(yv, 0.0f) + x[i];
    }
}

// ---------------- launch -----------------------------------------------------
extern "C" void kernel_launch(void* const* d_in, const int* in_sizes, int n_in,
                              void* d_out, int out_size) {
    const float* x     = (const float*)d_in[0];
    const float* pos   = (const float*)d_in[1];
    const float* w_qkv = (const float*)d_in[2];
    const float* b_qkv = (const float*)d_in[3];
    const float* w_p1  = (const float*)d_in[4];
    const float* b_p1  = (const float*)d_in[5];
    const float* w_p2  = (const float*)d_in[6];
    const float* b_p2  = (const float*)d_in[7];
    const float* w_a1  = (const float*)d_in[8];
    const float* b_a1  = (const float*)d_in[9];
    const float* w_a2  = (const float*)d_in[10];
    const float* b_a2  = (const float*)d_in[11];
    const float* w_fc  = (const float*)d_in[12];
    const float* b_fc  = (const float*)d_in[13];
    const float* gamma = (const float*)d_in[14];
    const float* beta  = (const float*)d_in[15];
    float* out = (float*)d_out;

    const int smem_qkv  = (64*192 + 64*64) * 4;
    const int smem_knn  = (3*NN + 8*512) * 4 + (8*512) * 4;
    const int smem_attn = (16384+16384+4096+192+64+64+256+64+64
                           +512+32+384+512 + ROWS*RP + ROWS*RP) * 4 + 128*4;

    cudaFuncSetAttribute(qkv_kernel,  cudaFuncAttributeMaxDynamicSharedMemorySize, smem_qkv);
    cudaFuncSetAttribute(knn_kernel,  cudaFuncAttributeMaxDynamicSharedMemorySize, smem_knn);
    cudaFuncSetAttribute(attn_kernel, cudaFuncAttributeMaxDynamicSharedMemorySize, smem_attn);

    qkv_kernel<<<NPTS/64, 192, smem_qkv>>>(x, w_qkv, b_qkv);
    knn_kernel<<<NPTS/8, 256, smem_knn>>>(pos);
    attn_kernel<<<GRID3, 256, smem_attn>>>(pos, w_p1, b_p1, w_p2, b_p2,
                                           w_a1, b_a1, w_a2, b_a2, w_fc, b_fc);
    bnstats_kernel<<<1, 256>>>();
    final_kernel<<<(NPTS*DD + 255)/256, 256>>>(x, gamma, beta, out);
}

// round 4
// speedup vs baseline: 1.2546x; 1.2546x over previous
#include <cuda_runtime.h>
#include <math.h>

#define BB 2
#define NN 4096
#define DD 64
#define HH 256
#define KK 16
#define NPTS (BB*NN)
#define ATTN_GRID 147
#define PTS 8               // points per iteration
#define ROWS 128            // PTS * KK rows
#define RP 66               // padded row stride for h / s1

typedef unsigned long long u64;

__device__ __forceinline__ u64 splat2(float a) {
    u64 r;
    asm("mov.b64 %0, {%1, %1};" : "=l"(r) : "r"(__float_as_uint(a)));
    return r;
}
__device__ __forceinline__ void fma2(u64& d, u64 a, u64 b) {
    asm("fma.rn.f32x2 %0, %1, %2, %0;" : "+l"(d) : "l"(a), "l"(b));
}
__device__ __forceinline__ float2 unpack2(u64 v) {
    unsigned int lo, hi;
    asm("mov.b64 {%0, %1}, %2;" : "=r"(lo), "=r"(hi) : "l"(v));
    return make_float2(__uint_as_float(lo), __uint_as_float(hi));
}

// ---------------- scratch ----------------------------------------------------
__device__ float g_qkv[NPTS*192];      // q|k|v per point
__device__ int   g_idx[NPTS*KK];       // knn indices
__device__ float g_y[NPTS*DD];         // pre-BN output of fc
__device__ float g_part[ATTN_GRID*2*DD];
__device__ float g_mv[2*DD];           // mean, rstd

// ---------------- kernel 1: QKV GEMM  (8192x64 @ 64x192) -------------------
__global__ void qkv_kernel(const float* __restrict__ x,
                           const float* __restrict__ w,
                           const float* __restrict__ bq) {
    extern __shared__ float sm[];
    float* ws = sm;             // 64*192
    float* xs = sm + 64*192;    // 64*64
    int tid = threadIdx.x;      // 192 threads
    for (int i = tid; i < 64*192; i += 192) ws[i] = w[i];
    int row0 = blockIdx.x * 64;
    for (int i = tid; i < 64*64; i += 192) xs[i] = x[row0*64 + i];
    __syncthreads();
    float bb = bq[tid];
    for (int r0 = 0; r0 < 64; r0 += 8) {
        float acc[8];
#pragma unroll
        for (int r = 0; r < 8; r++) acc[r] = bb;
        for (int i = 0; i < 64; i++) {
            float wv = ws[i*192 + tid];
#pragma unroll
            for (int r = 0; r < 8; r++) acc[r] = fmaf(xs[(r0+r)*64 + i], wv, acc[r]);
        }
#pragma unroll
        for (int r = 0; r < 8; r++) g_qkv[(row0 + r0 + r)*192 + tid] = acc[r];
    }
}

// ---------------- kernel 2: exact KNN (top-16 smallest (dist, idx)) --------
__device__ __forceinline__ bool lexless(float d1, int i1, float d2, int i2) {
    return (d1 < d2) || (d1 == d2 && i1 < i2);
}

__global__ void knn_kernel(const float* __restrict__ pos) {
    extern __shared__ float sm[];
    float* posX = sm;                 // NN
    float* posY = posX + NN;          // NN
    float* posZ = posY + NN;          // NN
    float* md   = posZ + NN;          // 8*512
    int*   mi   = (int*)(md + 8*512); // 8*512
    int tid = threadIdx.x;
    int warp = tid >> 5, lane = tid & 31;
    int b = blockIdx.x / (NN/8);
    int n = (blockIdx.x % (NN/8))*8 + warp;
    const float* posB = pos + (size_t)b*NN*3;
    for (int i = tid; i < NN; i += 256) {
        posX[i] = posB[i*3+0];
        posY[i] = posB[i*3+1];
        posZ[i] = posB[i*3+2];
    }
    __syncthreads();
    float px = posX[n], py = posY[n], pz = posZ[n];

    float bd[16]; int bi[16];
#pragma unroll
    for (int j = 0; j < 16; j++) { bd[j] = 3.0e38f; bi[j] = 0x7fff0000 + j; }
    float wd = 3.0e38f; int wi = 0x7fff000F;

    for (int c = lane; c < NN; c += 32) {
        float dx = px - posX[c];
        float dy = py - posY[c];
        float dz = pz - posZ[c];
        float d2 = __fadd_rn(__fadd_rn(__fmul_rn(dx,dx), __fmul_rn(dy,dy)),
                             __fmul_rn(dz,dz));
        float thr2 = __fmul_rn(__fmul_rn(wd, wd), 1.0000005f);
        if (d2 <= thr2) {
            float d = sqrtf(d2);
            if (lexless(d, c, wd, wi)) {
#pragma unroll
                for (int j = 0; j < 16; j++)
                    if (bd[j] == wd && bi[j] == wi) { bd[j] = d; bi[j] = c; }
                wd = bd[0]; wi = bi[0];
#pragma unroll
                for (int j = 1; j < 16; j++)
                    if (lexless(wd, wi, bd[j], bi[j])) { wd = bd[j]; wi = bi[j]; }
            }
        }
    }
    float* mdw = md + warp*512;
    int*   miw = mi + warp*512;
#pragma unroll
    for (int j = 0; j < 16; j++) { mdw[j*32 + lane] = bd[j]; miw[j*32 + lane] = bi[j]; }
    __syncwarp();
    int outbase = (b*NN + n)*KK;
    for (int r = 0; r < 16; r++) {
        float cd = 3.0e38f; int ci = 0x7fffffff; int cpos = 0;
#pragma unroll
        for (int j = 0; j < 16; j++) {
            float dv = mdw[j*32 + lane]; int iv = miw[j*32 + lane];
            if (lexless(dv, iv, cd, ci)) { cd = dv; ci = iv; cpos = j*32 + lane; }
        }
#pragma unroll
        for (int off = 16; off > 0; off >>= 1) {
            float od = __shfl_down_sync(0xffffffffu, cd, off);
            int   oi = __shfl_down_sync(0xffffffffu, ci, off);
            int   op = __shfl_down_sync(0xffffffffu, cpos, off);
            if (lexless(od, oi, cd, ci)) { cd = od; ci = oi; cpos = op; }
        }
        if (lane == 0) { g_idx[outbase + r] = ci; mdw[cpos] = 3.0e38f; }
        __syncwarp();
    }
}

// ---------------- kernel 3: fused gather + MLPs + softmax + fc -------------
// 512 threads, 8 points/iter (128 rows), 4r x 4c tiles, packed f32x2 FMA.
__global__ __launch_bounds__(512, 1)
void attn_kernel(const float* __restrict__ pos,
                 const float* __restrict__ w_p1, const float* __restrict__ b_p1,
                 const float* __restrict__ w_p2, const float* __restrict__ b_p2,
                 const float* __restrict__ w_a1, const float* __restrict__ b_a1,
                 const float* __restrict__ w_a2, const float* __restrict__ b_a2,
                 const float* __restrict__ w_fc, const float* __restrict__ b_fc) {
    extern __shared__ float sm[];
    float* w_a1s = sm;                 // 16384 [d][j]
    float* w_a2s = w_a1s + 16384;      // 16384 [j][d]
    float* w_p2s = w_a2s + 16384;      // 4096  [p][d]
    float* w_p1s = w_p2s + 4096;       // 192
    float* b_p1s = w_p1s + 192;        // 64
    float* b_p2s = b_p1s + 64;         // 64
    float* b_a1s = b_p2s + 64;         // 256
    float* b_a2s = b_a1s + 256;        // 64
    float* b_fcs = b_a2s + 64;         // 64
    float* qs    = b_fcs + 64;         // 512  (8 x 64)
    float* p0s   = qs + 512;           // 32   (8 x 4)
    float* rel   = p0s + 32;           // 384  (128 x 3)
    float* aggs  = rel + 384;          // 512
    float* h     = aggs + 512;         // 128*66
    float* s1    = h + ROWS*RP;        // 128*66
    int*   sidx  = (int*)(s1 + ROWS*RP); // 128

    int tid = threadIdx.x;
    for (int i = tid; i < 16384; i += 512) w_a1s[i] = w_a1[i];
    for (int i = tid; i < 16384; i += 512) w_a2s[i] = w_a2[i];
    for (int i = tid; i < 4096;  i += 512) w_p2s[i] = w_p2[i];
    if (tid < 192) w_p1s[tid] = w_p1[tid];
    if (tid < 256) b_a1s[tid] = b_a1[tid];
    if (tid < 64) {
        b_p1s[tid] = b_p1[tid]; b_p2s[tid] = b_p2[tid];
        b_a2s[tid] = b_a2[tid]; b_fcs[tid] = b_fc[tid];
    }
    float accY = 0.0f, accY2 = 0.0f;   // BN partials (d = tid & 63 fixed)

    const int rt = tid >> 4;            // 0..31
    const int ct = tid & 15;            // 0..15
    const int r0 = rt * 4;
    const int c0 = ct * 4;
    __syncthreads();

    for (int g = blockIdx.x; g < NPTS/PTS; g += ATTN_GRID) {
        int pbase = g * PTS;
        int bofs = (pbase >> 12) << 12;

        // ---- per-point loads
        if (tid < 128) sidx[tid] = g_idx[pbase*KK + tid];
        {
            int l = tid >> 6, d = tid & 63;
            qs[tid] = g_qkv[(size_t)(pbase + l)*192 + d];
        }
        if (tid < 24) {
            int l = tid / 3, c = tid - l*3;
            p0s[l*4 + c] = pos[(size_t)(pbase + l)*3 + c];
        }
        __syncthreads();

        // ---- gather: h = q - k_nb
#pragma unroll
        for (int e = 0; e < 16; e++) {
            int i = tid + e*512;
            int r = i >> 6, d = i & 63;
            int l = r >> 4;
            h[r*RP + d] = qs[l*64 + d] -
                          g_qkv[(size_t)(bofs + sidx[r])*192 + 64 + d];
        }
        if (tid < 384) {
            int r = tid / 3, c = tid - r*3;
            int l = r >> 4;
            rel[tid] = p0s[l*4 + c] - pos[(size_t)(bofs + sidx[r])*3 + c];
        }
        __syncthreads();

        // ---- pos-MLP hidden: t1 = relu(rel @ w_p1 + b_p1) -> s1[r][p]
#pragma unroll
        for (int e = 0; e < 16; e++) {
            int i = tid + e*512;
            int r = i >> 6, pp = i & 63;
            float a = b_p1s[pp];
            a = fmaf(rel[r*3+0], w_p1s[pp],       a);
            a = fmaf(rel[r*3+1], w_p1s[64 + pp],  a);
            a = fmaf(rel[r*3+2], w_p1s[128 + pp], a);
            s1[r*RP + pp] = fmaxf(a, 0.0f);
        }
        __syncthreads();

        // ---- h += t1 @ w_p2 + b_p2   (packed f32x2)
        {
            u64 acc[8] = {0,0,0,0,0,0,0,0};
#pragma unroll 8
            for (int k = 0; k < 64; k++) {
                const u64* wp = (const u64*)&w_p2s[k*64 + c0];
                u64 w0 = wp[0], w1 = wp[1];
                u64 a0 = splat2(s1[(r0+0)*RP + k]);
                u64 a1 = splat2(s1[(r0+1)*RP + k]);
                u64 a2 = splat2(s1[(r0+2)*RP + k]);
                u64 a3 = splat2(s1[(r0+3)*RP + k]);
                fma2(acc[0], a0, w0); fma2(acc[1], a0, w1);
                fma2(acc[2], a1, w0); fma2(acc[3], a1, w1);
                fma2(acc[4], a2, w0); fma2(acc[5], a2, w1);
                fma2(acc[6], a3, w0); fma2(acc[7], a3, w1);
            }
            __syncthreads();   // t1 consumed before anything overwrites s1
            float b0 = b_p2s[c0+0], b1 = b_p2s[c0+1];
            float b2 = b_p2s[c0+2], b3 = b_p2s[c0+3];
#pragma unroll
            for (int i = 0; i < 4; i++) {
                float2 lo = unpack2(acc[i*2+0]);
                float2 hi = unpack2(acc[i*2+1]);
                float* hp = &h[(r0+i)*RP + c0];
                hp[0] += lo.x + b0; hp[1] += lo.y + b1;
                hp[2] += hi.x + b2; hp[3] += hi.y + b3;
            }
        }
        __syncthreads();

        // ---- attn MLP: 4 chunks of 64 hidden cols; scores stay in regs
        u64 sacc[8] = {0,0,0,0,0,0,0,0};

        for (int jc = 0; jc < 4; jc++) {
            // GEMM1 chunk: s1 = relu(h @ w_a1[:, jc*64..] + b)
            u64 acc[8] = {0,0,0,0,0,0,0,0};
#pragma unroll 8
            for (int d = 0; d < 64; d++) {
                const u64* wp = (const u64*)&w_a1s[d*256 + jc*64 + c0];
                u64 w0 = wp[0], w1 = wp[1];
                u64 a0 = splat2(h[(r0+0)*RP + d]);
                u64 a1 = splat2(h[(r0+1)*RP + d]);
                u64 a2 = splat2(h[(r0+2)*RP + d]);
                u64 a3 = splat2(h[(r0+3)*RP + d]);
                fma2(acc[0], a0, w0); fma2(acc[1], a0, w1);
                fma2(acc[2], a1, w0); fma2(acc[3], a1, w1);
                fma2(acc[4], a2, w0); fma2(acc[5], a2, w1);
                fma2(acc[6], a3, w0); fma2(acc[7], a3, w1);
            }
            {
                float b0 = b_a1s[jc*64 + c0+0], b1 = b_a1s[jc*64 + c0+1];
                float b2 = b_a1s[jc*64 + c0+2], b3 = b_a1s[jc*64 + c0+3];
#pragma unroll
                for (int i = 0; i < 4; i++) {
                    float2 lo = unpack2(acc[i*2+0]);
                    float2 hi = unpack2(acc[i*2+1]);
                    float2 r01 = make_float2(fmaxf(lo.x + b0, 0.0f),
                                             fmaxf(lo.y + b1, 0.0f));
                    float2 r23 = make_float2(fmaxf(hi.x + b2, 0.0f),
                                             fmaxf(hi.y + b3, 0.0f));
                    *(float2*)&s1[(r0+i)*RP + c0]     = r01;
                    *(float2*)&s1[(r0+i)*RP + c0 + 2] = r23;
                }
            }
            __syncthreads();

            // GEMM2 chunk: sacc += s1 @ w_a2[jc*64..][:]
#pragma unroll 8
            for (int j = 0; j < 64; j++) {
                const u64* wp = (const u64*)&w_a2s[(jc*64 + j)*64 + c0];
                u64 w0 = wp[0], w1 = wp[1];
                u64 a0 = splat2(s1[(r0+0)*RP + j]);
                u64 a1 = splat2(s1[(r0+1)*RP + j]);
                u64 a2 = splat2(s1[(r0+2)*RP + j]);
                u64 a3 = splat2(s1[(r0+3)*RP + j]);
                fma2(sacc[0], a0, w0); fma2(sacc[1], a0, w1);
                fma2(sacc[2], a1, w0); fma2(sacc[3], a1, w1);
                fma2(sacc[4], a2, w0); fma2(sacc[5], a2, w1);
                fma2(sacc[6], a3, w0); fma2(sacc[7], a3, w1);
            }
            __syncthreads();
        }

        // ---- scores (+bias) -> s1[r][d]
        {
            float b0 = b_a2s[c0+0], b1 = b_a2s[c0+1];
            float b2 = b_a2s[c0+2], b3 = b_a2s[c0+3];
#pragma unroll
            for (int i = 0; i < 4; i++) {
                float2 lo = unpack2(sacc[i*2+0]);
                float2 hi = unpack2(sacc[i*2+1]);
                *(float2*)&s1[(r0+i)*RP + c0]     = make_float2(lo.x + b0, lo.y + b1);
                *(float2*)&s1[(r0+i)*RP + c0 + 2] = make_float2(hi.x + b2, hi.y + b3);
            }
        }
        __syncthreads();

        // ---- softmax over K + weighted v-sum (v from L2)
        {
            int l = tid >> 6, d = tid & 63;
            float vreg[16];
#pragma unroll
            for (int k = 0; k < 16; k++)
                vreg[k] = g_qkv[(size_t)(bofs + sidx[l*16 + k])*192 + 128 + d];
            float mx = -3.0e38f;
#pragma unroll
            for (int k = 0; k < 16; k++)
                mx = fmaxf(mx, s1[(l*16 + k)*RP + d]);
            float ssum = 0.0f, a = 0.0f;
#pragma unroll
            for (int k = 0; k < 16; k++) {
                float e = expf(s1[(l*16 + k)*RP + d] - mx);
                ssum += e;
                a = fmaf(e, vreg[k], a);
            }
            aggs[tid] = a / ssum;
        }
        __syncthreads();

        // ---- fc (w_fc via L1/L2) + BN partials
        {
            int l = tid >> 6, d = tid & 63;
            float y = b_fcs[d];
#pragma unroll 8
            for (int c = 0; c < 64; c++)
                y = fmaf(aggs[l*64 + c], w_fc[c*64 + d], y);
            g_y[(size_t)(pbase + l)*64 + d] = y;
            accY += y;
            accY2 = fmaf(y, y, accY2);
        }
        __syncthreads();
    }

    // ---- reduce BN partials across the 8 d-groups (reuse h as scratch)
    float* red = h;
    red[tid] = accY;
    __syncthreads();
    if (tid < 64) {
        float s = 0.0f;
#pragma unroll
        for (int q = 0; q < 8; q++) s += red[q*64 + tid];
        g_part[blockIdx.x*128 + tid] = s;
    }
    __syncthreads();
    red[tid] = accY2;
    __syncthreads();
    if (tid < 64) {
        float s = 0.0f;
#pragma unroll
        for (int q = 0; q < 8; q++) s += red[q*64 + tid];
        g_part[blockIdx.x*128 + 64 + tid] = s;
    }
}

// ---------------- kernel 4: finish BN statistics ----------------------------
__global__ void bnstats_kernel() {
    __shared__ float sred[2048];
    int tid = threadIdx.x;            // 1024
    int d = tid & 63, q = tid >> 6;   // 16 groups
    float s = 0.0f, s2 = 0.0f;
    for (int blk = q; blk < ATTN_GRID; blk += 16) {
        s  += g_part[blk*128 + d];
        s2 += g_part[blk*128 + 64 + d];
    }
    sred[tid] = s; sred[1024 + tid] = s2;
    __syncthreads();
    if (tid < 64) {
        float ts = 0.0f, ts2 = 0.0f;
#pragma unroll
        for (int k = 0; k < 16; k++) {
            ts  += sred[k*64 + d];
            ts2 += sred[1024 + k*64 + d];
        }
        float mean = ts / (float)NPTS;
        float var  = ts2 / (float)NPTS - mean*mean;
        g_mv[d]      = mean;
        g_mv[64 + d] = rsqrtf(var + 1e-5f);
    }
}

// ---------------- kernel 5: BN apply + relu + residual ----------------------
__global__ void final_kernel(const float* __restrict__ x,
                             const float* __restrict__ gamma,
                             const float* __restrict__ beta,
                             float* __restrict__ out) {
    int i = blockIdx.x * blockDim.x + threadIdx.x;
    if (i < NPTS*DD) {
        int d = i & 63;
        float yv = (g_y[i] - g_mv[d]) * g_mv[64 + d] * gamma[d] + beta[d];
        out[i] = fmaxf(yv, 0.0f) + x[i];
    }
}

// ---------------- launch -----------------------------------------------------
extern "C" void kernel_launch(void* const* d_in, const int* in_sizes, int n_in,
                              void* d_out, int out_size) {
    const float* x     = (const float*)d_in[0];
    const float* pos   = (const float*)d_in[1];
    const float* w_qkv = (const float*)d_in[2];
    const float* b_qkv = (const float*)d_in[3];
    const float* w_p1  = (const float*)d_in[4];
    const float* b_p1  = (const float*)d_in[5];
    const float* w_p2  = (const float*)d_in[6];
    const float* b_p2  = (const float*)d_in[7];
    const float* w_a1  = (const float*)d_in[8];
    const float* b_a1  = (const float*)d_in[9];
    const float* w_a2  = (const float*)d_in[10];
    const float* b_a2  = (const float*)d_in[11];
    const float* w_fc  = (const float*)d_in[12];
    const float* b_fc  = (const float*)d_in[13];
    const float* gamma = (const float*)d_in[14];
    const float* beta  = (const float*)d_in[15];
    float* out = (float*)d_out;

    const int smem_qkv  = (64*192 + 64*64) * 4;
    const int smem_knn  = (3*NN + 8*512) * 4 + (8*512) * 4;
    const int smem_attn = (16384+16384+4096+192+64+64+256+64+64
                           +512+32+384+512 + ROWS*RP + ROWS*RP) * 4 + 128*4;

    cudaFuncSetAttribute(qkv_kernel,  cudaFuncAttributeMaxDynamicSharedMemorySize, smem_qkv);
    cudaFuncSetAttribute(knn_kernel,  cudaFuncAttributeMaxDynamicSharedMemorySize, smem_knn);
    cudaFuncSetAttribute(attn_kernel, cudaFuncAttributeMaxDynamicSharedMemorySize, smem_attn);

    qkv_kernel<<<NPTS/64, 192, smem_qkv>>>(x, w_qkv, b_qkv);
    knn_kernel<<<NPTS/8, 256, smem_knn>>>(pos);
    attn_kernel<<<ATTN_GRID, 512, smem_attn>>>(pos, w_p1, b_p1, w_p2, b_p2,
                                               w_a1, b_a1, w_a2, b_a2, w_fc, b_fc);
    bnstats_kernel<<<1, 1024>>>();
    final_kernel<<<(NPTS*DD + 255)/256, 256>>>(x, gamma, beta, out);
}

// round 5
// speedup vs baseline: 1.4218x; 1.1332x over previous
#include <cuda_runtime.h>
#include <cuda_bf16.h>
#include <math.h>

#define BB 2
#define NN 4096
#define DD 64
#define HH 256
#define KK 16
#define NPTS (BB*NN)
#define ATTN_GRID 148
#define PTS 8               // points per iteration
#define ROWS 128            // PTS * KK rows
#define HP 66               // h fp32 row stride
#define H2P 36              // h2 packed row stride (u32)
#define SCP 65              // scores row stride

typedef unsigned long long u64;
typedef unsigned int u32;

__device__ __forceinline__ u64 splat2(float a) {
    u64 r;
    asm("mov.b64 %0, {%1, %1};" : "=l"(r) : "r"(__float_as_uint(a)));
    return r;
}
__device__ __forceinline__ void fma2(u64& d, u64 a, u64 b) {
    asm("fma.rn.f32x2 %0, %1, %2, %0;" : "+l"(d) : "l"(a), "l"(b));
}
__device__ __forceinline__ float2 unpack2(u64 v) {
    u32 lo, hi;
    asm("mov.b64 {%0, %1}, %2;" : "=r"(lo), "=r"(hi) : "l"(v));
    return make_float2(__uint_as_float(lo), __uint_as_float(hi));
}

// split two fp32 into packed bf16x2 hi and lo parts (x0 -> low half)
__device__ __forceinline__ void split2(float x0, float x1, u32& hi, u32& lo) {
    __nv_bfloat16 h0 = __float2bfloat16_rn(x0);
    __nv_bfloat16 h1 = __float2bfloat16_rn(x1);
    __nv_bfloat16 l0 = __float2bfloat16_rn(x0 - __bfloat162float(h0));
    __nv_bfloat16 l1 = __float2bfloat16_rn(x1 - __bfloat162float(h1));
    hi = (u32)*(unsigned short*)&h0 | ((u32)*(unsigned short*)&h1 << 16);
    lo = (u32)*(unsigned short*)&l0 | ((u32)*(unsigned short*)&l1 << 16);
}

__device__ __forceinline__ void mma16816(float* c, const u32* a, u32 b0, u32 b1) {
    asm volatile(
        "mma.sync.aligned.m16n8k16.row.col.f32.bf16.bf16.f32 "
        "{%0,%1,%2,%3}, {%4,%5,%6,%7}, {%8,%9}, {%0,%1,%2,%3};"
        : "+f"(c[0]), "+f"(c[1]), "+f"(c[2]), "+f"(c[3])
        : "r"(a[0]), "r"(a[1]), "r"(a[2]), "r"(a[3]), "r"(b0), "r"(b1));
}

// ---------------- scratch ----------------------------------------------------
__device__ float g_qkv[NPTS*192];      // q|k|v per point
__device__ int   g_idx[NPTS*KK];       // knn indices
__device__ float g_y[NPTS*DD];         // pre-BN output of fc
__device__ float g_part[ATTN_GRID*2*DD];
__device__ float g_mv[2*DD];           // mean, rstd

// ---------------- kernel 1: QKV GEMM  (8192x64 @ 64x192) -------------------
__global__ void qkv_kernel(const float* __restrict__ x,
                           const float* __restrict__ w,
                           const float* __restrict__ bq) {
    extern __shared__ float sm[];
    float* ws = sm;             // 64*192
    float* xs = sm + 64*192;    // 64*64
    int tid = threadIdx.x;      // 192 threads
    for (int i = tid; i < 64*192; i += 192) ws[i] = w[i];
    int row0 = blockIdx.x * 64;
    for (int i = tid; i < 64*64; i += 192) xs[i] = x[row0*64 + i];
    __syncthreads();
    float bb = bq[tid];
    for (int r0 = 0; r0 < 64; r0 += 8) {
        float acc[8];
#pragma unroll
        for (int r = 0; r < 8; r++) acc[r] = bb;
        for (int i = 0; i < 64; i++) {
            float wv = ws[i*192 + tid];
#pragma unroll
            for (int r = 0; r < 8; r++) acc[r] = fmaf(xs[(r0+r)*64 + i], wv, acc[r]);
        }
#pragma unroll
        for (int r = 0; r < 8; r++) g_qkv[(row0 + r0 + r)*192 + tid] = acc[r];
    }
}

// ---------------- kernel 2: exact KNN ---------------------------------------
__device__ __forceinline__ bool lexless(float d1, int i1, float d2, int i2) {
    return (d1 < d2) || (d1 == d2 && i1 < i2);
}

__global__ void knn_kernel(const float* __restrict__ pos) {
    extern __shared__ float sm[];
    float* posX = sm;                 // NN
    float* posY = posX + NN;          // NN
    float* posZ = posY + NN;          // NN
    float* md   = posZ + NN;          // 8*512
    int*   mi   = (int*)(md + 8*512); // 8*512
    int tid = threadIdx.x;
    int warp = tid >> 5, lane = tid & 31;
    int b = blockIdx.x / (NN/8);
    int n = (blockIdx.x % (NN/8))*8 + warp;
    const float* posB = pos + (size_t)b*NN*3;
    for (int i = tid; i < NN; i += 256) {
        posX[i] = posB[i*3+0];
        posY[i] = posB[i*3+1];
        posZ[i] = posB[i*3+2];
    }
    __syncthreads();
    float px = posX[n], py = posY[n], pz = posZ[n];

    float bd[16]; int bi[16];
#pragma unroll
    for (int j = 0; j < 16; j++) { bd[j] = 3.0e38f; bi[j] = 0x7fff0000 + j; }
    float wd = 3.0e38f; int wi = 0x7fff000F;

    for (int c = lane; c < NN; c += 32) {
        float dx = px - posX[c];
        float dy = py - posY[c];
        float dz = pz - posZ[c];
        float d2 = __fadd_rn(__fadd_rn(__fmul_rn(dx,dx), __fmul_rn(dy,dy)),
                             __fmul_rn(dz,dz));
        float thr2 = __fmul_rn(__fmul_rn(wd, wd), 1.0000005f);
        if (d2 <= thr2) {
            float d = sqrtf(d2);
            if (lexless(d, c, wd, wi)) {
#pragma unroll
                for (int j = 0; j < 16; j++)
                    if (bd[j] == wd && bi[j] == wi) { bd[j] = d; bi[j] = c; }
                wd = bd[0]; wi = bi[0];
#pragma unroll
                for (int j = 1; j < 16; j++)
                    if (lexless(wd, wi, bd[j], bi[j])) { wd = bd[j]; wi = bi[j]; }
            }
        }
    }
    float* mdw = md + warp*512;
    int*   miw = mi + warp*512;
#pragma unroll
    for (int j = 0; j < 16; j++) { mdw[j*32 + lane] = bd[j]; miw[j*32 + lane] = bi[j]; }
    __syncwarp();
    int outbase = (b*NN + n)*KK;
    for (int r = 0; r < 16; r++) {
        float cd = 3.0e38f; int ci = 0x7fffffff; int cpos = 0;
#pragma unroll
        for (int j = 0; j < 16; j++) {
            float dv = mdw[j*32 + lane]; int iv = miw[j*32 + lane];
            if (lexless(dv, iv, cd, ci)) { cd = dv; ci = iv; cpos = j*32 + lane; }
        }
#pragma unroll
        for (int off = 16; off > 0; off >>= 1) {
            float od = __shfl_down_sync(0xffffffffu, cd, off);
            int   oi = __shfl_down_sync(0xffffffffu, ci, off);
            int   op = __shfl_down_sync(0xffffffffu, cpos, off);
            if (lexless(od, oi, cd, ci)) { cd = od; ci = oi; cpos = op; }
        }
        if (lane == 0) { g_idx[outbase + r] = ci; mdw[cpos] = 3.0e38f; }
        __syncwarp();
    }
}

// ---------------- kernel 3: fused attn (tensor-core MLPs) -------------------
__global__ __launch_bounds__(512, 1)
void attn_kernel(const float* __restrict__ pos,
                 const float* __restrict__ w_p1, const float* __restrict__ b_p1,
                 const float* __restrict__ w_p2, const float* __restrict__ b_p2,
                 const float* __restrict__ w_a1, const float* __restrict__ b_a1,
                 const float* __restrict__ w_a2, const float* __restrict__ b_a2,
                 const float* __restrict__ w_fc, const float* __restrict__ b_fc) {
    extern __shared__ float sm[];
    u32* w1hi = (u32*)sm;               // 8192  (32 kpairs x 256, swizzled)
    u32* w1lo = w1hi + 8192;            // 8192
    u32* w2hi = w1lo + 8192;            // 8192  (128 kpairs x 64, swizzled)
    u32* w2lo = w2hi + 8192;            // 8192
    float* h    = (float*)(w2lo + 8192);// 8448  (128 x 66) [alias: stage]
    u32* h2hi   = (u32*)(h + 8448);     // 4608  (128 x 36) [alias: scores]
    u32* h2lo   = h2hi + 4608;          // 4608
    float* t1c  = (float*)(h2lo + 4608);// 4224  (128 x 33)
    float* qs   = t1c + 4224;           // 512
    float* p0s  = qs + 512;             // 32
    float* rel  = p0s + 32;             // 384
    float* aggs = rel + 384;            // 512
    float* b_p1s = aggs + 512;          // 64
    float* b_p2s = b_p1s + 64;          // 64
    float* b_a1s = b_p2s + 64;          // 256
    float* b_a2s = b_a1s + 256;         // 64
    float* b_fcs = b_a2s + 64;          // 64
    float* w_p1s = b_fcs + 64;          // 192
    int*   sidx  = (int*)(w_p1s + 192); // 128
    float* stage  = h;                  // 8x1056 = 8448
    float* scores = (float*)h2hi;       // 128 x 65 = 8320 <= 9216

    int tid = threadIdx.x;
    int lane = tid & 31;
    int wid = tid >> 5;
    int g4 = lane >> 2, t4 = lane & 3;
    int mt = wid >> 1, hf = wid & 1;

    // ---- weight prep: bf16 split + fragment swizzle (once) ----
    for (int i = tid; i < 8192; i += 512) {
        int kp = i >> 8, n = i & 255;
        u32 hi, lo;
        split2(w_a1[(2*kp)*256 + n], w_a1[(2*kp+1)*256 + n], hi, lo);
        int dst = kp*256 + (n ^ ((kp & 3) << 3));
        w1hi[dst] = hi; w1lo[dst] = lo;
    }
    for (int i = tid; i < 8192; i += 512) {
        int kp = i >> 6, n = i & 63;
        u32 hi, lo;
        split2(w_a2[(2*kp)*64 + n], w_a2[(2*kp+1)*64 + n], hi, lo);
        int dst = kp*64 + (n ^ ((kp & 3) << 3));
        w2hi[dst] = hi; w2lo[dst] = lo;
    }
    if (tid < 192) w_p1s[tid] = w_p1[tid];
    if (tid < 256) b_a1s[tid] = b_a1[tid];
    if (tid < 64) {
        b_p1s[tid] = b_p1[tid]; b_p2s[tid] = b_p2[tid];
        b_a2s[tid] = b_a2[tid]; b_fcs[tid] = b_fc[tid];
    }
    float accY = 0.0f, accY2 = 0.0f;

    const int r0 = (tid >> 4) * 4;       // FFMA2 p2 tiling
    const int c0 = (tid & 15) * 4;
    __syncthreads();

    for (int g = blockIdx.x; g < NPTS/PTS; g += ATTN_GRID) {
        int pbase = g * PTS;
        int bofs = (pbase >> 12) << 12;

        // ---- per-point loads
        if (tid < 128) sidx[tid] = g_idx[pbase*KK + tid];
        {
            int l = tid >> 6, d = tid & 63;
            qs[tid] = g_qkv[(size_t)(pbase + l)*192 + d];
        }
        if (tid < 24) {
            int l = tid / 3, c = tid - l*3;
            p0s[l*4 + c] = pos[(size_t)(pbase + l)*3 + c];
        }
        __syncthreads();

        // ---- gather: h = q - k_nb (fp32), rel
#pragma unroll
        for (int e = 0; e < 16; e++) {
            int i = tid + e*512;
            int r = i >> 6, d = i & 63;
            int l = r >> 4;
            h[r*HP + d] = qs[l*64 + d] -
                          g_qkv[(size_t)(bofs + sidx[r])*192 + 64 + d];
        }
        if (tid < 384) {
            int r = tid / 3, c = tid - r*3;
            int l = r >> 4;
            rel[tid] = p0s[l*4 + c] - pos[(size_t)(bofs + sidx[r])*3 + c];
        }
        __syncthreads();

        // ---- pos-MLP + p2 GEMM (FFMA2, 2 k-chunks of 32)
        {
            u64 pacc[8] = {0,0,0,0,0,0,0,0};
            for (int kc = 0; kc < 2; kc++) {
#pragma unroll
                for (int e = 0; e < 8; e++) {
                    int i = tid + e*512;
                    int r = i >> 5, pp = i & 31;
                    int p = kc*32 + pp;
                    float a = b_p1s[p];
                    a = fmaf(rel[r*3+0], w_p1s[p],       a);
                    a = fmaf(rel[r*3+1], w_p1s[64 + p],  a);
                    a = fmaf(rel[r*3+2], w_p1s[128 + p], a);
                    t1c[r*33 + pp] = fmaxf(a, 0.0f);
                }
                __syncthreads();
#pragma unroll 8
                for (int kk = 0; kk < 32; kk++) {
                    int p = kc*32 + kk;
                    u64 w0 = *(const u64*)&w_p2[p*64 + c0];
                    u64 w1 = *(const u64*)&w_p2[p*64 + c0 + 2];
                    u64 a0 = splat2(t1c[(r0+0)*33 + kk]);
                    u64 a1 = splat2(t1c[(r0+1)*33 + kk]);
                    u64 a2 = splat2(t1c[(r0+2)*33 + kk]);
                    u64 a3 = splat2(t1c[(r0+3)*33 + kk]);
                    fma2(pacc[0], a0, w0); fma2(pacc[1], a0, w1);
                    fma2(pacc[2], a1, w0); fma2(pacc[3], a1, w1);
                    fma2(pacc[4], a2, w0); fma2(pacc[5], a2, w1);
                    fma2(pacc[6], a3, w0); fma2(pacc[7], a3, w1);
                }
                __syncthreads();
            }
            float bb0 = b_p2s[c0+0], bb1 = b_p2s[c0+1];
            float bb2 = b_p2s[c0+2], bb3 = b_p2s[c0+3];
#pragma unroll
            for (int i = 0; i < 4; i++) {
                float2 lo = unpack2(pacc[i*2+0]);
                float2 hi = unpack2(pacc[i*2+1]);
                float* hp = &h[(r0+i)*HP + c0];
                hp[0] += lo.x + bb0; hp[1] += lo.y + bb1;
                hp[2] += hi.x + bb2; hp[3] += hi.y + bb3;
            }
        }
        __syncthreads();

        // ---- h fp32 -> packed bf16 split (h2hi/h2lo)
#pragma unroll
        for (int e = 0; e < 8; e++) {
            int i = tid + e*512;          // 4096 pairs
            int row = i >> 5, kp = i & 31;
            float2 x = *(const float2*)&h[row*HP + 2*kp];
            u32 hi, lo;
            split2(x.x, x.y, hi, lo);
            h2hi[row*H2P + kp] = hi;
            h2lo[row*H2P + kp] = lo;
        }
        __syncthreads();

        // ---- load A fragments (h) for this warp's m-tile
        u32 ahi[16], alo[16];
        {
            int rowA = mt*16 + g4;
#pragma unroll
            for (int ks = 0; ks < 4; ks++) {
                int c = ks*8 + t4;
                ahi[ks*4+0] = h2hi[rowA*H2P + c];
                ahi[ks*4+1] = h2hi[(rowA+8)*H2P + c];
                ahi[ks*4+2] = h2hi[rowA*H2P + c + 4];
                ahi[ks*4+3] = h2hi[(rowA+8)*H2P + c + 4];
                alo[ks*4+0] = h2lo[rowA*H2P + c];
                alo[ks*4+1] = h2lo[(rowA+8)*H2P + c];
                alo[ks*4+2] = h2lo[rowA*H2P + c + 4];
                alo[ks*4+3] = h2lo[(rowA+8)*H2P + c + 4];
            }
        }

        // ---- chunked attn MLP on tensor cores (sync-free)
        float C2[32];
#pragma unroll
        for (int z = 0; z < 32; z++) C2[z] = 0.0f;

#pragma unroll
        for (int jc = 0; jc < 4; jc++) {
            u32 s2hi[8], s2lo[8];         // A2 frags: 2 k2-steps x 4 regs
#pragma unroll
            for (int u = 0; u < 2; u++) {
                float cA[4] = {0,0,0,0}, cB[4] = {0,0,0,0};
                int nbase = jc*64 + hf*32 + u*16;
                int nswA = (nbase + g4) ^ (t4 << 3);
                int nswB = (nbase + 8 + g4) ^ (t4 << 3);
#pragma unroll
                for (int ks = 0; ks < 4; ks++) {
                    int kp0 = ks*8 + t4;
                    u32 bh0 = w1hi[kp0*256 + nswA];
                    u32 bh1 = w1hi[(kp0+4)*256 + nswA];
                    u32 bl0 = w1lo[kp0*256 + nswA];
                    u32 bl1 = w1lo[(kp0+4)*256 + nswA];
                    mma16816(cA, &ahi[ks*4], bh0, bh1);
                    mma16816(cA, &ahi[ks*4], bl0, bl1);
                    mma16816(cA, &alo[ks*4], bh0, bh1);
                    u32 ch0 = w1hi[kp0*256 + nswB];
                    u32 ch1 = w1hi[(kp0+4)*256 + nswB];
                    u32 cl0 = w1lo[kp0*256 + nswB];
                    u32 cl1 = w1lo[(kp0+4)*256 + nswB];
                    mma16816(cB, &ahi[ks*4], ch0, ch1);
                    mma16816(cB, &ahi[ks*4], cl0, cl1);
                    mma16816(cB, &alo[ks*4], ch0, ch1);
                }
                // bias + relu + split -> A2 fragment for k2-step u
                int cb = nbase + t4*2;
                float bA0 = b_a1s[cb],     bA1 = b_a1s[cb+1];
                float bB0 = b_a1s[cb+8],   bB1 = b_a1s[cb+9];
                float sA0 = fmaxf(cA[0] + bA0, 0.0f);
                float sA1 = fmaxf(cA[1] + bA1, 0.0f);
                float sA2 = fmaxf(cA[2] + bA0, 0.0f);
                float sA3 = fmaxf(cA[3] + bA1, 0.0f);
                float sB0 = fmaxf(cB[0] + bB0, 0.0f);
                float sB1 = fmaxf(cB[1] + bB1, 0.0f);
                float sB2 = fmaxf(cB[2] + bB0, 0.0f);
                float sB3 = fmaxf(cB[3] + bB1, 0.0f);
                split2(sA0, sA1, s2hi[u*4+0], s2lo[u*4+0]);
                split2(sA2, sA3, s2hi[u*4+1], s2lo[u*4+1]);
                split2(sB0, sB1, s2hi[u*4+2], s2lo[u*4+2]);
                split2(sB2, sB3, s2hi[u*4+3], s2lo[u*4+3]);
            }
            // GEMM2 chunk: C2 += s1_chunk @ w_a2[k2-range]
#pragma unroll
            for (int nt = 0; nt < 8; nt++) {
#pragma unroll
                for (int u = 0; u < 2; u++) {
                    int kp = jc*32 + hf*16 + u*8 + t4;
                    int nsw = (nt*8 + g4) ^ (t4 << 3);
                    u32 bh0 = w2hi[kp*64 + nsw];
                    u32 bh1 = w2hi[(kp+4)*64 + nsw];
                    u32 bl0 = w2lo[kp*64 + nsw];
                    u32 bl1 = w2lo[(kp+4)*64 + nsw];
                    mma16816(&C2[nt*4], &s2hi[u*4], bh0, bh1);
                    mma16816(&C2[nt*4], &s2hi[u*4], bl0, bl1);
                    mma16816(&C2[nt*4], &s2lo[u*4], bh0, bh1);
                }
            }
        }

        // ---- cross-half reduction of scores
        if (hf) {
            float* sp = stage + mt*1056 + lane*33;
#pragma unroll
            for (int z = 0; z < 32; z++) sp[z] = C2[z];
        }
        __syncthreads();
        if (!hf) {
            float* sp = stage + mt*1056 + lane*33;
#pragma unroll
            for (int nt = 0; nt < 8; nt++) {
                int cb = nt*8 + t4*2;
                float v0 = C2[nt*4+0] + sp[nt*4+0] + b_a2s[cb];
                float v1 = C2[nt*4+1] + sp[nt*4+1] + b_a2s[cb+1];
                float v2 = C2[nt*4+2] + sp[nt*4+2] + b_a2s[cb];
                float v3 = C2[nt*4+3] + sp[nt*4+3] + b_a2s[cb+1];
                scores[(mt*16 + g4)*SCP + cb]     = v0;
                scores[(mt*16 + g4)*SCP + cb + 1] = v1;
                scores[(mt*16 + g4 + 8)*SCP + cb]     = v2;
                scores[(mt*16 + g4 + 8)*SCP + cb + 1] = v3;
            }
        }
        __syncthreads();

        // ---- softmax over K + weighted v-sum (v from L2)
        {
            int l = tid >> 6, d = tid & 63;
            float vreg[16];
#pragma unroll
            for (int k = 0; k < 16; k++)
                vreg[k] = g_qkv[(size_t)(bofs + sidx[l*16 + k])*192 + 128 + d];
            float mx = -3.0e38f;
#pragma unroll
            for (int k = 0; k < 16; k++)
                mx = fmaxf(mx, scores[(l*16 + k)*SCP + d]);
            float ssum = 0.0f, a = 0.0f;
#pragma unroll
            for (int k = 0; k < 16; k++) {
                float e = expf(scores[(l*16 + k)*SCP + d] - mx);
                ssum += e;
                a = fmaf(e, vreg[k], a);
            }
            aggs[tid] = a / ssum;
        }
        __syncthreads();

        // ---- fc (w_fc via L1/L2) + BN partials
        {
            int l = tid >> 6, d = tid & 63;
            float y = b_fcs[d];
#pragma unroll 8
            for (int c = 0; c < 64; c++)
                y = fmaf(aggs[l*64 + c], w_fc[c*64 + d], y);
            g_y[(size_t)(pbase + l)*64 + d] = y;
            accY += y;
            accY2 = fmaf(y, y, accY2);
        }
        __syncthreads();
    }

    // ---- reduce BN partials (reuse h as scratch)
    float* red = h;
    red[tid] = accY;
    __syncthreads();
    if (tid < 64) {
        float s = 0.0f;
#pragma unroll
        for (int q = 0; q < 8; q++) s += red[q*64 + tid];
        g_part[blockIdx.x*128 + tid] = s;
    }
    __syncthreads();
    red[tid] = accY2;
    __syncthreads();
    if (tid < 64) {
        float s = 0.0f;
#pragma unroll
        for (int q = 0; q < 8; q++) s += red[q*64 + tid];
        g_part[blockIdx.x*128 + 64 + tid] = s;
    }
}

// ---------------- kernel 4: finish BN statistics ----------------------------
__global__ void bnstats_kernel() {
    __shared__ float sred[2048];
    int tid = threadIdx.x;            // 1024
    int d = tid & 63, q = tid >> 6;   // 16 groups
    float s = 0.0f, s2 = 0.0f;
    for (int blk = q; blk < ATTN_GRID; blk += 16) {
        s  += g_part[blk*128 + d];
        s2 += g_part[blk*128 + 64 + d];
    }
    sred[tid] = s; sred[1024 + tid] = s2;
    __syncthreads();
    if (tid < 64) {
        float ts = 0.0f, ts2 = 0.0f;
#pragma unroll
        for (int k = 0; k < 16; k++) {
            ts  += sred[k*64 + d];
            ts2 += sred[1024 + k*64 + d];
        }
        float mean = ts / (float)NPTS;
        float var  = ts2 / (float)NPTS - mean*mean;
        g_mv[d]      = mean;
        g_mv[64 + d] = rsqrtf(var + 1e-5f);
    }
}

// ---------------- kernel 5: BN apply + relu + residual ----------------------
__global__ void final_kernel(const float* __restrict__ x,
                             const float* __restrict__ gamma,
                             const float* __restrict__ beta,
                             float* __restrict__ out) {
    int i = blockIdx.x * blockDim.x + threadIdx.x;
    if (i < NPTS*DD) {
        int d = i & 63;
        float yv = (g_y[i] - g_mv[d]) * g_mv[64 + d] * gamma[d] + beta[d];
        out[i] = fmaxf(yv, 0.0f) + x[i];
    }
}

// ---------------- launch -----------------------------------------------------
extern "C" void kernel_launch(void* const* d_in, const int* in_sizes, int n_in,
                              void* d_out, int out_size) {
    const float* x     = (const float*)d_in[0];
    const float* pos   = (const float*)d_in[1];
    const float* w_qkv = (const float*)d_in[2];
    const float* b_qkv = (const float*)d_in[3];
    const float* w_p1  = (const float*)d_in[4];
    const float* b_p1  = (const float*)d_in[5];
    const float* w_p2  = (const float*)d_in[6];
    const float* b_p2  = (const float*)d_in[7];
    const float* w_a1  = (const float*)d_in[8];
    const float* b_a1  = (const float*)d_in[9];
    const float* w_a2  = (const float*)d_in[10];
    const float* b_a2  = (const float*)d_in[11];
    const float* w_fc  = (const float*)d_in[12];
    const float* b_fc  = (const float*)d_in[13];
    const float* gamma = (const float*)d_in[14];
    const float* beta  = (const float*)d_in[15];
    float* out = (float*)d_out;

    const int smem_qkv  = (64*192 + 64*64) * 4;
    const int smem_knn  = (3*NN + 8*512) * 4 + (8*512) * 4;
    const int smem_attn = (8192*4 + 8448 + 9216 + 4224
                           + 512 + 32 + 384 + 512
                           + 64 + 64 + 256 + 64 + 64 + 192 + 128) * 4;  // 227712 B

    cudaFuncSetAttribute(qkv_kernel,  cudaFuncAttributeMaxDynamicSharedMemorySize, smem_qkv);
    cudaFuncSetAttribute(knn_kernel,  cudaFuncAttributeMaxDynamicSharedMemorySize, smem_knn);
    cudaFuncSetAttribute(attn_kernel, cudaFuncAttributeMaxDynamicSharedMemorySize, smem_attn);

    qkv_kernel<<<NPTS/64, 192, smem_qkv>>>(x, w_qkv, b_qkv);
    knn_kernel<<<NPTS/8, 256, smem_knn>>>(pos);
    attn_kernel<<<ATTN_GRID, 512, smem_attn>>>(pos, w_p1, b_p1, w_p2, b_p2,
                                               w_a1, b_a1, w_a2, b_a2, w_fc, b_fc);
    bnstats_kernel<<<1, 1024>>>();
    final_kernel<<<(NPTS*DD + 255)/256, 256>>>(x, gamma, beta, out);
}

// round 7
// speedup vs baseline: 1.4920x; 1.0494x over previous
#include <cuda_runtime.h>
#include <cuda_bf16.h>
#include <math.h>

#define BB 2
#define NN 4096
#define DD 64
#define HH 256
#define KK 16
#define NPTS (BB*NN)
#define ATTN_GRID 148
#define PTS 8               // points per iteration
#define ROWS 128            // PTS * KK rows
#define HP 66               // h fp32 row stride
#define H2P 36              // h2 packed row stride (u32)
#define SCP 65              // scores row stride

typedef unsigned long long u64;
typedef unsigned int u32;

__device__ __forceinline__ u64 splat2(float a) {
    u64 r;
    asm("mov.b64 %0, {%1, %1};" : "=l"(r) : "r"(__float_as_uint(a)));
    return r;
}
__device__ __forceinline__ void fma2(u64& d, u64 a, u64 b) {
    asm("fma.rn.f32x2 %0, %1, %2, %0;" : "+l"(d) : "l"(a), "l"(b));
}
__device__ __forceinline__ float2 unpack2(u64 v) {
    u32 lo, hi;
    asm("mov.b64 {%0, %1}, %2;" : "=r"(lo), "=r"(hi) : "l"(v));
    return make_float2(__uint_as_float(lo), __uint_as_float(hi));
}

// split two fp32 into packed bf16x2 hi and lo parts (x0 -> low half)
__device__ __forceinline__ void split2(float x0, float x1, u32& hi, u32& lo) {
    __nv_bfloat16 h0 = __float2bfloat16_rn(x0);
    __nv_bfloat16 h1 = __float2bfloat16_rn(x1);
    __nv_bfloat16 l0 = __float2bfloat16_rn(x0 - __bfloat162float(h0));
    __nv_bfloat16 l1 = __float2bfloat16_rn(x1 - __bfloat162float(h1));
    hi = (u32)*(unsigned short*)&h0 | ((u32)*(unsigned short*)&h1 << 16);
    lo = (u32)*(unsigned short*)&l0 | ((u32)*(unsigned short*)&l1 << 16);
}

__device__ __forceinline__ void mma16816(float* c, const u32* a, u32 b0, u32 b1) {
    asm volatile(
        "mma.sync.aligned.m16n8k16.row.col.f32.bf16.bf16.f32 "
        "{%0,%1,%2,%3}, {%4,%5,%6,%7}, {%8,%9}, {%0,%1,%2,%3};"
        : "+f"(c[0]), "+f"(c[1]), "+f"(c[2]), "+f"(c[3])
        : "r"(a[0]), "r"(a[1]), "r"(a[2]), "r"(a[3]), "r"(b0), "r"(b1));
}

// ---------------- scratch ----------------------------------------------------
__device__ float g_qkv[NPTS*192];      // q|k|v per point
__device__ int   g_idx[NPTS*KK];       // knn indices
__device__ float g_y[NPTS*DD];         // pre-BN output of fc
__device__ float g_part[ATTN_GRID*2*DD];
__device__ float g_mv[2*DD];           // mean, rstd

// ---------------- kernel 1: QKV GEMM  (8192x64 @ 64x192) -------------------
__global__ void qkv_kernel(const float* __restrict__ x,
                           const float* __restrict__ w,
                           const float* __restrict__ bq) {
    extern __shared__ float sm[];
    float* ws = sm;             // 64*192
    float* xs = sm + 64*192;    // 64*64
    int tid = threadIdx.x;      // 192 threads
    for (int i = tid; i < 64*192; i += 192) ws[i] = w[i];
    int row0 = blockIdx.x * 64;
    for (int i = tid; i < 64*64; i += 192) xs[i] = x[row0*64 + i];
    __syncthreads();
    float bb = bq[tid];
    for (int r0 = 0; r0 < 64; r0 += 8) {
        float acc[8];
#pragma unroll
        for (int r = 0; r < 8; r++) acc[r] = bb;
        for (int i = 0; i < 64; i++) {
            float wv = ws[i*192 + tid];
#pragma unroll
            for (int r = 0; r < 8; r++) acc[r] = fmaf(xs[(r0+r)*64 + i], wv, acc[r]);
        }
#pragma unroll
        for (int r = 0; r < 8; r++) g_qkv[(row0 + r0 + r)*192 + tid] = acc[r];
    }
}

// ---------------- kernel 2: exact KNN ---------------------------------------
__device__ __forceinline__ bool lexless(float d1, int i1, float d2, int i2) {
    return (d1 < d2) || (d1 == d2 && i1 < i2);
}

__global__ void knn_kernel(const float* __restrict__ pos) {
    extern __shared__ float sm[];
    float* posX = sm;                 // NN
    float* posY = posX + NN;          // NN
    float* posZ = posY + NN;          // NN
    float* md   = posZ + NN;          // 8*512
    int*   mi   = (int*)(md + 8*512); // 8*512
    int tid = threadIdx.x;
    int warp = tid >> 5, lane = tid & 31;
    int b = blockIdx.x / (NN/8);
    int n = (blockIdx.x % (NN/8))*8 + warp;
    const float* posB = pos + (size_t)b*NN*3;
    for (int i = tid; i < NN; i += 256) {
        posX[i] = posB[i*3+0];
        posY[i] = posB[i*3+1];
        posZ[i] = posB[i*3+2];
    }
    __syncthreads();
    float px = posX[n], py = posY[n], pz = posZ[n];

    float bd[16]; int bi[16];
#pragma unroll
    for (int j = 0; j < 16; j++) { bd[j] = 3.0e38f; bi[j] = 0x7fff0000 + j; }
    float wd = 3.0e38f; int wi = 0x7fff000F;

    for (int c = lane; c < NN; c += 32) {
        float dx = px - posX[c];
        float dy = py - posY[c];
        float dz = pz - posZ[c];
        float d2 = __fadd_rn(__fadd_rn(__fmul_rn(dx,dx), __fmul_rn(dy,dy)),
                             __fmul_rn(dz,dz));
        float thr2 = __fmul_rn(__fmul_rn(wd, wd), 1.0000005f);
        if (d2 <= thr2) {
            float d = sqrtf(d2);
            if (lexless(d, c, wd, wi)) {
#pragma unroll
                for (int j = 0; j < 16; j++)
                    if (bd[j] == wd && bi[j] == wi) { bd[j] = d; bi[j] = c; }
                wd = bd[0]; wi = bi[0];
#pragma unroll
                for (int j = 1; j < 16; j++)
                    if (lexless(wd, wi, bd[j], bi[j])) { wd = bd[j]; wi = bi[j]; }
            }
        }
    }
    float* mdw = md + warp*512;
    int*   miw = mi + warp*512;
#pragma unroll
    for (int j = 0; j < 16; j++) { mdw[j*32 + lane] = bd[j]; miw[j*32 + lane] = bi[j]; }
    __syncwarp();
    int outbase = (b*NN + n)*KK;
    for (int r = 0; r < 16; r++) {
        float cd = 3.0e38f; int ci = 0x7fffffff; int cpos = 0;
#pragma unroll
        for (int j = 0; j < 16; j++) {
            float dv = mdw[j*32 + lane]; int iv = miw[j*32 + lane];
            if (lexless(dv, iv, cd, ci)) { cd = dv; ci = iv; cpos = j*32 + lane; }
        }
#pragma unroll
        for (int off = 16; off > 0; off >>= 1) {
            float od = __shfl_down_sync(0xffffffffu, cd, off);
            int   oi = __shfl_down_sync(0xffffffffu, ci, off);
            int   op = __shfl_down_sync(0xffffffffu, cpos, off);
            if (lexless(od, oi, cd, ci)) { cd = od; ci = oi; cpos = op; }
        }
        if (lane == 0) { g_idx[outbase + r] = ci; mdw[cpos] = 3.0e38f; }
        __syncwarp();
    }
}

// ---------------- probe: shifts the ncu fixed capture slot onto attn --------
__global__ void probe_kernel() {}

// ---------------- kernel 3: fused attn (tensor-core MLPs) -------------------
__global__ __launch_bounds__(512, 1)
void attn_kernel(const float* __restrict__ pos,
                 const float* __restrict__ w_p1, const float* __restrict__ b_p1,
                 const float* __restrict__ w_p2, const float* __restrict__ b_p2,
                 const float* __restrict__ w_a1, const float* __restrict__ b_a1,
                 const float* __restrict__ w_a2, const float* __restrict__ b_a2,
                 const float* __restrict__ w_fc, const float* __restrict__ b_fc) {
    extern __shared__ float sm[];
    u32* w1hi = (u32*)sm;               // 8192  (32 kpairs x 256, swizzled)
    u32* w1lo = w1hi + 8192;            // 8192
    u32* w2hi = w1lo + 8192;            // 8192  (128 kpairs x 64, swizzled)
    u32* w2lo = w2hi + 8192;            // 8192
    float* h    = (float*)(w2lo + 8192);// 8448  (128 x 66) [alias: stage]
    u32* h2hi   = (u32*)(h + 8448);     // 4608  (128 x 36) [alias: scores]
    u32* h2lo   = h2hi + 4608;          // 4608
    float* t1c  = (float*)(h2lo + 4608);// 4224  (128 x 33)
    float* qs   = t1c + 4224;           // 512
    float* p0s  = qs + 512;             // 32
    float* rel  = p0s + 32;             // 384
    float* aggs = rel + 384;            // 512
    float* b_p1s = aggs + 512;          // 64
    float* b_p2s = b_p1s + 64;          // 64
    float* b_a1s = b_p2s + 64;          // 256
    float* b_a2s = b_a1s + 256;         // 64
    float* b_fcs = b_a2s + 64;          // 64
    float* w_p1s = b_fcs + 64;          // 192
    int*   sidx  = (int*)(w_p1s + 192); // 128
    float* stage  = h;                  // 8x1056 = 8448
    float* scores = (float*)h2hi;       // 128 x 65 = 8320 <= 9216

    int tid = threadIdx.x;
    int lane = tid & 31;
    int wid = tid >> 5;
    int g4 = lane >> 2, t4 = lane & 3;
    int mt = wid >> 1, hf = wid & 1;

    // ---- weight prep: bf16 split + fragment swizzle (once) ----
    for (int i = tid; i < 8192; i += 512) {
        int kp = i >> 8, n = i & 255;
        u32 hi, lo;
        split2(w_a1[(2*kp)*256 + n], w_a1[(2*kp+1)*256 + n], hi, lo);
        int dst = kp*256 + (n ^ ((kp & 3) << 3));
        w1hi[dst] = hi; w1lo[dst] = lo;
    }
    for (int i = tid; i < 8192; i += 512) {
        int kp = i >> 6, n = i & 63;
        u32 hi, lo;
        split2(w_a2[(2*kp)*64 + n], w_a2[(2*kp+1)*64 + n], hi, lo);
        int dst = kp*64 + (n ^ ((kp & 3) << 3));
        w2hi[dst] = hi; w2lo[dst] = lo;
    }
    if (tid < 192) w_p1s[tid] = w_p1[tid];
    if (tid < 256) b_a1s[tid] = b_a1[tid];
    if (tid < 64) {
        b_p1s[tid] = b_p1[tid]; b_p2s[tid] = b_p2[tid];
        b_a2s[tid] = b_a2[tid]; b_fcs[tid] = b_fc[tid];
    }
    float accY = 0.0f, accY2 = 0.0f;

    const int r0 = (tid >> 4) * 4;       // FFMA2 p2 tiling
    const int c0 = (tid & 15) * 4;
    __syncthreads();

    for (int g = blockIdx.x; g < NPTS/PTS; g += ATTN_GRID) {
        int pbase = g * PTS;
        int bofs = (pbase >> 12) << 12;

        // ---- per-point loads
        if (tid < 128) sidx[tid] = g_idx[pbase*KK + tid];
        {
            int l = tid >> 6, d = tid & 63;
            qs[tid] = g_qkv[(size_t)(pbase + l)*192 + d];
        }
        if (tid < 24) {
            int l = tid / 3, c = tid - l*3;
            p0s[l*4 + c] = pos[(size_t)(pbase + l)*3 + c];
        }
        __syncthreads();

        // ---- gather: h = q - k_nb (fp32), rel
#pragma unroll
        for (int e = 0; e < 16; e++) {
            int i = tid + e*512;
            int r = i >> 6, d = i & 63;
            int l = r >> 4;
            h[r*HP + d] = qs[l*64 + d] -
                          g_qkv[(size_t)(bofs + sidx[r])*192 + 64 + d];
        }
        if (tid < 384) {
            int r = tid / 3, c = tid - r*3;
            int l = r >> 4;
            rel[tid] = p0s[l*4 + c] - pos[(size_t)(bofs + sidx[r])*3 + c];
        }
        __syncthreads();

        // ---- pos-MLP + p2 GEMM (FFMA2, 2 k-chunks of 32)
        {
            u64 pacc[8] = {0,0,0,0,0,0,0,0};
            for (int kc = 0; kc < 2; kc++) {
#pragma unroll
                for (int e = 0; e < 8; e++) {
                    int i = tid + e*512;
                    int r = i >> 5, pp = i & 31;
                    int p = kc*32 + pp;
                    float a = b_p1s[p];
                    a = fmaf(rel[r*3+0], w_p1s[p],       a);
                    a = fmaf(rel[r*3+1], w_p1s[64 + p],  a);
                    a = fmaf(rel[r*3+2], w_p1s[128 + p], a);
                    t1c[r*33 + pp] = fmaxf(a, 0.0f);
                }
                __syncthreads();
#pragma unroll 8
                for (int kk = 0; kk < 32; kk++) {
                    int p = kc*32 + kk;
                    u64 w0 = *(const u64*)&w_p2[p*64 + c0];
                    u64 w1 = *(const u64*)&w_p2[p*64 + c0 + 2];
                    u64 a0 = splat2(t1c[(r0+0)*33 + kk]);
                    u64 a1 = splat2(t1c[(r0+1)*33 + kk]);
                    u64 a2 = splat2(t1c[(r0+2)*33 + kk]);
                    u64 a3 = splat2(t1c[(r0+3)*33 + kk]);
                    fma2(pacc[0], a0, w0); fma2(pacc[1], a0, w1);
                    fma2(pacc[2], a1, w0); fma2(pacc[3], a1, w1);
                    fma2(pacc[4], a2, w0); fma2(pacc[5], a2, w1);
                    fma2(pacc[6], a3, w0); fma2(pacc[7], a3, w1);
                }
                __syncthreads();
            }
            float bb0 = b_p2s[c0+0], bb1 = b_p2s[c0+1];
            float bb2 = b_p2s[c0+2], bb3 = b_p2s[c0+3];
#pragma unroll
            for (int i = 0; i < 4; i++) {
                float2 lo = unpack2(pacc[i*2+0]);
                float2 hi = unpack2(pacc[i*2+1]);
                float* hp = &h[(r0+i)*HP + c0];
                hp[0] += lo.x + bb0; hp[1] += lo.y + bb1;
                hp[2] += hi.x + bb2; hp[3] += hi.y + bb3;
            }
        }
        __syncthreads();

        // ---- h fp32 -> packed bf16 split (h2hi/h2lo)
#pragma unroll
        for (int e = 0; e < 8; e++) {
            int i = tid + e*512;          // 4096 pairs
            int row = i >> 5, kp = i & 31;
            float2 x = *(const float2*)&h[row*HP + 2*kp];
            u32 hi, lo;
            split2(x.x, x.y, hi, lo);
            h2hi[row*H2P + kp] = hi;
            h2lo[row*H2P + kp] = lo;
        }
        __syncthreads();

        // ---- load A fragments (h) for this warp's m-tile
        u32 ahi[16], alo[16];
        {
            int rowA = mt*16 + g4;
#pragma unroll
            for (int ks = 0; ks < 4; ks++) {
                int c = ks*8 + t4;
                ahi[ks*4+0] = h2hi[rowA*H2P + c];
                ahi[ks*4+1] = h2hi[(rowA+8)*H2P + c];
                ahi[ks*4+2] = h2hi[rowA*H2P + c + 4];
                ahi[ks*4+3] = h2hi[(rowA+8)*H2P + c + 4];
                alo[ks*4+0] = h2lo[rowA*H2P + c];
                alo[ks*4+1] = h2lo[(rowA+8)*H2P + c];
                alo[ks*4+2] = h2lo[rowA*H2P + c + 4];
                alo[ks*4+3] = h2lo[(rowA+8)*H2P + c + 4];
            }
        }

        // ---- chunked attn MLP on tensor cores (sync-free)
        float C2[32];
#pragma unroll
        for (int z = 0; z < 32; z++) C2[z] = 0.0f;

#pragma unroll
        for (int jc = 0; jc < 4; jc++) {
            u32 s2hi[8], s2lo[8];         // A2 frags: 2 k2-steps x 4 regs
#pragma unroll
            for (int u = 0; u < 2; u++) {
                float cA[4] = {0,0,0,0}, cB[4] = {0,0,0,0};
                int nbase = jc*64 + hf*32 + u*16;
                int nswA = (nbase + g4) ^ (t4 << 3);
                int nswB = (nbase + 8 + g4) ^ (t4 << 3);
#pragma unroll
                for (int ks = 0; ks < 4; ks++) {
                    int kp0 = ks*8 + t4;
                    u32 bh0 = w1hi[kp0*256 + nswA];
                    u32 bh1 = w1hi[(kp0+4)*256 + nswA];
                    u32 bl0 = w1lo[kp0*256 + nswA];
                    u32 bl1 = w1lo[(kp0+4)*256 + nswA];
                    mma16816(cA, &ahi[ks*4], bh0, bh1);
                    mma16816(cA, &ahi[ks*4], bl0, bl1);
                    mma16816(cA, &alo[ks*4], bh0, bh1);
                    u32 ch0 = w1hi[kp0*256 + nswB];
                    u32 ch1 = w1hi[(kp0+4)*256 + nswB];
                    u32 cl0 = w1lo[kp0*256 + nswB];
                    u32 cl1 = w1lo[(kp0+4)*256 + nswB];
                    mma16816(cB, &ahi[ks*4], ch0, ch1);
                    mma16816(cB, &ahi[ks*4], cl0, cl1);
                    mma16816(cB, &alo[ks*4], ch0, ch1);
                }
                // bias + relu + split -> A2 fragment for k2-step u
                int cb = nbase + t4*2;
                float bA0 = b_a1s[cb],     bA1 = b_a1s[cb+1];
                float bB0 = b_a1s[cb+8],   bB1 = b_a1s[cb+9];
                float sA0 = fmaxf(cA[0] + bA0, 0.0f);
                float sA1 = fmaxf(cA[1] + bA1, 0.0f);
                float sA2 = fmaxf(cA[2] + bA0, 0.0f);
                float sA3 = fmaxf(cA[3] + bA1, 0.0f);
                float sB0 = fmaxf(cB[0] + bB0, 0.0f);
                float sB1 = fmaxf(cB[1] + bB1, 0.0f);
                float sB2 = fmaxf(cB[2] + bB0, 0.0f);
                float sB3 = fmaxf(cB[3] + bB1, 0.0f);
                split2(sA0, sA1, s2hi[u*4+0], s2lo[u*4+0]);
                split2(sA2, sA3, s2hi[u*4+1], s2lo[u*4+1]);
                split2(sB0, sB1, s2hi[u*4+2], s2lo[u*4+2]);
                split2(sB2, sB3, s2hi[u*4+3], s2lo[u*4+3]);
            }
            // GEMM2 chunk: C2 += s1_chunk @ w_a2[k2-range]
#pragma unroll
            for (int nt = 0; nt < 8; nt++) {
#pragma unroll
                for (int u = 0; u < 2; u++) {
                    int kp = jc*32 + hf*16 + u*8 + t4;
                    int nsw = (nt*8 + g4) ^ (t4 << 3);
                    u32 bh0 = w2hi[kp*64 + nsw];
                    u32 bh1 = w2hi[(kp+4)*64 + nsw];
                    u32 bl0 = w2lo[kp*64 + nsw];
                    u32 bl1 = w2lo[(kp+4)*64 + nsw];
                    mma16816(&C2[nt*4], &s2hi[u*4], bh0, bh1);
                    mma16816(&C2[nt*4], &s2hi[u*4], bl0, bl1);
                    mma16816(&C2[nt*4], &s2lo[u*4], bh0, bh1);
                }
            }
        }

        // ---- cross-half reduction of scores
        if (hf) {
            float* sp = stage + mt*1056 + lane*33;
#pragma unroll
            for (int z = 0; z < 32; z++) sp[z] = C2[z];
        }
        __syncthreads();
        if (!hf) {
            float* sp = stage + mt*1056 + lane*33;
#pragma unroll
            for (int nt = 0; nt < 8; nt++) {
                int cb = nt*8 + t4*2;
                float v0 = C2[nt*4+0] + sp[nt*4+0] + b_a2s[cb];
                float v1 = C2[nt*4+1] + sp[nt*4+1] + b_a2s[cb+1];
                float v2 = C2[nt*4+2] + sp[nt*4+2] + b_a2s[cb];
                float v3 = C2[nt*4+3] + sp[nt*4+3] + b_a2s[cb+1];
                scores[(mt*16 + g4)*SCP + cb]     = v0;
                scores[(mt*16 + g4)*SCP + cb + 1] = v1;
                scores[(mt*16 + g4 + 8)*SCP + cb]     = v2;
                scores[(mt*16 + g4 + 8)*SCP + cb + 1] = v3;
            }
        }
        __syncthreads();

        // ---- softmax over K + weighted v-sum (v from L2)
        {
            int l = tid >> 6, d = tid & 63;
            float vreg[16];
#pragma unroll
            for (int k = 0; k < 16; k++)
                vreg[k] = g_qkv[(size_t)(bofs + sidx[l*16 + k])*192 + 128 + d];
            float mx = -3.0e38f;
#pragma unroll
            for (int k = 0; k < 16; k++)
                mx = fmaxf(mx, scores[(l*16 + k)*SCP + d]);
            float ssum = 0.0f, a = 0.0f;
#pragma unroll
            for (int k = 0; k < 16; k++) {
                float e = __expf(scores[(l*16 + k)*SCP + d] - mx);
                ssum += e;
                a = fmaf(e, vreg[k], a);
            }
            aggs[tid] = a / ssum;
        }
        __syncthreads();

        // ---- fc (w_fc via L1/L2) + BN partials
        {
            int l = tid >> 6, d = tid & 63;
            float y = b_fcs[d];
#pragma unroll 8
            for (int c = 0; c < 64; c++)
                y = fmaf(aggs[l*64 + c], w_fc[c*64 + d], y);
            g_y[(size_t)(pbase + l)*64 + d] = y;
            accY += y;
            accY2 = fmaf(y, y, accY2);
        }
        __syncthreads();
    }

    // ---- reduce BN partials (reuse h as scratch)
    float* red = h;
    red[tid] = accY;
    __syncthreads();
    if (tid < 64) {
        float s = 0.0f;
#pragma unroll
        for (int q = 0; q < 8; q++) s += red[q*64 + tid];
        g_part[blockIdx.x*128 + tid] = s;
    }
    __syncthreads();
    red[tid] = accY2;
    __syncthreads();
    if (tid < 64) {
        float s = 0.0f;
#pragma unroll
        for (int q = 0; q < 8; q++) s += red[q*64 + tid];
        g_part[blockIdx.x*128 + 64 + tid] = s;
    }
}

// ---------------- kernel 4: finish BN statistics ----------------------------
__global__ void bnstats_kernel() {
    __shared__ float sred[2048];
    int tid = threadIdx.x;            // 1024
    int d = tid & 63, q = tid >> 6;   // 16 groups
    float s = 0.0f, s2 = 0.0f;
    for (int blk = q; blk < ATTN_GRID; blk += 16) {
        s  += g_part[blk*128 + d];
        s2 += g_part[blk*128 + 64 + d];
    }
    sred[tid] = s; sred[1024 + tid] = s2;
    __syncthreads();
    if (tid < 64) {
        float ts = 0.0f, ts2 = 0.0f;
#pragma unroll
        for (int k = 0; k < 16; k++) {
            ts  += sred[k*64 + d];
            ts2 += sred[1024 + k*64 + d];
        }
        float mean = ts / (float)NPTS;
        float var  = ts2 / (float)NPTS - mean*mean;
        g_mv[d]      = mean;
        g_mv[64 + d] = rsqrtf(var + 1e-5f);
    }
}

// ---------------- kernel 5: BN apply + relu + residual ----------------------
__global__ void final_kernel(const float* __restrict__ x,
                             const float* __restrict__ gamma,
                             const float* __restrict__ beta,
                             float* __restrict__ out) {
    int i = blockIdx.x * blockDim.x + threadIdx.x;
    if (i < NPTS*DD) {
        int d = i & 63;
        float yv = (g_y[i] - g_mv[d]) * g_mv[64 + d] * gamma[d] + beta[d];
        out[i] = fmaxf(yv, 0.0f) + x[i];
    }
}

// ---------------- launch -----------------------------------------------------
extern "C" void kernel_launch(void* const* d_in, const int* in_sizes, int n_in,
                              void* d_out, int out_size) {
    const float* x     = (const float*)d_in[0];
    const float* pos   = (const float*)d_in[1];
    const float* w_qkv = (const float*)d_in[2];
    const float* b_qkv = (const float*)d_in[3];
    const float* w_p1  = (const float*)d_in[4];
    const float* b_p1  = (const float*)d_in[5];
    const float* w_p2  = (const float*)d_in[6];
    const float* b_p2  = (const float*)d_in[7];
    const float* w_a1  = (const float*)d_in[8];
    const float* b_a1  = (const float*)d_in[9];
    const float* w_a2  = (const float*)d_in[10];
    const float* b_a2  = (const float*)d_in[11];
    const float* w_fc  = (const float*)d_in[12];
    const float* b_fc  = (const float*)d_in[13];
    const float* gamma = (const float*)d_in[14];
    const float* beta  = (const float*)d_in[15];
    float* out = (float*)d_out;

    const int smem_qkv  = (64*192 + 64*64) * 4;
    const int smem_knn  = (3*NN + 8*512) * 4 + (8*512) * 4;
    const int smem_attn = (8192*4 + 8448 + 9216 + 4224
                           + 512 + 32 + 384 + 512
                           + 64 + 64 + 256 + 64 + 64 + 192 + 128) * 4;  // 227712 B

    cudaFuncSetAttribute(qkv_kernel,  cudaFuncAttributeMaxDynamicSharedMemorySize, smem_qkv);
    cudaFuncSetAttribute(knn_kernel,  cudaFuncAttributeMaxDynamicSharedMemorySize, smem_knn);
    cudaFuncSetAttribute(attn_kernel, cudaFuncAttributeMaxDynamicSharedMemorySize, smem_attn);

    qkv_kernel<<<NPTS/64, 192, smem_qkv>>>(x, w_qkv, b_qkv);
    knn_kernel<<<NPTS/8, 256, smem_knn>>>(pos);
    probe_kernel<<<1, 32>>>();
    attn_kernel<<<ATTN_GRID, 512, smem_attn>>>(pos, w_p1, b_p1, w_p2, b_p2,
                                               w_a1, b_a1, w_a2, b_a2, w_fc, b_fc);
    bnstats_kernel<<<1, 1024>>>();
    final_kernel<<<(NPTS*DD + 255)/256, 256>>>(x, gamma, beta, out);
}

// round 8
// speedup vs baseline: 2.3793x; 1.5948x over previous
#include <cuda_runtime.h>
#include <cuda_bf16.h>
#include <math.h>

#define BB 2
#define NN 4096
#define DD 64
#define HH 256
#define KK 16
#define NPTS (BB*NN)
#define ATTN_GRID 148
#define PTS 8               // points per iteration
#define ROWS 128            // PTS * KK rows
#define HP 66               // h fp32 row stride
#define H2P 36              // h2 packed row stride (u32)
#define SCP 65              // scores row stride

#define KNN_WARPS 16
#define KNN_THREADS 512
#define KNN_CAP 128
#define BIGD 3.0e38f

typedef unsigned long long u64;
typedef unsigned int u32;

__device__ __forceinline__ u64 splat2(float a) {
    u64 r;
    asm("mov.b64 %0, {%1, %1};" : "=l"(r) : "r"(__float_as_uint(a)));
    return r;
}
__device__ __forceinline__ void fma2(u64& d, u64 a, u64 b) {
    asm("fma.rn.f32x2 %0, %1, %2, %0;" : "+l"(d) : "l"(a), "l"(b));
}
__device__ __forceinline__ float2 unpack2(u64 v) {
    u32 lo, hi;
    asm("mov.b64 {%0, %1}, %2;" : "=r"(lo), "=r"(hi) : "l"(v));
    return make_float2(__uint_as_float(lo), __uint_as_float(hi));
}

// split two fp32 into packed bf16x2 hi and lo parts (x0 -> low half)
__device__ __forceinline__ void split2(float x0, float x1, u32& hi, u32& lo) {
    __nv_bfloat16 h0 = __float2bfloat16_rn(x0);
    __nv_bfloat16 h1 = __float2bfloat16_rn(x1);
    __nv_bfloat16 l0 = __float2bfloat16_rn(x0 - __bfloat162float(h0));
    __nv_bfloat16 l1 = __float2bfloat16_rn(x1 - __bfloat162float(h1));
    hi = (u32)*(unsigned short*)&h0 | ((u32)*(unsigned short*)&h1 << 16);
    lo = (u32)*(unsigned short*)&l0 | ((u32)*(unsigned short*)&l1 << 16);
}

__device__ __forceinline__ void mma16816(float* c, const u32* a, u32 b0, u32 b1) {
    asm volatile(
        "mma.sync.aligned.m16n8k16.row.col.f32.bf16.bf16.f32 "
        "{%0,%1,%2,%3}, {%4,%5,%6,%7}, {%8,%9}, {%0,%1,%2,%3};"
        : "+f"(c[0]), "+f"(c[1]), "+f"(c[2]), "+f"(c[3])
        : "r"(a[0]), "r"(a[1]), "r"(a[2]), "r"(a[3]), "r"(b0), "r"(b1));
}

// ---------------- scratch ----------------------------------------------------
__device__ float g_qkv[NPTS*192];      // q|k|v per point
__device__ int   g_idx[NPTS*KK];       // knn indices
__device__ float g_y[NPTS*DD];         // pre-BN output of fc
__device__ float g_part[ATTN_GRID*2*DD];
__device__ float g_mv[2*DD];           // mean, rstd

// ---------------- kernel 1: QKV GEMM  (8192x64 @ 64x192) -------------------
__global__ void qkv_kernel(const float* __restrict__ x,
                           const float* __restrict__ w,
                           const float* __restrict__ bq) {
    extern __shared__ float sm[];
    float* ws = sm;             // 64*192
    float* xs = sm + 64*192;    // 64*64
    int tid = threadIdx.x;      // 192 threads
    for (int i = tid; i < 64*192; i += 192) ws[i] = w[i];
    int row0 = blockIdx.x * 64;
    for (int i = tid; i < 64*64; i += 192) xs[i] = x[row0*64 + i];
    __syncthreads();
    float bb = bq[tid];
    for (int r0 = 0; r0 < 64; r0 += 8) {
        float acc[8];
#pragma unroll
        for (int r = 0; r < 8; r++) acc[r] = bb;
        for (int i = 0; i < 64; i++) {
            float wv = ws[i*192 + tid];
#pragma unroll
            for (int r = 0; r < 8; r++) acc[r] = fmaf(xs[(r0+r)*64 + i], wv, acc[r]);
        }
#pragma unroll
        for (int r = 0; r < 8; r++) g_qkv[(row0 + r0 + r)*192 + tid] = acc[r];
    }
}

// ---------------- kernel 2: KNN (warp threshold-filter, exact) --------------
__device__ __forceinline__ bool lexless(float d1, int i1, float d2, int i2) {
    return (d1 < d2) || (d1 == d2 && i1 < i2);
}

__device__ __forceinline__ void knn_flush(
    float& tD, int& tI, float& thrD, int& thrI, float& thr2,
    int& cnt, const float* bD, const int* bI, int lane)
{
    float e0 = (lane < 16) ? tD : BIGD;
    int   q0 = (lane < 16) ? tI : 0x7fffffff;
    float e1 = (lane      < cnt) ? bD[lane]      : BIGD;
    int   q1 = (lane      < cnt) ? bI[lane]      : 0x7fffffff;
    float e2 = (lane + 32 < cnt) ? bD[lane + 32] : BIGD;
    int   q2 = (lane + 32 < cnt) ? bI[lane + 32] : 0x7fffffff;
    float e3 = (lane + 64 < cnt) ? bD[lane + 64] : BIGD;
    int   q3 = (lane + 64 < cnt) ? bI[lane + 64] : 0x7fffffff;
    float e4 = (lane + 96 < cnt) ? bD[lane + 96] : BIGD;
    int   q4 = (lane + 96 < cnt) ? bI[lane + 96] : 0x7fffffff;

    float nD = BIGD; int nI = 0x7fffffff;
#pragma unroll
    for (int r = 0; r < 16; r++) {
        float md = e0; int mi = q0; int ms = 0;
        if (lexless(e1, q1, md, mi)) { md = e1; mi = q1; ms = 1; }
        if (lexless(e2, q2, md, mi)) { md = e2; mi = q2; ms = 2; }
        if (lexless(e3, q3, md, mi)) { md = e3; mi = q3; ms = 3; }
        if (lexless(e4, q4, md, mi)) { md = e4; mi = q4; ms = 4; }
        int src = (lane << 3) | ms;
#pragma unroll
        for (int off = 16; off; off >>= 1) {
            float od = __shfl_xor_sync(0xffffffffu, md, off);
            int   oi = __shfl_xor_sync(0xffffffffu, mi, off);
            int   os = __shfl_xor_sync(0xffffffffu, src, off);
            if (lexless(od, oi, md, mi)) { md = od; mi = oi; src = os; }
        }
        if (lane == (src >> 3)) {
            int sl = src & 7;
            if (sl == 0)      { e0 = BIGD; q0 = 0x7fffffff; }
            else if (sl == 1) { e1 = BIGD; q1 = 0x7fffffff; }
            else if (sl == 2) { e2 = BIGD; q2 = 0x7fffffff; }
            else if (sl == 3) { e3 = BIGD; q3 = 0x7fffffff; }
            else              { e4 = BIGD; q4 = 0x7fffffff; }
        }
        if (lane == r) { nD = md; nI = mi; }
    }
    tD = nD; tI = nI;
    thrD = __shfl_sync(0xffffffffu, nD, 15);
    thrI = __shfl_sync(0xffffffffu, nI, 15);
    thr2 = __fmul_rn(__fmul_rn(thrD, thrD), 1.0000005f);
    cnt = 0;
}

__global__ __launch_bounds__(KNN_THREADS, 1)
void knn_kernel(const float* __restrict__ pos) {
    extern __shared__ float sm[];
    float* posX = sm;                      // NN
    float* posY = posX + NN;               // NN
    float* posZ = posY + NN;               // NN
    float* bufD = posZ + NN;               // KNN_WARPS*KNN_CAP
    int*   bufI = (int*)(bufD + KNN_WARPS*KNN_CAP);

    int tid = threadIdx.x;
    int warp = tid >> 5, lane = tid & 31;
    int b = blockIdx.x / (NN/KNN_WARPS);
    int n = (blockIdx.x % (NN/KNN_WARPS))*KNN_WARPS + warp;
    const float* posB = pos + (size_t)b*NN*3;
    for (int i = tid; i < NN; i += KNN_THREADS) {
        posX[i] = posB[i*3+0];
        posY[i] = posB[i*3+1];
        posZ[i] = posB[i*3+2];
    }
    __syncthreads();
    float px = posX[n], py = posY[n], pz = posZ[n];
    float* bD = bufD + warp*KNN_CAP;
    int*   bI = bufI + warp*KNN_CAP;

    float tD = BIGD; int tI = 0x7fff0000 + lane;   // lanes 0..15 hold running top-16
    float thrD = BIGD; int thrI = 0x7fffffff;
    float thr2 = __int_as_float(0x7f800000);       // +inf: accept everything at first
    int cnt = 0;

    for (int c = lane; c < NN; c += 32) {
        float dx = px - posX[c];
        float dy = py - posY[c];
        float dz = pz - posZ[c];
        float d2 = __fadd_rn(__fadd_rn(__fmul_rn(dx,dx), __fmul_rn(dy,dy)),
                             __fmul_rn(dz,dz));
        bool push = false;
        float dv = 0.0f;
        if (d2 <= thr2) {
            dv = sqrtf(d2);
            push = lexless(dv, c, thrD, thrI);
        }
        u32 mask = __ballot_sync(0xffffffffu, push);
        if (push) {
            int p = cnt + __popc(mask & ((1u << lane) - 1u));
            bD[p] = dv; bI[p] = c;
        }
        cnt += __popc(mask);
        if (cnt > KNN_CAP - 32)
            knn_flush(tD, tI, thrD, thrI, thr2, cnt, bD, bI, lane);
    }
    knn_flush(tD, tI, thrD, thrI, thr2, cnt, bD, bI, lane);

    if (lane < 16) g_idx[(b*NN + n)*KK + lane] = tI;
}

// ---------------- probe: keeps attn in the ncu fixed capture slot -----------
__global__ void probe_kernel() {}

// ---------------- kernel 3: fused attn (tensor-core MLPs) -------------------
__global__ __launch_bounds__(512, 1)
void attn_kernel(const float* __restrict__ pos,
                 const float* __restrict__ w_p1, const float* __restrict__ b_p1,
                 const float* __restrict__ w_p2, const float* __restrict__ b_p2,
                 const float* __restrict__ w_a1, const float* __restrict__ b_a1,
                 const float* __restrict__ w_a2, const float* __restrict__ b_a2,
                 const float* __restrict__ w_fc, const float* __restrict__ b_fc) {
    extern __shared__ float sm[];
    u32* w1hi = (u32*)sm;               // 8192  (32 kpairs x 256, swizzled)
    u32* w1lo = w1hi + 8192;            // 8192
    u32* w2hi = w1lo + 8192;            // 8192  (128 kpairs x 64, swizzled)
    u32* w2lo = w2hi + 8192;            // 8192
    float* h    = (float*)(w2lo + 8192);// 8448  (128 x 66) [alias: stage]
    u32* h2hi   = (u32*)(h + 8448);     // 4608  (128 x 36) [alias: scores]
    u32* h2lo   = h2hi + 4608;          // 4608
    float* t1c  = (float*)(h2lo + 4608);// 4224  (128 x 33)
    float* qs   = t1c + 4224;           // 512
    float* p0s  = qs + 512;             // 32
    float* rel  = p0s + 32;             // 384
    float* aggs = rel + 384;            // 512
    float* b_p1s = aggs + 512;          // 64
    float* b_p2s = b_p1s + 64;          // 64
    float* b_a1s = b_p2s + 64;          // 256
    float* b_a2s = b_a1s + 256;         // 64
    float* b_fcs = b_a2s + 64;          // 64
    float* w_p1s = b_fcs + 64;          // 192
    int*   sidx  = (int*)(w_p1s + 192); // 128
    float* stage  = h;                  // 8x1056 = 8448
    float* scores = (float*)h2hi;       // 128 x 65 = 8320 <= 9216

    int tid = threadIdx.x;
    int lane = tid & 31;
    int wid = tid >> 5;
    int g4 = lane >> 2, t4 = lane & 3;
    int mt = wid >> 1, hf = wid & 1;

    // ---- weight prep: bf16 split + fragment swizzle (once) ----
    for (int i = tid; i < 8192; i += 512) {
        int kp = i >> 8, n = i & 255;
        u32 hi, lo;
        split2(w_a1[(2*kp)*256 + n], w_a1[(2*kp+1)*256 + n], hi, lo);
        int dst = kp*256 + (n ^ ((kp & 3) << 3));
        w1hi[dst] = hi; w1lo[dst] = lo;
    }
    for (int i = tid; i < 8192; i += 512) {
        int kp = i >> 6, n = i & 63;
        u32 hi, lo;
        split2(w_a2[(2*kp)*64 + n], w_a2[(2*kp+1)*64 + n], hi, lo);
        int dst = kp*64 + (n ^ ((kp & 3) << 3));
        w2hi[dst] = hi; w2lo[dst] = lo;
    }
    if (tid < 192) w_p1s[tid] = w_p1[tid];
    if (tid < 256) b_a1s[tid] = b_a1[tid];
    if (tid < 64) {
        b_p1s[tid] = b_p1[tid]; b_p2s[tid] = b_p2[tid];
        b_a2s[tid] = b_a2[tid]; b_fcs[tid] = b_fc[tid];
    }
    float accY = 0.0f, accY2 = 0.0f;

    const int r0 = (tid >> 4) * 4;       // FFMA2 p2 tiling
    const int c0 = (tid & 15) * 4;
    __syncthreads();

    for (int g = blockIdx.x; g < NPTS/PTS; g += ATTN_GRID) {
        int pbase = g * PTS;
        int bofs = (pbase >> 12) << 12;

        // ---- per-point loads
        if (tid < 128) sidx[tid] = g_idx[pbase*KK + tid];
        {
            int l = tid >> 6, d = tid & 63;
            qs[tid] = g_qkv[(size_t)(pbase + l)*192 + d];
        }
        if (tid < 24) {
            int l = tid / 3, c = tid - l*3;
            p0s[l*4 + c] = pos[(size_t)(pbase + l)*3 + c];
        }
        __syncthreads();

        // ---- gather: h = q - k_nb (fp32), rel
#pragma unroll
        for (int e = 0; e < 16; e++) {
            int i = tid + e*512;
            int r = i >> 6, d = i & 63;
            int l = r >> 4;
            h[r*HP + d] = qs[l*64 + d] -
                          g_qkv[(size_t)(bofs + sidx[r])*192 + 64 + d];
        }
        if (tid < 384) {
            int r = tid / 3, c = tid - r*3;
            int l = r >> 4;
            rel[tid] = p0s[l*4 + c] - pos[(size_t)(bofs + sidx[r])*3 + c];
        }
        __syncthreads();

        // ---- pos-MLP + p2 GEMM (FFMA2, 2 k-chunks of 32)
        {
            u64 pacc[8] = {0,0,0,0,0,0,0,0};
            for (int kc = 0; kc < 2; kc++) {
#pragma unroll
                for (int e = 0; e < 8; e++) {
                    int i = tid + e*512;
                    int r = i >> 5, pp = i & 31;
                    int p = kc*32 + pp;
                    float a = b_p1s[p];
                    a = fmaf(rel[r*3+0], w_p1s[p],       a);
                    a = fmaf(rel[r*3+1], w_p1s[64 + p],  a);
                    a = fmaf(rel[r*3+2], w_p1s[128 + p], a);
                    t1c[r*33 + pp] = fmaxf(a, 0.0f);
                }
                __syncthreads();
#pragma unroll 8
                for (int kk = 0; kk < 32; kk++) {
                    int p = kc*32 + kk;
                    u64 w0 = *(const u64*)&w_p2[p*64 + c0];
                    u64 w1 = *(const u64*)&w_p2[p*64 + c0 + 2];
                    u64 a0 = splat2(t1c[(r0+0)*33 + kk]);
                    u64 a1 = splat2(t1c[(r0+1)*33 + kk]);
                    u64 a2 = splat2(t1c[(r0+2)*33 + kk]);
                    u64 a3 = splat2(t1c[(r0+3)*33 + kk]);
                    fma2(pacc[0], a0, w0); fma2(pacc[1], a0, w1);
                    fma2(pacc[2], a1, w0); fma2(pacc[3], a1, w1);
                    fma2(pacc[4], a2, w0); fma2(pacc[5], a2, w1);
                    fma2(pacc[6], a3, w0); fma2(pacc[7], a3, w1);
                }
                __syncthreads();
            }
            float bb0 = b_p2s[c0+0], bb1 = b_p2s[c0+1];
            float bb2 = b_p2s[c0+2], bb3 = b_p2s[c0+3];
#pragma unroll
            for (int i = 0; i < 4; i++) {
                float2 lo = unpack2(pacc[i*2+0]);
                float2 hi = unpack2(pacc[i*2+1]);
                float* hp = &h[(r0+i)*HP + c0];
                hp[0] += lo.x + bb0; hp[1] += lo.y + bb1;
                hp[2] += hi.x + bb2; hp[3] += hi.y + bb3;
            }
        }
        __syncthreads();

        // ---- h fp32 -> packed bf16 split (h2hi/h2lo)
#pragma unroll
        for (int e = 0; e < 8; e++) {
            int i = tid + e*512;          // 4096 pairs
            int row = i >> 5, kp = i & 31;
            float2 x = *(const float2*)&h[row*HP + 2*kp];
            u32 hi, lo;
            split2(x.x, x.y, hi, lo);
            h2hi[row*H2P + kp] = hi;
            h2lo[row*H2P + kp] = lo;
        }
        __syncthreads();

        // ---- load A fragments (h) for this warp's m-tile
        u32 ahi[16], alo[16];
        {
            int rowA = mt*16 + g4;
#pragma unroll
            for (int ks = 0; ks < 4; ks++) {
                int c = ks*8 + t4;
                ahi[ks*4+0] = h2hi[rowA*H2P + c];
                ahi[ks*4+1] = h2hi[(rowA+8)*H2P + c];
                ahi[ks*4+2] = h2hi[rowA*H2P + c + 4];
                ahi[ks*4+3] = h2hi[(rowA+8)*H2P + c + 4];
                alo[ks*4+0] = h2lo[rowA*H2P + c];
                alo[ks*4+1] = h2lo[(rowA+8)*H2P + c];
                alo[ks*4+2] = h2lo[rowA*H2P + c + 4];
                alo[ks*4+3] = h2lo[(rowA+8)*H2P + c + 4];
            }
        }

        // ---- chunked attn MLP on tensor cores (sync-free)
        float C2[32];
#pragma unroll
        for (int z = 0; z < 32; z++) C2[z] = 0.0f;

#pragma unroll
        for (int jc = 0; jc < 4; jc++) {
            u32 s2hi[8], s2lo[8];         // A2 frags: 2 k2-steps x 4 regs
#pragma unroll
            for (int u = 0; u < 2; u++) {
                float cA[4] = {0,0,0,0}, cB[4] = {0,0,0,0};
                int nbase = jc*64 + hf*32 + u*16;
                int nswA = (nbase + g4) ^ (t4 << 3);
                int nswB = (nbase + 8 + g4) ^ (t4 << 3);
#pragma unroll
                for (int ks = 0; ks < 4; ks++) {
                    int kp0 = ks*8 + t4;
                    u32 bh0 = w1hi[kp0*256 + nswA];
                    u32 bh1 = w1hi[(kp0+4)*256 + nswA];
                    u32 bl0 = w1lo[kp0*256 + nswA];
                    u32 bl1 = w1lo[(kp0+4)*256 + nswA];
                    mma16816(cA, &ahi[ks*4], bh0, bh1);
                    mma16816(cA, &ahi[ks*4], bl0, bl1);
                    mma16816(cA, &alo[ks*4], bh0, bh1);
                    u32 ch0 = w1hi[kp0*256 + nswB];
                    u32 ch1 = w1hi[(kp0+4)*256 + nswB];
                    u32 cl0 = w1lo[kp0*256 + nswB];
                    u32 cl1 = w1lo[(kp0+4)*256 + nswB];
                    mma16816(cB, &ahi[ks*4], ch0, ch1);
                    mma16816(cB, &ahi[ks*4], cl0, cl1);
                    mma16816(cB, &alo[ks*4], ch0, ch1);
                }
                // bias + relu + split -> A2 fragment for k2-step u
                int cb = nbase + t4*2;
                float bA0 = b_a1s[cb],     bA1 = b_a1s[cb+1];
                float bB0 = b_a1s[cb+8],   bB1 = b_a1s[cb+9];
                float sA0 = fmaxf(cA[0] + bA0, 0.0f);
                float sA1 = fmaxf(cA[1] + bA1, 0.0f);
                float sA2 = fmaxf(cA[2] + bA0, 0.0f);
                float sA3 = fmaxf(cA[3] + bA1, 0.0f);
                float sB0 = fmaxf(cB[0] + bB0, 0.0f);
                float sB1 = fmaxf(cB[1] + bB1, 0.0f);
                float sB2 = fmaxf(cB[2] + bB0, 0.0f);
                float sB3 = fmaxf(cB[3] + bB1, 0.0f);
                split2(sA0, sA1, s2hi[u*4+0], s2lo[u*4+0]);
                split2(sA2, sA3, s2hi[u*4+1], s2lo[u*4+1]);
                split2(sB0, sB1, s2hi[u*4+2], s2lo[u*4+2]);
                split2(sB2, sB3, s2hi[u*4+3], s2lo[u*4+3]);
            }
            // GEMM2 chunk: C2 += s1_chunk @ w_a2[k2-range]
#pragma unroll
            for (int nt = 0; nt < 8; nt++) {
#pragma unroll
                for (int u = 0; u < 2; u++) {
                    int kp = jc*32 + hf*16 + u*8 + t4;
                    int nsw = (nt*8 + g4) ^ (t4 << 3);
                    u32 bh0 = w2hi[kp*64 + nsw];
                    u32 bh1 = w2hi[(kp+4)*64 + nsw];
                    u32 bl0 = w2lo[kp*64 + nsw];
                    u32 bl1 = w2lo[(kp+4)*64 + nsw];
                    mma16816(&C2[nt*4], &s2hi[u*4], bh0, bh1);
                    mma16816(&C2[nt*4], &s2hi[u*4], bl0, bl1);
                    mma16816(&C2[nt*4], &s2lo[u*4], bh0, bh1);
                }
            }
        }

        // ---- cross-half reduction of scores
        if (hf) {
            float* sp = stage + mt*1056 + lane*33;
#pragma unroll
            for (int z = 0; z < 32; z++) sp[z] = C2[z];
        }
        __syncthreads();
        if (!hf) {
            float* sp = stage + mt*1056 + lane*33;
#pragma unroll
            for (int nt = 0; nt < 8; nt++) {
                int cb = nt*8 + t4*2;
                float v0 = C2[nt*4+0] + sp[nt*4+0] + b_a2s[cb];
                float v1 = C2[nt*4+1] + sp[nt*4+1] + b_a2s[cb+1];
                float v2 = C2[nt*4+2] + sp[nt*4+2] + b_a2s[cb];
                float v3 = C2[nt*4+3] + sp[nt*4+3] + b_a2s[cb+1];
                scores[(mt*16 + g4)*SCP + cb]     = v0;
                scores[(mt*16 + g4)*SCP + cb + 1] = v1;
                scores[(mt*16 + g4 + 8)*SCP + cb]     = v2;
                scores[(mt*16 + g4 + 8)*SCP + cb + 1] = v3;
            }
        }
        __syncthreads();

        // ---- softmax over K + weighted v-sum (v from L2)
        {
            int l = tid >> 6, d = tid & 63;
            float vreg[16];
#pragma unroll
            for (int k = 0; k < 16; k++)
                vreg[k] = g_qkv[(size_t)(bofs + sidx[l*16 + k])*192 + 128 + d];
            float mx = -3.0e38f;
#pragma unroll
            for (int k = 0; k < 16; k++)
                mx = fmaxf(mx, scores[(l*16 + k)*SCP + d]);
            float ssum = 0.0f, a = 0.0f;
#pragma unroll
            for (int k = 0; k < 16; k++) {
                float e = __expf(scores[(l*16 + k)*SCP + d] - mx);
                ssum += e;
                a = fmaf(e, vreg[k], a);
            }
            aggs[tid] = a / ssum;
        }
        __syncthreads();

        // ---- fc (w_fc via L1/L2) + BN partials
        {
            int l = tid >> 6, d = tid & 63;
            float y = b_fcs[d];
#pragma unroll 8
            for (int c = 0; c < 64; c++)
                y = fmaf(aggs[l*64 + c], w_fc[c*64 + d], y);
            g_y[(size_t)(pbase + l)*64 + d] = y;
            accY += y;
            accY2 = fmaf(y, y, accY2);
        }
        __syncthreads();
    }

    // ---- reduce BN partials (reuse h as scratch)
    float* red = h;
    red[tid] = accY;
    __syncthreads();
    if (tid < 64) {
        float s = 0.0f;
#pragma unroll
        for (int q = 0; q < 8; q++) s += red[q*64 + tid];
        g_part[blockIdx.x*128 + tid] = s;
    }
    __syncthreads();
    red[tid] = accY2;
    __syncthreads();
    if (tid < 64) {
        float s = 0.0f;
#pragma unroll
        for (int q = 0; q < 8; q++) s += red[q*64 + tid];
        g_part[blockIdx.x*128 + 64 + tid] = s;
    }
}

// ---------------- kernel 4: finish BN statistics ----------------------------
__global__ void bnstats_kernel() {
    __shared__ float sred[2048];
    int tid = threadIdx.x;            // 1024
    int d = tid & 63, q = tid >> 6;   // 16 groups
    float s = 0.0f, s2 = 0.0f;
    for (int blk = q; blk < ATTN_GRID; blk += 16) {
        s  += g_part[blk*128 + d];
        s2 += g_part[blk*128 + 64 + d];
    }
    sred[tid] = s; sred[1024 + tid] = s2;
    __syncthreads();
    if (tid < 64) {
        float ts = 0.0f, ts2 = 0.0f;
#pragma unroll
        for (int k = 0; k < 16; k++) {
            ts  += sred[k*64 + d];
            ts2 += sred[1024 + k*64 + d];
        }
        float mean = ts / (float)NPTS;
        float var  = ts2 / (float)NPTS - mean*mean;
        g_mv[d]      = mean;
        g_mv[64 + d] = rsqrtf(var + 1e-5f);
    }
}

// ---------------- kernel 5: BN apply + relu + residual ----------------------
__global__ void final_kernel(const float* __restrict__ x,
                             const float* __restrict__ gamma,
                             const float* __restrict__ beta,
                             float* __restrict__ out) {
    int i = blockIdx.x * blockDim.x + threadIdx.x;
    if (i < NPTS*DD) {
        int d = i & 63;
        float yv = (g_y[i] - g_mv[d]) * g_mv[64 + d] * gamma[d] + beta[d];
        out[i] = fmaxf(yv, 0.0f) + x[i];
    }
}

// ---------------- launch -----------------------------------------------------
extern "C" void kernel_launch(void* const* d_in, const int* in_sizes, int n_in,
                              void* d_out, int out_size) {
    const float* x     = (const float*)d_in[0];
    const float* pos   = (const float*)d_in[1];
    const float* w_qkv = (const float*)d_in[2];
    const float* b_qkv = (const float*)d_in[3];
    const float* w_p1  = (const float*)d_in[4];
    const float* b_p1  = (const float*)d_in[5];
    const float* w_p2  = (const float*)d_in[6];
    const float* b_p2  = (const float*)d_in[7];
    const float* w_a1  = (const float*)d_in[8];
    const float* b_a1  = (const float*)d_in[9];
    const float* w_a2  = (const float*)d_in[10];
    const float* b_a2  = (const float*)d_in[11];
    const float* w_fc  = (const float*)d_in[12];
    const float* b_fc  = (const float*)d_in[13];
    const float* gamma = (const float*)d_in[14];
    const float* beta  = (const float*)d_in[15];
    float* out = (float*)d_out;

    const int smem_qkv  = (64*192 + 64*64) * 4;
    const int smem_knn  = 3*NN*4 + KNN_WARPS*KNN_CAP*8;   // 64 KB
    const int smem_attn = (8192*4 + 8448 + 9216 + 4224
                           + 512 + 32 + 384 + 512
                           + 64 + 64 + 256 + 64 + 64 + 192 + 128) * 4;  // 227712 B

    cudaFuncSetAttribute(qkv_kernel,  cudaFuncAttributeMaxDynamicSharedMemorySize, smem_qkv);
    cudaFuncSetAttribute(knn_kernel,  cudaFuncAttributeMaxDynamicSharedMemorySize, smem_knn);
    cudaFuncSetAttribute(attn_kernel, cudaFuncAttributeMaxDynamicSharedMemorySize, smem_attn);

    qkv_kernel<<<NPTS/64, 192, smem_qkv>>>(x, w_qkv, b_qkv);
    knn_kernel<<<NPTS/KNN_WARPS, KNN_THREADS, smem_knn>>>(pos);
    probe_kernel<<<1, 32>>>();
    attn_kernel<<<ATTN_GRID, 512, smem_attn>>>(pos, w_p1, b_p1, w_p2, b_p2,
                                               w_a1, b_a1, w_a2, b_a2, w_fc, b_fc);
    bnstats_kernel<<<1, 1024>>>();
    final_kernel<<<(NPTS*DD + 255)/256, 256>>>(x, gamma, beta, out);
}

// round 9
// speedup vs baseline: 2.8452x; 1.1958x over previous
#include <cuda_runtime.h>
#include <cuda_bf16.h>
#include <math.h>

#define BB 2
#define NN 4096
#define DD 64
#define HH 256
#define KK 16
#define NPTS (BB*NN)
#define ATTN_GRID 148
#define PTS 8               // points per iteration
#define ROWS 128            // PTS * KK rows
#define H2P 36              // packed bf16x2 row stride (u32)
#define SCP 65              // scores row stride

#define KNN_WARPS 16
#define KNN_THREADS 512
#define KNN_CAP 128
#define BIGD 3.0e38f

typedef unsigned long long u64;
typedef unsigned int u32;

// split two fp32 into packed bf16x2 hi and lo parts (x0 -> low half)
__device__ __forceinline__ void split2(float x0, float x1, u32& hi, u32& lo) {
    __nv_bfloat16 h0 = __float2bfloat16_rn(x0);
    __nv_bfloat16 h1 = __float2bfloat16_rn(x1);
    __nv_bfloat16 l0 = __float2bfloat16_rn(x0 - __bfloat162float(h0));
    __nv_bfloat16 l1 = __float2bfloat16_rn(x1 - __bfloat162float(h1));
    hi = (u32)*(unsigned short*)&h0 | ((u32)*(unsigned short*)&h1 << 16);
    lo = (u32)*(unsigned short*)&l0 | ((u32)*(unsigned short*)&l1 << 16);
}

__device__ __forceinline__ void mma16816(float* c, const u32* a, u32 b0, u32 b1) {
    asm volatile(
        "mma.sync.aligned.m16n8k16.row.col.f32.bf16.bf16.f32 "
        "{%0,%1,%2,%3}, {%4,%5,%6,%7}, {%8,%9}, {%0,%1,%2,%3};"
        : "+f"(c[0]), "+f"(c[1]), "+f"(c[2]), "+f"(c[3])
        : "r"(a[0]), "r"(a[1]), "r"(a[2]), "r"(a[3]), "r"(b0), "r"(b1));
}

// ---------------- scratch ----------------------------------------------------
__device__ float g_qkv[NPTS*192];      // q|k|v per point
__device__ int   g_idx[NPTS*KK];       // knn indices
__device__ float g_y[NPTS*DD];         // pre-BN output of fc
__device__ float g_part[ATTN_GRID*2*DD];
__device__ float g_mv[2*DD];           // mean, rstd

// ---------------- kernel 1: QKV GEMM  (8192x64 @ 64x192) -------------------
__global__ void qkv_kernel(const float* __restrict__ x,
                           const float* __restrict__ w,
                           const float* __restrict__ bq) {
    extern __shared__ float sm[];
    float* ws = sm;             // 64*192
    float* xs = sm + 64*192;    // 64*64
    int tid = threadIdx.x;      // 192 threads
    for (int i = tid; i < 64*192; i += 192) ws[i] = w[i];
    int row0 = blockIdx.x * 64;
    for (int i = tid; i < 64*64; i += 192) xs[i] = x[row0*64 + i];
    __syncthreads();
    float bb = bq[tid];
    for (int r0 = 0; r0 < 64; r0 += 8) {
        float acc[8];
#pragma unroll
        for (int r = 0; r < 8; r++) acc[r] = bb;
        for (int i = 0; i < 64; i++) {
            float wv = ws[i*192 + tid];
#pragma unroll
            for (int r = 0; r < 8; r++) acc[r] = fmaf(xs[(r0+r)*64 + i], wv, acc[r]);
        }
#pragma unroll
        for (int r = 0; r < 8; r++) g_qkv[(row0 + r0 + r)*192 + tid] = acc[r];
    }
}

// ---------------- kernel 2: KNN (warp threshold-filter, exact) --------------
__device__ __forceinline__ bool lexless(float d1, int i1, float d2, int i2) {
    return (d1 < d2) || (d1 == d2 && i1 < i2);
}

__device__ __forceinline__ void knn_flush(
    float& tD, int& tI, float& thrD, int& thrI, float& thr2,
    int& cnt, const float* bD, const int* bI, int lane)
{
    float e0 = (lane < 16) ? tD : BIGD;
    int   q0 = (lane < 16) ? tI : 0x7fffffff;
    float e1 = (lane      < cnt) ? bD[lane]      : BIGD;
    int   q1 = (lane      < cnt) ? bI[lane]      : 0x7fffffff;
    float e2 = (lane + 32 < cnt) ? bD[lane + 32] : BIGD;
    int   q2 = (lane + 32 < cnt) ? bI[lane + 32] : 0x7fffffff;
    float e3 = (lane + 64 < cnt) ? bD[lane + 64] : BIGD;
    int   q3 = (lane + 64 < cnt) ? bI[lane + 64] : 0x7fffffff;
    float e4 = (lane + 96 < cnt) ? bD[lane + 96] : BIGD;
    int   q4 = (lane + 96 < cnt) ? bI[lane + 96] : 0x7fffffff;

    float nD = BIGD; int nI = 0x7fffffff;
#pragma unroll
    for (int r = 0; r < 16; r++) {
        float md = e0; int mi = q0; int ms = 0;
        if (lexless(e1, q1, md, mi)) { md = e1; mi = q1; ms = 1; }
        if (lexless(e2, q2, md, mi)) { md = e2; mi = q2; ms = 2; }
        if (lexless(e3, q3, md, mi)) { md = e3; mi = q3; ms = 3; }
        if (lexless(e4, q4, md, mi)) { md = e4; mi = q4; ms = 4; }
        int src = (lane << 3) | ms;
#pragma unroll
        for (int off = 16; off; off >>= 1) {
            float od = __shfl_xor_sync(0xffffffffu, md, off);
            int   oi = __shfl_xor_sync(0xffffffffu, mi, off);
            int   os = __shfl_xor_sync(0xffffffffu, src, off);
            if (lexless(od, oi, md, mi)) { md = od; mi = oi; src = os; }
        }
        if (lane == (src >> 3)) {
            int sl = src & 7;
            if (sl == 0)      { e0 = BIGD; q0 = 0x7fffffff; }
            else if (sl == 1) { e1 = BIGD; q1 = 0x7fffffff; }
            else if (sl == 2) { e2 = BIGD; q2 = 0x7fffffff; }
            else if (sl == 3) { e3 = BIGD; q3 = 0x7fffffff; }
            else              { e4 = BIGD; q4 = 0x7fffffff; }
        }
        if (lane == r) { nD = md; nI = mi; }
    }
    tD = nD; tI = nI;
    thrD = __shfl_sync(0xffffffffu, nD, 15);
    thrI = __shfl_sync(0xffffffffu, nI, 15);
    thr2 = __fmul_rn(__fmul_rn(thrD, thrD), 1.0000005f);
    cnt = 0;
}

__global__ __launch_bounds__(KNN_THREADS, 1)
void knn_kernel(const float* __restrict__ pos) {
    extern __shared__ float sm[];
    float* posX = sm;                      // NN
    float* posY = posX + NN;               // NN
    float* posZ = posY + NN;               // NN
    float* bufD = posZ + NN;               // KNN_WARPS*KNN_CAP
    int*   bufI = (int*)(bufD + KNN_WARPS*KNN_CAP);

    int tid = threadIdx.x;
    int warp = tid >> 5, lane = tid & 31;
    int b = blockIdx.x / (NN/KNN_WARPS);
    int n = (blockIdx.x % (NN/KNN_WARPS))*KNN_WARPS + warp;
    const float* posB = pos + (size_t)b*NN*3;
    for (int i = tid; i < NN; i += KNN_THREADS) {
        posX[i] = posB[i*3+0];
        posY[i] = posB[i*3+1];
        posZ[i] = posB[i*3+2];
    }
    __syncthreads();
    float px = posX[n], py = posY[n], pz = posZ[n];
    float* bD = bufD + warp*KNN_CAP;
    int*   bI = bufI + warp*KNN_CAP;

    float tD = BIGD; int tI = 0x7fff0000 + lane;
    float thrD = BIGD; int thrI = 0x7fffffff;
    float thr2 = __int_as_float(0x7f800000);
    int cnt = 0;

    for (int c = lane; c < NN; c += 32) {
        float dx = px - posX[c];
        float dy = py - posY[c];
        float dz = pz - posZ[c];
        float d2 = __fadd_rn(__fadd_rn(__fmul_rn(dx,dx), __fmul_rn(dy,dy)),
                             __fmul_rn(dz,dz));
        bool push = false;
        float dv = 0.0f;
        if (d2 <= thr2) {
            dv = sqrtf(d2);
            push = lexless(dv, c, thrD, thrI);
        }
        u32 mask = __ballot_sync(0xffffffffu, push);
        if (push) {
            int p = cnt + __popc(mask & ((1u << lane) - 1u));
            bD[p] = dv; bI[p] = c;
        }
        cnt += __popc(mask);
        if (cnt > KNN_CAP - 32)
            knn_flush(tD, tI, thrD, thrI, thr2, cnt, bD, bI, lane);
    }
    knn_flush(tD, tI, thrD, thrI, thr2, cnt, bD, bI, lane);

    if (lane < 16) g_idx[(b*NN + n)*KK + lane] = tI;
}

// ---------------- probes: put knn in the ncu fixed capture slot (#3) --------
__global__ void probe_kernel() {}
__global__ void probe_kernel2() {}

// ---------------- kernel 3: fused attn (all GEMMs on tensor cores) ----------
__global__ __launch_bounds__(512, 1)
void attn_kernel(const float* __restrict__ pos,
                 const float* __restrict__ w_p1, const float* __restrict__ b_p1,
                 const float* __restrict__ w_p2, const float* __restrict__ b_p2,
                 const float* __restrict__ w_a1, const float* __restrict__ b_a1,
                 const float* __restrict__ w_a2, const float* __restrict__ b_a2,
                 const float* __restrict__ w_fc, const float* __restrict__ b_fc) {
    extern __shared__ float sm[];
    u32* w1hi  = (u32*)sm;                // 8192
    u32* w1lo  = w1hi + 8192;             // 8192
    u32* w2hi  = w1lo + 8192;             // 8192
    u32* w2lo  = w2hi + 8192;             // 8192
    u32* w2phi = w2lo + 8192;             // 2048  (w_p2 as MMA-B)
    u32* w2plo = w2phi + 2048;            // 2048
    u32* t1hi  = w2plo + 2048;            // 4608  [row x 36]  (alias: stage)
    u32* t1lo  = t1hi + 4608;             // 4608
    u32* h2hi  = t1lo + 4608;             // 4608  [row x 36]  (alias: scores)
    u32* h2lo  = h2hi + 4608;             // 4608
    float* qs    = (float*)(h2lo + 4608); // 512
    float* p0s   = qs + 512;              // 32
    float* rel   = p0s + 32;              // 384
    float* aggs  = rel + 384;             // 512
    float* b_p1s = aggs + 512;            // 64
    float* b_p2s = b_p1s + 64;            // 64
    float* b_a1s = b_p2s + 64;            // 256
    float* b_a2s = b_a1s + 256;           // 64
    float* b_fcs = b_a2s + 64;            // 64
    float* w_p1s = b_fcs + 64;            // 192
    int*   sidx  = (int*)(w_p1s + 192);   // 128
    float* stage  = (float*)t1hi;         // 8 x 1056 = 8448 f32 (<= 9216 u32)
    float* scores = (float*)h2hi;         // 128 x 65 = 8320 f32 (<= 9216 u32)

    int tid = threadIdx.x;
    int lane = tid & 31;
    int wid = tid >> 5;
    int g4 = lane >> 2, t4 = lane & 3;
    int mt = wid >> 1, hf = wid & 1;      // MLP-chain mapping
    int mtp = wid >> 1, nh = wid & 1;     // p2-MMA mapping (same split)

    // ---- weight prep: bf16 split + fragment swizzle (once) ----
    for (int i = tid; i < 8192; i += 512) {
        int kp = i >> 8, n = i & 255;
        u32 hi, lo;
        split2(w_a1[(2*kp)*256 + n], w_a1[(2*kp+1)*256 + n], hi, lo);
        int dst = kp*256 + (n ^ ((kp & 3) << 3));
        w1hi[dst] = hi; w1lo[dst] = lo;
    }
    for (int i = tid; i < 8192; i += 512) {
        int kp = i >> 6, n = i & 63;
        u32 hi, lo;
        split2(w_a2[(2*kp)*64 + n], w_a2[(2*kp+1)*64 + n], hi, lo);
        int dst = kp*64 + (n ^ ((kp & 3) << 3));
        w2hi[dst] = hi; w2lo[dst] = lo;
    }
    for (int i = tid; i < 2048; i += 512) {
        int kp = i >> 6, n = i & 63;
        u32 hi, lo;
        split2(w_p2[(2*kp)*64 + n], w_p2[(2*kp+1)*64 + n], hi, lo);
        int dst = kp*64 + (n ^ ((kp & 3) << 3));
        w2phi[dst] = hi; w2plo[dst] = lo;
    }
    if (tid < 192) w_p1s[tid] = w_p1[tid];
    if (tid < 256) b_a1s[tid] = b_a1[tid];
    if (tid < 64) {
        b_p1s[tid] = b_p1[tid]; b_p2s[tid] = b_p2[tid];
        b_a2s[tid] = b_a2[tid]; b_fcs[tid] = b_fc[tid];
    }
    float accY = 0.0f, accY2 = 0.0f;
    __syncthreads();

    for (int g = blockIdx.x; g < NPTS/PTS; g += ATTN_GRID) {
        int pbase = g * PTS;
        int bofs = (pbase >> 12) << 12;

        // ---- A: per-point loads
        if (tid < 128) sidx[tid] = g_idx[pbase*KK + tid];
        {
            int l = tid >> 6, d = tid & 63;
            qs[tid] = g_qkv[(size_t)(pbase + l)*192 + d];
        }
        if (tid < 24) {
            int l = tid / 3, c = tid - l*3;
            p0s[l*4 + c] = pos[(size_t)(pbase + l)*3 + c];
        }
        __syncthreads();

        // ---- B: rel
        if (tid < 384) {
            int r = tid / 3, c = tid - r*3;
            int l = r >> 4;
            rel[tid] = p0s[l*4 + c] - pos[(size_t)(bofs + sidx[r])*3 + c];
        }
        __syncthreads();

        // ---- C: pos-MLP -> t1 (bf16 split tiles)
#pragma unroll
        for (int e = 0; e < 8; e++) {
            int i = tid + e*512;              // 4096 pairs
            int r = i >> 5, kp = i & 31;
            int pp = kp*2;
            float r0v = rel[r*3+0], r1v = rel[r*3+1], r2v = rel[r*3+2];
            float a0 = b_p1s[pp];
            a0 = fmaf(r0v, w_p1s[pp],        a0);
            a0 = fmaf(r1v, w_p1s[64 + pp],   a0);
            a0 = fmaf(r2v, w_p1s[128 + pp],  a0);
            float a1 = b_p1s[pp+1];
            a1 = fmaf(r0v, w_p1s[pp+1],      a1);
            a1 = fmaf(r1v, w_p1s[64 + pp+1], a1);
            a1 = fmaf(r2v, w_p1s[128 + pp+1],a1);
            a0 = fmaxf(a0, 0.0f); a1 = fmaxf(a1, 0.0f);
            u32 hi, lo;
            split2(a0, a1, hi, lo);
            t1hi[r*H2P + kp] = hi;
            t1lo[r*H2P + kp] = lo;
        }
        __syncthreads();

        // ---- D: p2 on MMA + qk gather in C-frag positions -> h2
        {
            // A frags from t1 (this warp's point = mtp)
            u32 pahi[16], palo[16];
            int rowA = mtp*16 + g4;
#pragma unroll
            for (int ks = 0; ks < 4; ks++) {
                int c = ks*8 + t4;
                pahi[ks*4+0] = t1hi[rowA*H2P + c];
                pahi[ks*4+1] = t1hi[(rowA+8)*H2P + c];
                pahi[ks*4+2] = t1hi[rowA*H2P + c + 4];
                pahi[ks*4+3] = t1hi[(rowA+8)*H2P + c + 4];
                palo[ks*4+0] = t1lo[rowA*H2P + c];
                palo[ks*4+1] = t1lo[(rowA+8)*H2P + c];
                palo[ks*4+2] = t1lo[rowA*H2P + c + 4];
                palo[ks*4+3] = t1lo[(rowA+8)*H2P + c + 4];
            }
            float cP[16];
#pragma unroll
            for (int z = 0; z < 16; z++) cP[z] = 0.0f;
#pragma unroll
            for (int ntl = 0; ntl < 4; ntl++) {
                int nsw = (nh*32 + ntl*8 + g4) ^ (t4 << 3);
#pragma unroll
                for (int ks = 0; ks < 4; ks++) {
                    int kp0 = ks*8 + t4;
                    u32 bh0 = w2phi[kp0*64 + nsw];
                    u32 bh1 = w2phi[(kp0+4)*64 + nsw];
                    u32 bl0 = w2plo[kp0*64 + nsw];
                    u32 bl1 = w2plo[(kp0+4)*64 + nsw];
                    mma16816(&cP[ntl*4], &pahi[ks*4], bh0, bh1);
                    mma16816(&cP[ntl*4], &pahi[ks*4], bl0, bl1);
                    mma16816(&cP[ntl*4], &palo[ks*4], bh0, bh1);
                }
            }
            int r1 = mtp*16 + g4, r2 = r1 + 8;
            const float* krow1 = g_qkv + (size_t)(bofs + sidx[r1])*192 + 64;
            const float* krow2 = g_qkv + (size_t)(bofs + sidx[r2])*192 + 64;
#pragma unroll
            for (int ntl = 0; ntl < 4; ntl++) {
                int cb = nh*32 + ntl*8 + t4*2;
                float2 k1 = *(const float2*)&krow1[cb];
                float2 k2 = *(const float2*)&krow2[cb];
                float2 q1 = *(const float2*)&qs[mtp*64 + cb];
                float bb0 = b_p2s[cb], bb1 = b_p2s[cb+1];
                float h10 = (q1.x - k1.x) + cP[ntl*4+0] + bb0;
                float h11 = (q1.y - k1.y) + cP[ntl*4+1] + bb1;
                float h20 = (q1.x - k2.x) + cP[ntl*4+2] + bb0;
                float h21 = (q1.y - k2.y) + cP[ntl*4+3] + bb1;
                int kp = cb >> 1;
                u32 hi, lo;
                split2(h10, h11, hi, lo);
                h2hi[r1*H2P + kp] = hi; h2lo[r1*H2P + kp] = lo;
                split2(h20, h21, hi, lo);
                h2hi[r2*H2P + kp] = hi; h2lo[r2*H2P + kp] = lo;
            }
        }
        __syncthreads();

        // ---- E: load A1 fragments (h2) for this warp's m-tile
        u32 ahi[16], alo[16];
        {
            int rowA = mt*16 + g4;
#pragma unroll
            for (int ks = 0; ks < 4; ks++) {
                int c = ks*8 + t4;
                ahi[ks*4+0] = h2hi[rowA*H2P + c];
                ahi[ks*4+1] = h2hi[(rowA+8)*H2P + c];
                ahi[ks*4+2] = h2hi[rowA*H2P + c + 4];
                ahi[ks*4+3] = h2hi[(rowA+8)*H2P + c + 4];
                alo[ks*4+0] = h2lo[rowA*H2P + c];
                alo[ks*4+1] = h2lo[(rowA+8)*H2P + c];
                alo[ks*4+2] = h2lo[rowA*H2P + c + 4];
                alo[ks*4+3] = h2lo[(rowA+8)*H2P + c + 4];
            }
        }

        // ---- F: chunked attn MLP on tensor cores (sync-free)
        float C2[32];
#pragma unroll
        for (int z = 0; z < 32; z++) C2[z] = 0.0f;

#pragma unroll
        for (int jc = 0; jc < 4; jc++) {
            u32 s2hi[8], s2lo[8];
#pragma unroll
            for (int u = 0; u < 2; u++) {
                float cA[4] = {0,0,0,0}, cB[4] = {0,0,0,0};
                int nbase = jc*64 + hf*32 + u*16;
                int nswA = (nbase + g4) ^ (t4 << 3);
                int nswB = (nbase + 8 + g4) ^ (t4 << 3);
#pragma unroll
                for (int ks = 0; ks < 4; ks++) {
                    int kp0 = ks*8 + t4;
                    u32 bh0 = w1hi[kp0*256 + nswA];
                    u32 bh1 = w1hi[(kp0+4)*256 + nswA];
                    u32 bl0 = w1lo[kp0*256 + nswA];
                    u32 bl1 = w1lo[(kp0+4)*256 + nswA];
                    mma16816(cA, &ahi[ks*4], bh0, bh1);
                    mma16816(cA, &ahi[ks*4], bl0, bl1);
                    mma16816(cA, &alo[ks*4], bh0, bh1);
                    u32 ch0 = w1hi[kp0*256 + nswB];
                    u32 ch1 = w1hi[(kp0+4)*256 + nswB];
                    u32 cl0 = w1lo[kp0*256 + nswB];
                    u32 cl1 = w1lo[(kp0+4)*256 + nswB];
                    mma16816(cB, &ahi[ks*4], ch0, ch1);
                    mma16816(cB, &ahi[ks*4], cl0, cl1);
                    mma16816(cB, &alo[ks*4], ch0, ch1);
                }
                int cb = nbase + t4*2;
                float bA0 = b_a1s[cb],   bA1 = b_a1s[cb+1];
                float bB0 = b_a1s[cb+8], bB1 = b_a1s[cb+9];
                float sA0 = fmaxf(cA[0] + bA0, 0.0f);
                float sA1 = fmaxf(cA[1] + bA1, 0.0f);
                float sA2 = fmaxf(cA[2] + bA0, 0.0f);
                float sA3 = fmaxf(cA[3] + bA1, 0.0f);
                float sB0 = fmaxf(cB[0] + bB0, 0.0f);
                float sB1 = fmaxf(cB[1] + bB1, 0.0f);
                float sB2 = fmaxf(cB[2] + bB0, 0.0f);
                float sB3 = fmaxf(cB[3] + bB1, 0.0f);
                split2(sA0, sA1, s2hi[u*4+0], s2lo[u*4+0]);
                split2(sA2, sA3, s2hi[u*4+1], s2lo[u*4+1]);
                split2(sB0, sB1, s2hi[u*4+2], s2lo[u*4+2]);
                split2(sB2, sB3, s2hi[u*4+3], s2lo[u*4+3]);
            }
#pragma unroll
            for (int nt = 0; nt < 8; nt++) {
#pragma unroll
                for (int u = 0; u < 2; u++) {
                    int kp = jc*32 + hf*16 + u*8 + t4;
                    int nsw = (nt*8 + g4) ^ (t4 << 3);
                    u32 bh0 = w2hi[kp*64 + nsw];
                    u32 bh1 = w2hi[(kp+4)*64 + nsw];
                    u32 bl0 = w2lo[kp*64 + nsw];
                    u32 bl1 = w2lo[(kp+4)*64 + nsw];
                    mma16816(&C2[nt*4], &s2hi[u*4], bh0, bh1);
                    mma16816(&C2[nt*4], &s2hi[u*4], bl0, bl1);
                    mma16816(&C2[nt*4], &s2lo[u*4], bh0, bh1);
                }
            }
        }

        // ---- cross-half reduction of scores (stage in t1 region)
        if (hf) {
            float* sp = stage + mt*1056 + lane*33;
#pragma unroll
            for (int z = 0; z < 32; z++) sp[z] = C2[z];
        }
        __syncthreads();
        if (!hf) {
            float* sp = stage + mt*1056 + lane*33;
#pragma unroll
            for (int nt = 0; nt < 8; nt++) {
                int cb = nt*8 + t4*2;
                float v0 = C2[nt*4+0] + sp[nt*4+0] + b_a2s[cb];
                float v1 = C2[nt*4+1] + sp[nt*4+1] + b_a2s[cb+1];
                float v2 = C2[nt*4+2] + sp[nt*4+2] + b_a2s[cb];
                float v3 = C2[nt*4+3] + sp[nt*4+3] + b_a2s[cb+1];
                scores[(mt*16 + g4)*SCP + cb]         = v0;
                scores[(mt*16 + g4)*SCP + cb + 1]     = v1;
                scores[(mt*16 + g4 + 8)*SCP + cb]     = v2;
                scores[(mt*16 + g4 + 8)*SCP + cb + 1] = v3;
            }
        }
        __syncthreads();

        // ---- G: softmax over K + weighted v-sum (v from L2)
        {
            int l = tid >> 6, d = tid & 63;
            float vreg[16];
#pragma unroll
            for (int k = 0; k < 16; k++)
                vreg[k] = g_qkv[(size_t)(bofs + sidx[l*16 + k])*192 + 128 + d];
            float mx = -3.0e38f;
#pragma unroll
            for (int k = 0; k < 16; k++)
                mx = fmaxf(mx, scores[(l*16 + k)*SCP + d]);
            float ssum = 0.0f, a = 0.0f;
#pragma unroll
            for (int k = 0; k < 16; k++) {
                float e = __expf(scores[(l*16 + k)*SCP + d] - mx);
                ssum += e;
                a = fmaf(e, vreg[k], a);
            }
            aggs[tid] = a / ssum;
        }
        __syncthreads();

        // ---- H: fc (w_fc via L1/L2) + BN partials
        {
            int l = tid >> 6, d = tid & 63;
            float y = b_fcs[d];
#pragma unroll 8
            for (int c = 0; c < 64; c++)
                y = fmaf(aggs[l*64 + c], w_fc[c*64 + d], y);
            g_y[(size_t)(pbase + l)*64 + d] = y;
            accY += y;
            accY2 = fmaf(y, y, accY2);
        }
        __syncthreads();
    }

    // ---- reduce BN partials (t1 region as scratch)
    float* red = (float*)t1hi;
    red[tid] = accY;
    __syncthreads();
    if (tid < 64) {
        float s = 0.0f;
#pragma unroll
        for (int q = 0; q < 8; q++) s += red[q*64 + tid];
        g_part[blockIdx.x*128 + tid] = s;
    }
    __syncthreads();
    red[tid] = accY2;
    __syncthreads();
    if (tid < 64) {
        float s = 0.0f;
#pragma unroll
        for (int q = 0; q < 8; q++) s += red[q*64 + tid];
        g_part[blockIdx.x*128 + 64 + tid] = s;
    }
}

// ---------------- kernel 4: finish BN statistics ----------------------------
__global__ void bnstats_kernel() {
    __shared__ float sred[2048];
    int tid = threadIdx.x;            // 1024
    int d = tid & 63, q = tid >> 6;   // 16 groups
    float s = 0.0f, s2 = 0.0f;
    for (int blk = q; blk < ATTN_GRID; blk += 16) {
        s  += g_part[blk*128 + d];
        s2 += g_part[blk*128 + 64 + d];
    }
    sred[tid] = s; sred[1024 + tid] = s2;
    __syncthreads();
    if (tid < 64) {
        float ts = 0.0f, ts2 = 0.0f;
#pragma unroll
        for (int k = 0; k < 16; k++) {
            ts  += sred[k*64 + d];
            ts2 += sred[1024 + k*64 + d];
        }
        float mean = ts / (float)NPTS;
        float var  = ts2 / (float)NPTS - mean*mean;
        g_mv[d]      = mean;
        g_mv[64 + d] = rsqrtf(var + 1e-5f);
    }
}

// ---------------- kernel 5: BN apply + relu + residual ----------------------
__global__ void final_kernel(const float* __restrict__ x,
                             const float* __restrict__ gamma,
                             const float* __restrict__ beta,
                             float* __restrict__ out) {
    int i = blockIdx.x * blockDim.x + threadIdx.x;
    if (i < NPTS*DD) {
        int d = i & 63;
        float yv = (g_y[i] - g_mv[d]) * g_mv[64 + d] * gamma[d] + beta[d];
        out[i] = fmaxf(yv, 0.0f) + x[i];
    }
}

// ---------------- launch -----------------------------------------------------
extern "C" void kernel_launch(void* const* d_in, const int* in_sizes, int n_in,
                              void* d_out, int out_size) {
    const float* x     = (const float*)d_in[0];
    const float* pos   = (const float*)d_in[1];
    const float* w_qkv = (const float*)d_in[2];
    const float* b_qkv = (const float*)d_in[3];
    const float* w_p1  = (const float*)d_in[4];
    const float* b_p1  = (const float*)d_in[5];
    const float* w_p2  = (const float*)d_in[6];
    const float* b_p2  = (const float*)d_in[7];
    const float* w_a1  = (const float*)d_in[8];
    const float* b_a1  = (const float*)d_in[9];
    const float* w_a2  = (const float*)d_in[10];
    const float* b_a2  = (const float*)d_in[11];
    const float* w_fc  = (const float*)d_in[12];
    const float* b_fc  = (const float*)d_in[13];
    const float* gamma = (const float*)d_in[14];
    const float* beta  = (const float*)d_in[15];
    float* out = (float*)d_out;

    const int smem_qkv  = (64*192 + 64*64) * 4;
    const int smem_knn  = 3*NN*4 + KNN_WARPS*KNN_CAP*8;   // 64 KB
    const int smem_attn = (8192*4 + 2048*2 + 4608*4
                           + 512 + 32 + 384 + 512
                           + 64 + 64 + 256 + 64 + 64 + 192 + 128) * 4;  // 230272 B

    cudaFuncSetAttribute(qkv_kernel,  cudaFuncAttributeMaxDynamicSharedMemorySize, smem_qkv);
    cudaFuncSetAttribute(knn_kernel,  cudaFuncAttributeMaxDynamicSharedMemorySize, smem_knn);
    cudaFuncSetAttribute(attn_kernel, cudaFuncAttributeMaxDynamicSharedMemorySize, smem_attn);

    qkv_kernel<<<NPTS/64, 192, smem_qkv>>>(x, w_qkv, b_qkv);
    probe_kernel<<<1, 32>>>();
    probe_kernel2<<<1, 32>>>();
    knn_kernel<<<NPTS/KNN_WARPS, KNN_THREADS, smem_knn>>>(pos);
    attn_kernel<<<ATTN_GRID, 512, smem_attn>>>(pos, w_p1, b_p1, w_p2, b_p2,
                                               w_a1, b_a1, w_a2, b_a2, w_fc, b_fc);
    bnstats_kernel<<<1, 1024>>>();
    final_kernel<<<(NPTS*DD + 255)/256, 256>>>(x, gamma, beta, out);
}

// round 10
// speedup vs baseline: 2.9298x; 1.0298x over previous
#include <cuda_runtime.h>
#include <cuda_bf16.h>
#include <math.h>

#define BB 2
#define NN 4096
#define DD 64
#define HH 256
#define KK 16
#define NPTS (BB*NN)
#define ATTN_GRID 148
#define PTS 8               // points per iteration
#define ROWS 128            // PTS * KK rows
#define H2P 36              // packed bf16x2 row stride (u32)
#define SCP 65              // scores row stride

#define KNN_CAP 128
#define BIGD 3.0e38f

typedef unsigned long long u64;
typedef unsigned int u32;

// split two fp32 into packed bf16x2 hi and lo parts (x0 -> low half)
__device__ __forceinline__ void split2(float x0, float x1, u32& hi, u32& lo) {
    __nv_bfloat16 h0 = __float2bfloat16_rn(x0);
    __nv_bfloat16 h1 = __float2bfloat16_rn(x1);
    __nv_bfloat16 l0 = __float2bfloat16_rn(x0 - __bfloat162float(h0));
    __nv_bfloat16 l1 = __float2bfloat16_rn(x1 - __bfloat162float(h1));
    hi = (u32)*(unsigned short*)&h0 | ((u32)*(unsigned short*)&h1 << 16);
    lo = (u32)*(unsigned short*)&l0 | ((u32)*(unsigned short*)&l1 << 16);
}

__device__ __forceinline__ void mma16816(float* c, const u32* a, u32 b0, u32 b1) {
    asm volatile(
        "mma.sync.aligned.m16n8k16.row.col.f32.bf16.bf16.f32 "
        "{%0,%1,%2,%3}, {%4,%5,%6,%7}, {%8,%9}, {%0,%1,%2,%3};"
        : "+f"(c[0]), "+f"(c[1]), "+f"(c[2]), "+f"(c[3])
        : "r"(a[0]), "r"(a[1]), "r"(a[2]), "r"(a[3]), "r"(b0), "r"(b1));
}

// ---------------- scratch ----------------------------------------------------
__device__ float g_qkv[NPTS*192];      // q|k|v per point
__device__ int   g_idx[NPTS*KK];       // knn indices
__device__ float g_y[NPTS*DD];         // pre-BN output of fc
__device__ float g_part[ATTN_GRID*2*DD];
__device__ float g_mv[2*DD];           // mean, rstd
__device__ int   g_cellcnt[1024];      // zero-init at load; re-zeroed by scatter
__device__ int   g_cellstart[1025];
__device__ int   g_cellcur[1024];
__device__ float4 g_posb[NPTS];        // cell-sorted (x,y,z,idx)

// ---------------- binning kernels -------------------------------------------
__device__ __forceinline__ int cell_of(float x, float y, float z, int b) {
    int cx = min(7, max(0, (int)(x * 8.0f)));
    int cy = min(7, max(0, (int)(y * 8.0f)));
    int cz = min(7, max(0, (int)(z * 8.0f)));
    return b*512 + cz*64 + cy*8 + cx;
}

__global__ void bincount_kernel(const float* __restrict__ pos) {
    int i = blockIdx.x*blockDim.x + threadIdx.x;
    if (i < NPTS) {
        float x = pos[(size_t)i*3], y = pos[(size_t)i*3+1], z = pos[(size_t)i*3+2];
        atomicAdd(&g_cellcnt[cell_of(x, y, z, i >> 12)], 1);
    }
}

__global__ void binprefix_kernel() {
    __shared__ int sh[1024];
    int tid = threadIdx.x;
    int c = g_cellcnt[tid];
    sh[tid] = c;
    for (int off = 1; off < 1024; off <<= 1) {
        __syncthreads();
        int v = (tid >= off) ? sh[tid - off] : 0;
        __syncthreads();
        sh[tid] += v;
    }
    int excl = sh[tid] - c;
    g_cellstart[tid] = excl;
    g_cellcur[tid] = excl;
    if (tid == 1023) g_cellstart[1024] = sh[tid];
}

__global__ void binscatter_kernel(const float* __restrict__ pos) {
    int i = blockIdx.x*blockDim.x + threadIdx.x;
    if (i < 1024) g_cellcnt[i] = 0;          // reset for next launch/replay
    if (i < NPTS) {
        float x = pos[(size_t)i*3], y = pos[(size_t)i*3+1], z = pos[(size_t)i*3+2];
        int slot = atomicAdd(&g_cellcur[cell_of(x, y, z, i >> 12)], 1);
        g_posb[slot] = make_float4(x, y, z, __int_as_float(i & 4095));
    }
}

// ---------------- kernel 2: KNN (grid rings + threshold filter, exact) ------
__device__ __forceinline__ bool lexless(float d1, int i1, float d2, int i2) {
    return (d1 < d2) || (d1 == d2 && i1 < i2);
}

__device__ __forceinline__ void knn_flush(
    float& tD, int& tI, float& thrD, int& thrI, float& thr2,
    int& cnt, const float* bD, const int* bI, int lane)
{
    float e0 = (lane < 16) ? tD : BIGD;
    int   q0 = (lane < 16) ? tI : 0x7fffffff;
    float e1 = (lane      < cnt) ? bD[lane]      : BIGD;
    int   q1 = (lane      < cnt) ? bI[lane]      : 0x7fffffff;
    float e2 = (lane + 32 < cnt) ? bD[lane + 32] : BIGD;
    int   q2 = (lane + 32 < cnt) ? bI[lane + 32] : 0x7fffffff;
    float e3 = (lane + 64 < cnt) ? bD[lane + 64] : BIGD;
    int   q3 = (lane + 64 < cnt) ? bI[lane + 64] : 0x7fffffff;
    float e4 = (lane + 96 < cnt) ? bD[lane + 96] : BIGD;
    int   q4 = (lane + 96 < cnt) ? bI[lane + 96] : 0x7fffffff;

    float nD = BIGD; int nI = 0x7fffffff;
#pragma unroll
    for (int r = 0; r < 16; r++) {
        float md = e0; int mi = q0; int ms = 0;
        if (lexless(e1, q1, md, mi)) { md = e1; mi = q1; ms = 1; }
        if (lexless(e2, q2, md, mi)) { md = e2; mi = q2; ms = 2; }
        if (lexless(e3, q3, md, mi)) { md = e3; mi = q3; ms = 3; }
        if (lexless(e4, q4, md, mi)) { md = e4; mi = q4; ms = 4; }
        int src = (lane << 3) | ms;
#pragma unroll
        for (int off = 16; off; off >>= 1) {
            float od = __shfl_xor_sync(0xffffffffu, md, off);
            int   oi = __shfl_xor_sync(0xffffffffu, mi, off);
            int   os = __shfl_xor_sync(0xffffffffu, src, off);
            if (lexless(od, oi, md, mi)) { md = od; mi = oi; src = os; }
        }
        if (lane == (src >> 3)) {
            int sl = src & 7;
            if (sl == 0)      { e0 = BIGD; q0 = 0x7fffffff; }
            else if (sl == 1) { e1 = BIGD; q1 = 0x7fffffff; }
            else if (sl == 2) { e2 = BIGD; q2 = 0x7fffffff; }
            else if (sl == 3) { e3 = BIGD; q3 = 0x7fffffff; }
            else              { e4 = BIGD; q4 = 0x7fffffff; }
        }
        if (lane == r) { nD = md; nI = mi; }
    }
    tD = nD; tI = nI;
    thrD = __shfl_sync(0xffffffffu, nD, 15);
    thrI = __shfl_sync(0xffffffffu, nI, 15);
    thr2 = __fmul_rn(__fmul_rn(thrD, thrD), 1.0000005f);
    cnt = 0;
}

#define KNN_RUN(x0v, x1v) do {                                                  \
    int s_ = g_cellstart[cellbase + (x0v)];                                     \
    int e_ = g_cellstart[cellbase + (x1v) + 1];                                 \
    for (int i0 = s_; i0 < e_; i0 += 32) {                                      \
        int j = i0 + lane;                                                      \
        bool push = false; float dv = 0.0f; int ci = 0;                         \
        if (j < e_) {                                                           \
            float4 p = g_posb[j];                                               \
            float dx = px - p.x, dy = py - p.y, dz = pz - p.z;                  \
            float d2 = __fadd_rn(__fadd_rn(__fmul_rn(dx,dx), __fmul_rn(dy,dy)), \
                                 __fmul_rn(dz,dz));                             \
            if (d2 <= thr2) {                                                   \
                dv = sqrtf(d2);                                                 \
                ci = __float_as_int(p.w);                                       \
                push = lexless(dv, ci, thrD, thrI);                             \
            }                                                                   \
        }                                                                       \
        u32 mask = __ballot_sync(0xffffffffu, push);                            \
        if (push) {                                                             \
            int pp = cnt + __popc(mask & ((1u << lane) - 1u));                  \
            bD[pp] = dv; bI[pp] = ci;                                           \
        }                                                                       \
        cnt += __popc(mask);                                                    \
        if (cnt > KNN_CAP - 32)                                                 \
            knn_flush(tD, tI, thrD, thrI, thr2, cnt, bD, bI, lane);             \
    }                                                                           \
} while (0)

__global__ __launch_bounds__(256, 1)
void knn_kernel(const float* __restrict__ pos) {
    __shared__ float bufD[8*KNN_CAP];
    __shared__ int   bufI[8*KNN_CAP];
    int warp = threadIdx.x >> 5, lane = threadIdx.x & 31;
    int q = blockIdx.x * 8 + warp;             // global query id
    int bq = q >> 12;
    float px = pos[(size_t)q*3 + 0];
    float py = pos[(size_t)q*3 + 1];
    float pz = pos[(size_t)q*3 + 2];
    int cx = min(7, max(0, (int)(px * 8.0f)));
    int cy = min(7, max(0, (int)(py * 8.0f)));
    int cz = min(7, max(0, (int)(pz * 8.0f)));
    float* bD = bufD + warp*KNN_CAP;
    int*   bI = bufI + warp*KNN_CAP;

    float tD = BIGD; int tI = 0x7fff0000 + lane;
    float thrD = BIGD; int thrI = 0x7fffffff;
    float thr2 = __int_as_float(0x7f800000);
    int cnt = 0;
    int base = bq * 512;

    for (int R = 0; R < 8; R++) {
        int zlo = max(cz - R, 0), zhi = min(cz + R, 7);
        for (int z = zlo; z <= zhi; z++) {
            int adz = (z > cz) ? (z - cz) : (cz - z);
            int ylo = max(cy - R, 0), yhi = min(cy + R, 7);
            for (int y = ylo; y <= yhi; y++) {
                int ady = (y > cy) ? (y - cy) : (cy - y);
                int cellbase = base + z*64 + y*8;
                if (adz == R || ady == R) {
                    int x0 = max(cx - R, 0), x1 = min(cx + R, 7);
                    KNN_RUN(x0, x1);
                } else {
                    if (cx - R >= 0) KNN_RUN(cx - R, cx - R);
                    if (cx + R <= 7) KNN_RUN(cx + R, cx + R);
                }
            }
        }
        if (cnt) knn_flush(tD, tI, thrD, thrI, thr2, cnt, bD, bI, lane);
        // points outside ring R are strictly farther than R*h; margin for rounding
        if (thrD < (float)R * 0.125f * 0.999999f) break;
    }

    if (lane < 16) g_idx[q*KK + lane] = tI;
}

// ---------------- kernel 1: QKV GEMM  (8192x64 @ 64x192) -------------------
__global__ void qkv_kernel(const float* __restrict__ x,
                           const float* __restrict__ w,
                           const float* __restrict__ bq) {
    extern __shared__ float sm[];
    float* ws = sm;             // 64*192
    float* xs = sm + 64*192;    // 64*64
    int tid = threadIdx.x;      // 192 threads
    for (int i = tid; i < 64*192; i += 192) ws[i] = w[i];
    int row0 = blockIdx.x * 64;
    for (int i = tid; i < 64*64; i += 192) xs[i] = x[row0*64 + i];
    __syncthreads();
    float bb = bq[tid];
    for (int r0 = 0; r0 < 64; r0 += 8) {
        float acc[8];
#pragma unroll
        for (int r = 0; r < 8; r++) acc[r] = bb;
        for (int i = 0; i < 64; i++) {
            float wv = ws[i*192 + tid];
#pragma unroll
            for (int r = 0; r < 8; r++) acc[r] = fmaf(xs[(r0+r)*64 + i], wv, acc[r]);
        }
#pragma unroll
        for (int r = 0; r < 8; r++) g_qkv[(row0 + r0 + r)*192 + tid] = acc[r];
    }
}

// ---------------- kernel 3: fused attn (all GEMMs on tensor cores) ----------
__global__ __launch_bounds__(512, 1)
void attn_kernel(const float* __restrict__ pos,
                 const float* __restrict__ w_p1, const float* __restrict__ b_p1,
                 const float* __restrict__ w_p2, const float* __restrict__ b_p2,
                 const float* __restrict__ w_a1, const float* __restrict__ b_a1,
                 const float* __restrict__ w_a2, const float* __restrict__ b_a2,
                 const float* __restrict__ w_fc, const float* __restrict__ b_fc) {
    extern __shared__ float sm[];
    u32* w1hi  = (u32*)sm;                // 8192
    u32* w1lo  = w1hi + 8192;             // 8192
    u32* w2hi  = w1lo + 8192;             // 8192
    u32* w2lo  = w2hi + 8192;             // 8192
    u32* w2phi = w2lo + 8192;             // 2048  (w_p2 as MMA-B)
    u32* w2plo = w2phi + 2048;            // 2048
    u32* t1hi  = w2plo + 2048;            // 4608  [row x 36]  (alias: stage)
    u32* t1lo  = t1hi + 4608;             // 4608
    u32* h2hi  = t1lo + 4608;             // 4608  [row x 36]  (alias: scores)
    u32* h2lo  = h2hi + 4608;             // 4608
    float* qs    = (float*)(h2lo + 4608); // 512
    float* p0s   = qs + 512;              // 32
    float* rel   = p0s + 32;              // 384
    float* aggs  = rel + 384;             // 512
    float* b_p1s = aggs + 512;            // 64
    float* b_p2s = b_p1s + 64;            // 64
    float* b_a1s = b_p2s + 64;            // 256
    float* b_a2s = b_a1s + 256;           // 64
    float* b_fcs = b_a2s + 64;            // 64
    float* w_p1s = b_fcs + 64;            // 192
    int*   sidx  = (int*)(w_p1s + 192);   // 128
    float* stage  = (float*)t1hi;         // 8 x 1056 = 8448 f32 (<= 9216 u32)
    float* scores = (float*)h2hi;         // 128 x 65 = 8320 f32 (<= 9216 u32)

    int tid = threadIdx.x;
    int lane = tid & 31;
    int wid = tid >> 5;
    int g4 = lane >> 2, t4 = lane & 3;
    int mt = wid >> 1, hf = wid & 1;      // MLP-chain mapping
    int mtp = wid >> 1, nh = wid & 1;     // p2-MMA mapping (same split)

    // ---- weight prep: bf16 split + fragment swizzle (once) ----
    for (int i = tid; i < 8192; i += 512) {
        int kp = i >> 8, n = i & 255;
        u32 hi, lo;
        split2(w_a1[(2*kp)*256 + n], w_a1[(2*kp+1)*256 + n], hi, lo);
        int dst = kp*256 + (n ^ ((kp & 3) << 3));
        w1hi[dst] = hi; w1lo[dst] = lo;
    }
    for (int i = tid; i < 8192; i += 512) {
        int kp = i >> 6, n = i & 63;
        u32 hi, lo;
        split2(w_a2[(2*kp)*64 + n], w_a2[(2*kp+1)*64 + n], hi, lo);
        int dst = kp*64 + (n ^ ((kp & 3) << 3));
        w2hi[dst] = hi; w2lo[dst] = lo;
    }
    for (int i = tid; i < 2048; i += 512) {
        int kp = i >> 6, n = i & 63;
        u32 hi, lo;
        split2(w_p2[(2*kp)*64 + n], w_p2[(2*kp+1)*64 + n], hi, lo);
        int dst = kp*64 + (n ^ ((kp & 3) << 3));
        w2phi[dst] = hi; w2plo[dst] = lo;
    }
    if (tid < 192) w_p1s[tid] = w_p1[tid];
    if (tid < 256) b_a1s[tid] = b_a1[tid];
    if (tid < 64) {
        b_p1s[tid] = b_p1[tid]; b_p2s[tid] = b_p2[tid];
        b_a2s[tid] = b_a2[tid]; b_fcs[tid] = b_fc[tid];
    }
    float accY = 0.0f, accY2 = 0.0f;
    __syncthreads();

    for (int g = blockIdx.x; g < NPTS/PTS; g += ATTN_GRID) {
        int pbase = g * PTS;
        int bofs = (pbase >> 12) << 12;

        // ---- A: per-point loads
        if (tid < 128) sidx[tid] = g_idx[pbase*KK + tid];
        {
            int l = tid >> 6, d = tid & 63;
            qs[tid] = g_qkv[(size_t)(pbase + l)*192 + d];
        }
        if (tid < 24) {
            int l = tid / 3, c = tid - l*3;
            p0s[l*4 + c] = pos[(size_t)(pbase + l)*3 + c];
        }
        __syncthreads();

        // ---- B: rel
        if (tid < 384) {
            int r = tid / 3, c = tid - r*3;
            int l = r >> 4;
            rel[tid] = p0s[l*4 + c] - pos[(size_t)(bofs + sidx[r])*3 + c];
        }
        __syncthreads();

        // ---- C: pos-MLP -> t1 (bf16 split tiles)
#pragma unroll
        for (int e = 0; e < 8; e++) {
            int i = tid + e*512;              // 4096 pairs
            int r = i >> 5, kp = i & 31;
            int pp = kp*2;
            float r0v = rel[r*3+0], r1v = rel[r*3+1], r2v = rel[r*3+2];
            float a0 = b_p1s[pp];
            a0 = fmaf(r0v, w_p1s[pp],        a0);
            a0 = fmaf(r1v, w_p1s[64 + pp],   a0);
            a0 = fmaf(r2v, w_p1s[128 + pp],  a0);
            float a1 = b_p1s[pp+1];
            a1 = fmaf(r0v, w_p1s[pp+1],      a1);
            a1 = fmaf(r1v, w_p1s[64 + pp+1], a1);
            a1 = fmaf(r2v, w_p1s[128 + pp+1],a1);
            a0 = fmaxf(a0, 0.0f); a1 = fmaxf(a1, 0.0f);
            u32 hi, lo;
            split2(a0, a1, hi, lo);
            t1hi[r*H2P + kp] = hi;
            t1lo[r*H2P + kp] = lo;
        }
        __syncthreads();

        // ---- D: p2 on MMA + qk gather in C-frag positions -> h2
        {
            u32 pahi[16], palo[16];
            int rowA = mtp*16 + g4;
#pragma unroll
            for (int ks = 0; ks < 4; ks++) {
                int c = ks*8 + t4;
                pahi[ks*4+0] = t1hi[rowA*H2P + c];
                pahi[ks*4+1] = t1hi[(rowA+8)*H2P + c];
                pahi[ks*4+2] = t1hi[rowA*H2P + c + 4];
                pahi[ks*4+3] = t1hi[(rowA+8)*H2P + c + 4];
                palo[ks*4+0] = t1lo[rowA*H2P + c];
                palo[ks*4+1] = t1lo[(rowA+8)*H2P + c];
                palo[ks*4+2] = t1lo[rowA*H2P + c + 4];
                palo[ks*4+3] = t1lo[(rowA+8)*H2P + c + 4];
            }
            float cP[16];
#pragma unroll
            for (int z = 0; z < 16; z++) cP[z] = 0.0f;
#pragma unroll
            for (int ntl = 0; ntl < 4; ntl++) {
                int nsw = (nh*32 + ntl*8 + g4) ^ (t4 << 3);
#pragma unroll
                for (int ks = 0; ks < 4; ks++) {
                    int kp0 = ks*8 + t4;
                    u32 bh0 = w2phi[kp0*64 + nsw];
                    u32 bh1 = w2phi[(kp0+4)*64 + nsw];
                    u32 bl0 = w2plo[kp0*64 + nsw];
                    u32 bl1 = w2plo[(kp0+4)*64 + nsw];
                    mma16816(&cP[ntl*4], &pahi[ks*4], bh0, bh1);
                    mma16816(&cP[ntl*4], &pahi[ks*4], bl0, bl1);
                    mma16816(&cP[ntl*4], &palo[ks*4], bh0, bh1);
                }
            }
            int r1 = mtp*16 + g4, r2 = r1 + 8;
            const float* krow1 = g_qkv + (size_t)(bofs + sidx[r1])*192 + 64;
            const float* krow2 = g_qkv + (size_t)(bofs + sidx[r2])*192 + 64;
#pragma unroll
            for (int ntl = 0; ntl < 4; ntl++) {
                int cb = nh*32 + ntl*8 + t4*2;
                float2 k1 = *(const float2*)&krow1[cb];
                float2 k2 = *(const float2*)&krow2[cb];
                float2 q1 = *(const float2*)&qs[mtp*64 + cb];
                float bb0 = b_p2s[cb], bb1 = b_p2s[cb+1];
                float h10 = (q1.x - k1.x) + cP[ntl*4+0] + bb0;
                float h11 = (q1.y - k1.y) + cP[ntl*4+1] + bb1;
                float h20 = (q1.x - k2.x) + cP[ntl*4+2] + bb0;
                float h21 = (q1.y - k2.y) + cP[ntl*4+3] + bb1;
                int kp = cb >> 1;
                u32 hi, lo;
                split2(h10, h11, hi, lo);
                h2hi[r1*H2P + kp] = hi; h2lo[r1*H2P + kp] = lo;
                split2(h20, h21, hi, lo);
                h2hi[r2*H2P + kp] = hi; h2lo[r2*H2P + kp] = lo;
            }
        }
        __syncthreads();

        // ---- E: load A1 fragments (h2) for this warp's m-tile
        u32 ahi[16], alo[16];
        {
            int rowA = mt*16 + g4;
#pragma unroll
            for (int ks = 0; ks < 4; ks++) {
                int c = ks*8 + t4;
                ahi[ks*4+0] = h2hi[rowA*H2P + c];
                ahi[ks*4+1] = h2hi[(rowA+8)*H2P + c];
                ahi[ks*4+2] = h2hi[rowA*H2P + c + 4];
                ahi[ks*4+3] = h2hi[(rowA+8)*H2P + c + 4];
                alo[ks*4+0] = h2lo[rowA*H2P + c];
                alo[ks*4+1] = h2lo[(rowA+8)*H2P + c];
                alo[ks*4+2] = h2lo[rowA*H2P + c + 4];
                alo[ks*4+3] = h2lo[(rowA+8)*H2P + c + 4];
            }
        }

        // ---- F: chunked attn MLP on tensor cores (sync-free)
        float C2[32];
#pragma unroll
        for (int z = 0; z < 32; z++) C2[z] = 0.0f;

#pragma unroll
        for (int jc = 0; jc < 4; jc++) {
            u32 s2hi[8], s2lo[8];
#pragma unroll
            for (int u = 0; u < 2; u++) {
                float cA[4] = {0,0,0,0}, cB[4] = {0,0,0,0};
                int nbase = jc*64 + hf*32 + u*16;
                int nswA = (nbase + g4) ^ (t4 << 3);
                int nswB = (nbase + 8 + g4) ^ (t4 << 3);
#pragma unroll
                for (int ks = 0; ks < 4; ks++) {
                    int kp0 = ks*8 + t4;
                    u32 bh0 = w1hi[kp0*256 + nswA];
                    u32 bh1 = w1hi[(kp0+4)*256 + nswA];
                    u32 bl0 = w1lo[kp0*256 + nswA];
                    u32 bl1 = w1lo[(kp0+4)*256 + nswA];
                    mma16816(cA, &ahi[ks*4], bh0, bh1);
                    mma16816(cA, &ahi[ks*4], bl0, bl1);
                    mma16816(cA, &alo[ks*4], bh0, bh1);
                    u32 ch0 = w1hi[kp0*256 + nswB];
                    u32 ch1 = w1hi[(kp0+4)*256 + nswB];
                    u32 cl0 = w1lo[kp0*256 + nswB];
                    u32 cl1 = w1lo[(kp0+4)*256 + nswB];
                    mma16816(cB, &ahi[ks*4], ch0, ch1);
                    mma16816(cB, &ahi[ks*4], cl0, cl1);
                    mma16816(cB, &alo[ks*4], ch0, ch1);
                }
                int cb = nbase + t4*2;
                float bA0 = b_a1s[cb],   bA1 = b_a1s[cb+1];
                float bB0 = b_a1s[cb+8], bB1 = b_a1s[cb+9];
                float sA0 = fmaxf(cA[0] + bA0, 0.0f);
                float sA1 = fmaxf(cA[1] + bA1, 0.0f);
                float sA2 = fmaxf(cA[2] + bA0, 0.0f);
                float sA3 = fmaxf(cA[3] + bA1, 0.0f);
                float sB0 = fmaxf(cB[0] + bB0, 0.0f);
                float sB1 = fmaxf(cB[1] + bB1, 0.0f);
                float sB2 = fmaxf(cB[2] + bB0, 0.0f);
                float sB3 = fmaxf(cB[3] + bB1, 0.0f);
                split2(sA0, sA1, s2hi[u*4+0], s2lo[u*4+0]);
                split2(sA2, sA3, s2hi[u*4+1], s2lo[u*4+1]);
                split2(sB0, sB1, s2hi[u*4+2], s2lo[u*4+2]);
                split2(sB2, sB3, s2hi[u*4+3], s2lo[u*4+3]);
            }
#pragma unroll
            for (int nt = 0; nt < 8; nt++) {
#pragma unroll
                for (int u = 0; u < 2; u++) {
                    int kp = jc*32 + hf*16 + u*8 + t4;
                    int nsw = (nt*8 + g4) ^ (t4 << 3);
                    u32 bh0 = w2hi[kp*64 + nsw];
                    u32 bh1 = w2hi[(kp+4)*64 + nsw];
                    u32 bl0 = w2lo[kp*64 + nsw];
                    u32 bl1 = w2lo[(kp+4)*64 + nsw];
                    mma16816(&C2[nt*4], &s2hi[u*4], bh0, bh1);
                    mma16816(&C2[nt*4], &s2hi[u*4], bl0, bl1);
                    mma16816(&C2[nt*4], &s2lo[u*4], bh0, bh1);
                }
            }
        }

        // ---- cross-half reduction of scores (stage in t1 region)
        if (hf) {
            float* sp = stage + mt*1056 + lane*33;
#pragma unroll
            for (int z = 0; z < 32; z++) sp[z] = C2[z];
        }
        __syncthreads();
        if (!hf) {
            float* sp = stage + mt*1056 + lane*33;
#pragma unroll
            for (int nt = 0; nt < 8; nt++) {
                int cb = nt*8 + t4*2;
                float v0 = C2[nt*4+0] + sp[nt*4+0] + b_a2s[cb];
                float v1 = C2[nt*4+1] + sp[nt*4+1] + b_a2s[cb+1];
                float v2 = C2[nt*4+2] + sp[nt*4+2] + b_a2s[cb];
                float v3 = C2[nt*4+3] + sp[nt*4+3] + b_a2s[cb+1];
                scores[(mt*16 + g4)*SCP + cb]         = v0;
                scores[(mt*16 + g4)*SCP + cb + 1]     = v1;
                scores[(mt*16 + g4 + 8)*SCP + cb]     = v2;
                scores[(mt*16 + g4 + 8)*SCP + cb + 1] = v3;
            }
        }
        __syncthreads();

        // ---- G: softmax over K + weighted v-sum (v from L2)
        {
            int l = tid >> 6, d = tid & 63;
            float vreg[16];
#pragma unroll
            for (int k = 0; k < 16; k++)
                vreg[k] = g_qkv[(size_t)(bofs + sidx[l*16 + k])*192 + 128 + d];
            float mx = -3.0e38f;
#pragma unroll
            for (int k = 0; k < 16; k++)
                mx = fmaxf(mx, scores[(l*16 + k)*SCP + d]);
            float ssum = 0.0f, a = 0.0f;
#pragma unroll
            for (int k = 0; k < 16; k++) {
                float e = __expf(scores[(l*16 + k)*SCP + d] - mx);
                ssum += e;
                a = fmaf(e, vreg[k], a);
            }
            aggs[tid] = a / ssum;
        }
        __syncthreads();

        // ---- H: fc (w_fc via L1/L2) + BN partials
        {
            int l = tid >> 6, d = tid & 63;
            float y = b_fcs[d];
#pragma unroll 8
            for (int c = 0; c < 64; c++)
                y = fmaf(aggs[l*64 + c], w_fc[c*64 + d], y);
            g_y[(size_t)(pbase + l)*64 + d] = y;
            accY += y;
            accY2 = fmaf(y, y, accY2);
        }
        __syncthreads();
    }

    // ---- reduce BN partials (t1 region as scratch)
    float* red = (float*)t1hi;
    red[tid] = accY;
    __syncthreads();
    if (tid < 64) {
        float s = 0.0f;
#pragma unroll
        for (int q = 0; q < 8; q++) s += red[q*64 + tid];
        g_part[blockIdx.x*128 + tid] = s;
    }
    __syncthreads();
    red[tid] = accY2;
    __syncthreads();
    if (tid < 64) {
        float s = 0.0f;
#pragma unroll
        for (int q = 0; q < 8; q++) s += red[q*64 + tid];
        g_part[blockIdx.x*128 + 64 + tid] = s;
    }
}

// ---------------- kernel 4: finish BN statistics ----------------------------
__global__ void bnstats_kernel() {
    __shared__ float sred[2048];
    int tid = threadIdx.x;            // 1024
    int d = tid & 63, q = tid >> 6;   // 16 groups
    float s = 0.0f, s2 = 0.0f;
    for (int blk = q; blk < ATTN_GRID; blk += 16) {
        s  += g_part[blk*128 + d];
        s2 += g_part[blk*128 + 64 + d];
    }
    sred[tid] = s; sred[1024 + tid] = s2;
    __syncthreads();
    if (tid < 64) {
        float ts = 0.0f, ts2 = 0.0f;
#pragma unroll
        for (int k = 0; k < 16; k++) {
            ts  += sred[k*64 + d];
            ts2 += sred[1024 + k*64 + d];
        }
        float mean = ts / (float)NPTS;
        float var  = ts2 / (float)NPTS - mean*mean;
        g_mv[d]      = mean;
        g_mv[64 + d] = rsqrtf(var + 1e-5f);
    }
}

// ---------------- kernel 5: BN apply + relu + residual ----------------------
__global__ void final_kernel(const float* __restrict__ x,
                             const float* __restrict__ gamma,
                             const float* __restrict__ beta,
                             float* __restrict__ out) {
    int i = blockIdx.x * blockDim.x + threadIdx.x;
    if (i < NPTS*DD) {
        int d = i & 63;
        float yv = (g_y[i] - g_mv[d]) * g_mv[64 + d] * gamma[d] + beta[d];
        out[i] = fmaxf(yv, 0.0f) + x[i];
    }
}

// ---------------- launch -----------------------------------------------------
extern "C" void kernel_launch(void* const* d_in, const int* in_sizes, int n_in,
                              void* d_out, int out_size) {
    const float* x     = (const float*)d_in[0];
    const float* pos   = (const float*)d_in[1];
    const float* w_qkv = (const float*)d_in[2];
    const float* b_qkv = (const float*)d_in[3];
    const float* w_p1  = (const float*)d_in[4];
    const float* b_p1  = (const float*)d_in[5];
    const float* w_p2  = (const float*)d_in[6];
    const float* b_p2  = (const float*)d_in[7];
    const float* w_a1  = (const float*)d_in[8];
    const float* b_a1  = (const float*)d_in[9];
    const float* w_a2  = (const float*)d_in[10];
    const float* b_a2  = (const float*)d_in[11];
    const float* w_fc  = (const float*)d_in[12];
    const float* b_fc  = (const float*)d_in[13];
    const float* gamma = (const float*)d_in[14];
    const float* beta  = (const float*)d_in[15];
    float* out = (float*)d_out;

    const int smem_qkv  = (64*192 + 64*64) * 4;
    const int smem_attn = (8192*4 + 2048*2 + 4608*4
                           + 512 + 32 + 384 + 512
                           + 64 + 64 + 256 + 64 + 64 + 192 + 128) * 4;  // 230272 B

    cudaFuncSetAttribute(qkv_kernel,  cudaFuncAttributeMaxDynamicSharedMemorySize, smem_qkv);
    cudaFuncSetAttribute(attn_kernel, cudaFuncAttributeMaxDynamicSharedMemorySize, smem_attn);

    bincount_kernel<<<NPTS/256, 256>>>(pos);            // 0
    binprefix_kernel<<<1, 1024>>>();                    // 1
    binscatter_kernel<<<NPTS/256, 256>>>(pos);          // 2
    knn_kernel<<<NPTS/8, 256>>>(pos);                   // 3 <- ncu capture slot
    qkv_kernel<<<NPTS/64, 192, smem_qkv>>>(x, w_qkv, b_qkv);
    attn_kernel<<<ATTN_GRID, 512, smem_attn>>>(pos, w_p1, b_p1, w_p2, b_p2,
                                               w_a1, b_a1, w_a2, b_a2, w_fc, b_fc);
    bnstats_kernel<<<1, 1024>>>();
    final_kernel<<<(NPTS*DD + 255)/256, 256>>>(x, gamma, beta, out);
}

// round 13
// speedup vs baseline: 3.7011x; 1.2632x over previous
#include <cuda_runtime.h>
#include <cuda_bf16.h>
#include <math.h>

#define BB 2
#define NN 4096
#define DD 64
#define HH 256
#define KK 16
#define NPTS (BB*NN)
#define ATTN_GRID 148
#define PTS 8               // points per iteration
#define ROWS 128            // PTS * KK rows
#define H2P 36              // packed bf16x2 row stride (u32)
#define SCP 65              // scores row stride

#define KNN_CAP 128
#define BIGD 3.0e38f

typedef unsigned long long u64;
typedef unsigned int u32;

// split two fp32 into packed bf16x2 hi and lo parts (x0 -> low half)
__device__ __forceinline__ void split2(float x0, float x1, u32& hi, u32& lo) {
    __nv_bfloat16 h0 = __float2bfloat16_rn(x0);
    __nv_bfloat16 h1 = __float2bfloat16_rn(x1);
    __nv_bfloat16 l0 = __float2bfloat16_rn(x0 - __bfloat162float(h0));
    __nv_bfloat16 l1 = __float2bfloat16_rn(x1 - __bfloat162float(h1));
    hi = (u32)*(unsigned short*)&h0 | ((u32)*(unsigned short*)&h1 << 16);
    lo = (u32)*(unsigned short*)&l0 | ((u32)*(unsigned short*)&l1 << 16);
}

__device__ __forceinline__ void mma16816(float* c, const u32* a, u32 b0, u32 b1) {
    asm volatile(
        "mma.sync.aligned.m16n8k16.row.col.f32.bf16.bf16.f32 "
        "{%0,%1,%2,%3}, {%4,%5,%6,%7}, {%8,%9}, {%0,%1,%2,%3};"
        : "+f"(c[0]), "+f"(c[1]), "+f"(c[2]), "+f"(c[3])
        : "r"(a[0]), "r"(a[1]), "r"(a[2]), "r"(a[3]), "r"(b0), "r"(b1));
}

// ---------------- scratch ----------------------------------------------------
__device__ float g_qkv[NPTS*192];      // q|k|v per point
__device__ int   g_idx[NPTS*KK];       // knn indices
__device__ float g_y[NPTS*DD];         // pre-BN output of fc
__device__ float g_part[ATTN_GRID*2*DD];
__device__ float g_mv[2*DD];           // mean, rstd
__device__ int   g_cellcnt[1024];      // zero-init at load; re-zeroed by scatter
__device__ int   g_cellstart[1025];
__device__ int   g_cellcur[1024];
__device__ float4 g_posb[NPTS];        // cell-sorted (x,y,z,idx)

// ---------------- binning kernels -------------------------------------------
__device__ __forceinline__ int cell_of(float x, float y, float z, int b) {
    int cx = min(7, max(0, (int)(x * 8.0f)));
    int cy = min(7, max(0, (int)(y * 8.0f)));
    int cz = min(7, max(0, (int)(z * 8.0f)));
    return b*512 + cz*64 + cy*8 + cx;
}

__global__ void bincount_kernel(const float* __restrict__ pos) {
    int i = blockIdx.x*blockDim.x + threadIdx.x;
    if (i < NPTS) {
        float x = pos[(size_t)i*3], y = pos[(size_t)i*3+1], z = pos[(size_t)i*3+2];
        atomicAdd(&g_cellcnt[cell_of(x, y, z, i >> 12)], 1);
    }
}

__global__ void binprefix_kernel() {
    __shared__ int sh[1024];
    int tid = threadIdx.x;
    int c = g_cellcnt[tid];
    sh[tid] = c;
    for (int off = 1; off < 1024; off <<= 1) {
        __syncthreads();
        int v = (tid >= off) ? sh[tid - off] : 0;
        __syncthreads();
        sh[tid] += v;
    }
    int excl = sh[tid] - c;
    g_cellstart[tid] = excl;
    g_cellcur[tid] = excl;
    if (tid == 1023) g_cellstart[1024] = sh[tid];
}

__global__ void binscatter_kernel(const float* __restrict__ pos) {
    int i = blockIdx.x*blockDim.x + threadIdx.x;
    if (i < 1024) g_cellcnt[i] = 0;          // reset for next launch/replay
    if (i < NPTS) {
        float x = pos[(size_t)i*3], y = pos[(size_t)i*3+1], z = pos[(size_t)i*3+2];
        int slot = atomicAdd(&g_cellcur[cell_of(x, y, z, i >> 12)], 1);
        g_posb[slot] = make_float4(x, y, z, __int_as_float(i & 4095));
    }
}

// ---------------- kernel 2: KNN (grid rings + threshold filter, exact) ------
// R10-proven flush/buffer; new: smem cellstart cache + fused rings 0+1.
__device__ __forceinline__ bool lexless(float d1, int i1, float d2, int i2) {
    return (d1 < d2) || (d1 == d2 && i1 < i2);
}

__device__ __forceinline__ void knn_flush(
    float& tD, int& tI, float& thrD, int& thrI, float& thr2,
    int& cnt, const float* bD, const int* bI, int lane)
{
    float e0 = (lane < 16) ? tD : BIGD;
    int   q0 = (lane < 16) ? tI : 0x7fffffff;
    float e1 = (lane      < cnt) ? bD[lane]      : BIGD;
    int   q1 = (lane      < cnt) ? bI[lane]      : 0x7fffffff;
    float e2 = (lane + 32 < cnt) ? bD[lane + 32] : BIGD;
    int   q2 = (lane + 32 < cnt) ? bI[lane + 32] : 0x7fffffff;
    float e3 = (lane + 64 < cnt) ? bD[lane + 64] : BIGD;
    int   q3 = (lane + 64 < cnt) ? bI[lane + 64] : 0x7fffffff;
    float e4 = (lane + 96 < cnt) ? bD[lane + 96] : BIGD;
    int   q4 = (lane + 96 < cnt) ? bI[lane + 96] : 0x7fffffff;

    float nD = BIGD; int nI = 0x7fffffff;
#pragma unroll
    for (int r = 0; r < 16; r++) {
        float md = e0; int mi = q0; int ms = 0;
        if (lexless(e1, q1, md, mi)) { md = e1; mi = q1; ms = 1; }
        if (lexless(e2, q2, md, mi)) { md = e2; mi = q2; ms = 2; }
        if (lexless(e3, q3, md, mi)) { md = e3; mi = q3; ms = 3; }
        if (lexless(e4, q4, md, mi)) { md = e4; mi = q4; ms = 4; }
        int src = (lane << 3) | ms;
#pragma unroll
        for (int off = 16; off; off >>= 1) {
            float od = __shfl_xor_sync(0xffffffffu, md, off);
            int   oi = __shfl_xor_sync(0xffffffffu, mi, off);
            int   os = __shfl_xor_sync(0xffffffffu, src, off);
            if (lexless(od, oi, md, mi)) { md = od; mi = oi; src = os; }
        }
        if (lane == (src >> 3)) {
            int sl = src & 7;
            if (sl == 0)      { e0 = BIGD; q0 = 0x7fffffff; }
            else if (sl == 1) { e1 = BIGD; q1 = 0x7fffffff; }
            else if (sl == 2) { e2 = BIGD; q2 = 0x7fffffff; }
            else if (sl == 3) { e3 = BIGD; q3 = 0x7fffffff; }
            else              { e4 = BIGD; q4 = 0x7fffffff; }
        }
        if (lane == r) { nD = md; nI = mi; }
    }
    tD = nD; tI = nI;
    thrD = __shfl_sync(0xffffffffu, nD, 15);
    thrI = __shfl_sync(0xffffffffu, nI, 15);
    thr2 = __fmul_rn(__fmul_rn(thrD, thrD), 1.0000005f);
    cnt = 0;
}

#define KNN_RUN(rowbase, x0v, x1v) do {                                         \
    int s_ = cstart[(rowbase) + (x0v)];                                         \
    int e_ = cstart[(rowbase) + (x1v) + 1];                                     \
    for (int i0 = s_; i0 < e_; i0 += 32) {                                      \
        int j = i0 + lane;                                                      \
        bool push = false; float dv = 0.0f; int ci = 0;                         \
        if (j < e_) {                                                           \
            float4 p = g_posb[j];                                               \
            float dx = px - p.x, dy = py - p.y, dz = pz - p.z;                  \
            float d2 = __fadd_rn(__fadd_rn(__fmul_rn(dx,dx), __fmul_rn(dy,dy)), \
                                 __fmul_rn(dz,dz));                             \
            if (d2 <= thr2) {                                                   \
                dv = sqrtf(d2);                                                 \
                ci = __float_as_int(p.w);                                       \
                push = lexless(dv, ci, thrD, thrI);                             \
            }                                                                   \
        }                                                                       \
        u32 mask = __ballot_sync(0xffffffffu, push);                            \
        if (push) {                                                             \
            int pp = cnt + __popc(mask & ((1u << lane) - 1u));                  \
            bD[pp] = dv; bI[pp] = ci;                                           \
        }                                                                       \
        cnt += __popc(mask);                                                    \
        if (cnt > KNN_CAP - 32)                                                 \
            knn_flush(tD, tI, thrD, thrI, thr2, cnt, bD, bI, lane);             \
    }                                                                           \
} while (0)

__global__ __launch_bounds__(256, 1)
void knn_kernel(const float* __restrict__ pos) {
    __shared__ int cstart[513];
    __shared__ float bufD[8*KNN_CAP];
    __shared__ int   bufI[8*KNN_CAP];
    int tid = threadIdx.x;
    int warp = tid >> 5, lane = tid & 31;
    int q = blockIdx.x * 8 + warp;             // global query id (block = one batch)
    int bq = q >> 12;
    for (int i = tid; i < 513; i += 256) cstart[i] = g_cellstart[bq*512 + i];
    __syncthreads();

    float px = pos[(size_t)q*3 + 0];
    float py = pos[(size_t)q*3 + 1];
    float pz = pos[(size_t)q*3 + 2];
    int cx = min(7, max(0, (int)(px * 8.0f)));
    int cy = min(7, max(0, (int)(py * 8.0f)));
    int cz = min(7, max(0, (int)(pz * 8.0f)));
    float* bD = bufD + warp*KNN_CAP;
    int*   bI = bufI + warp*KNN_CAP;

    float tD = BIGD; int tI = 0x7fff0000 + lane;
    float thrD = BIGD; int thrI = 0x7fffffff;
    float thr2 = __int_as_float(0x7f800000);
    int cnt = 0;

    // ---- phase 1: fused rings 0+1 = 3x3x3 block, uniform full-x rows
    {
        int zlo = max(cz-1, 0), zhi = min(cz+1, 7);
        int ylo = max(cy-1, 0), yhi = min(cy+1, 7);
        int x0 = max(cx-1, 0), x1 = min(cx+1, 7);
        for (int z = zlo; z <= zhi; z++)
            for (int y = ylo; y <= yhi; y++)
                KNN_RUN(z*64 + y*8, x0, x1);
        if (cnt) knn_flush(tD, tI, thrD, thrI, thr2, cnt, bD, bI, lane);
    }

    // ---- phase 2: rings R>=2 until certified
    if (!(thrD < 0.125f * 0.999999f)) {
        for (int R = 2; R < 8; R++) {
            int zlo = max(cz - R, 0), zhi = min(cz + R, 7);
            for (int z = zlo; z <= zhi; z++) {
                int adz = (z > cz) ? (z - cz) : (cz - z);
                int ylo = max(cy - R, 0), yhi = min(cy + R, 7);
                for (int y = ylo; y <= yhi; y++) {
                    int ady = (y > cy) ? (y - cy) : (cy - y);
                    int rowbase = z*64 + y*8;
                    if (adz == R || ady == R) {
                        int x0 = max(cx - R, 0), x1 = min(cx + R, 7);
                        KNN_RUN(rowbase, x0, x1);
                    } else {
                        if (cx - R >= 0) KNN_RUN(rowbase, cx - R, cx - R);
                        if (cx + R <= 7) KNN_RUN(rowbase, cx + R, cx + R);
                    }
                }
            }
            if (cnt) knn_flush(tD, tI, thrD, thrI, thr2, cnt, bD, bI, lane);
            if (thrD < (float)R * 0.125f * 0.999999f) break;
        }
    }

    if (lane < 16) g_idx[q*KK + lane] = tI;
}

// ---------------- kernel 1: QKV GEMM  (8192x64 @ 64x192) -------------------
__global__ void qkv_kernel(const float* __restrict__ x,
                           const float* __restrict__ w,
                           const float* __restrict__ bq) {
    extern __shared__ float sm[];
    float* ws = sm;             // 64*192
    float* xs = sm + 64*192;    // 64*64
    int tid = threadIdx.x;      // 192 threads
    for (int i = tid; i < 64*192; i += 192) ws[i] = w[i];
    int row0 = blockIdx.x * 64;
    for (int i = tid; i < 64*64; i += 192) xs[i] = x[row0*64 + i];
    __syncthreads();
    float bb = bq[tid];
    for (int r0 = 0; r0 < 64; r0 += 8) {
        float acc[8];
#pragma unroll
        for (int r = 0; r < 8; r++) acc[r] = bb;
        for (int i = 0; i < 64; i++) {
            float wv = ws[i*192 + tid];
#pragma unroll
            for (int r = 0; r < 8; r++) acc[r] = fmaf(xs[(r0+r)*64 + i], wv, acc[r]);
        }
#pragma unroll
        for (int r = 0; r < 8; r++) g_qkv[(row0 + r0 + r)*192 + tid] = acc[r];
    }
}

// ---------------- kernel 3: fused attn (all GEMMs on tensor cores) ----------
__global__ __launch_bounds__(512, 1)
void attn_kernel(const float* __restrict__ pos,
                 const float* __restrict__ w_p1, const float* __restrict__ b_p1,
                 const float* __restrict__ w_p2, const float* __restrict__ b_p2,
                 const float* __restrict__ w_a1, const float* __restrict__ b_a1,
                 const float* __restrict__ w_a2, const float* __restrict__ b_a2,
                 const float* __restrict__ w_fc, const float* __restrict__ b_fc) {
    extern __shared__ float sm[];
    u32* w1hi  = (u32*)sm;                // 8192
    u32* w1lo  = w1hi + 8192;             // 8192
    u32* w2hi  = w1lo + 8192;             // 8192
    u32* w2lo  = w2hi + 8192;             // 8192
    u32* w2phi = w2lo + 8192;             // 2048  (w_p2 as MMA-B)
    u32* w2plo = w2phi + 2048;            // 2048
    u32* t1hi  = w2plo + 2048;            // 4608  [row x 36]  (alias: stage)
    u32* t1lo  = t1hi + 4608;             // 4608
    u32* h2hi  = t1lo + 4608;             // 4608  [row x 36]  (alias: scores)
    u32* h2lo  = h2hi + 4608;             // 4608
    float* qs    = (float*)(h2lo + 4608); // 512
    float* p0s   = qs + 512;              // 32
    float* rel   = p0s + 32;              // 384
    float* aggs  = rel + 384;             // 512
    float* b_p1s = aggs + 512;            // 64
    float* b_p2s = b_p1s + 64;            // 64
    float* b_a1s = b_p2s + 64;            // 256
    float* b_a2s = b_a1s + 256;           // 64
    float* b_fcs = b_a2s + 64;            // 64
    float* w_p1s = b_fcs + 64;            // 192
    int*   sidx  = (int*)(w_p1s + 192);   // 128
    float* stage  = (float*)t1hi;         // 8 x 1056 = 8448 f32 (<= 9216 u32)
    float* scores = (float*)h2hi;         // 128 x 65 = 8320 f32 (<= 9216 u32)

    int tid = threadIdx.x;
    int lane = tid & 31;
    int wid = tid >> 5;
    int g4 = lane >> 2, t4 = lane & 3;
    int mt = wid >> 1, hf = wid & 1;      // MLP-chain mapping
    int mtp = wid >> 1, nh = wid & 1;     // p2-MMA mapping (same split)

    // ---- weight prep: bf16 split + fragment swizzle (once) ----
    for (int i = tid; i < 8192; i += 512) {
        int kp = i >> 8, n = i & 255;
        u32 hi, lo;
        split2(w_a1[(2*kp)*256 + n], w_a1[(2*kp+1)*256 + n], hi, lo);
        int dst = kp*256 + (n ^ ((kp & 3) << 3));
        w1hi[dst] = hi; w1lo[dst] = lo;
    }
    for (int i = tid; i < 8192; i += 512) {
        int kp = i >> 6, n = i & 63;
        u32 hi, lo;
        split2(w_a2[(2*kp)*64 + n], w_a2[(2*kp+1)*64 + n], hi, lo);
        int dst = kp*64 + (n ^ ((kp & 3) << 3));
        w2hi[dst] = hi; w2lo[dst] = lo;
    }
    for (int i = tid; i < 2048; i += 512) {
        int kp = i >> 6, n = i & 63;
        u32 hi, lo;
        split2(w_p2[(2*kp)*64 + n], w_p2[(2*kp+1)*64 + n], hi, lo);
        int dst = kp*64 + (n ^ ((kp & 3) << 3));
        w2phi[dst] = hi; w2plo[dst] = lo;
    }
    if (tid < 192) w_p1s[tid] = w_p1[tid];
    if (tid < 256) b_a1s[tid] = b_a1[tid];
    if (tid < 64) {
        b_p1s[tid] = b_p1[tid]; b_p2s[tid] = b_p2[tid];
        b_a2s[tid] = b_a2[tid]; b_fcs[tid] = b_fc[tid];
    }
    float accY = 0.0f, accY2 = 0.0f;
    __syncthreads();

    for (int g = blockIdx.x; g < NPTS/PTS; g += ATTN_GRID) {
        int pbase = g * PTS;
        int bofs = (pbase >> 12) << 12;

        // ---- A: per-point loads
        if (tid < 128) sidx[tid] = g_idx[pbase*KK + tid];
        {
            int l = tid >> 6, d = tid & 63;
            qs[tid] = g_qkv[(size_t)(pbase + l)*192 + d];
        }
        if (tid < 24) {
            int l = tid / 3, c = tid - l*3;
            p0s[l*4 + c] = pos[(size_t)(pbase + l)*3 + c];
        }
        __syncthreads();

        // ---- B: rel
        if (tid < 384) {
            int r = tid / 3, c = tid - r*3;
            int l = r >> 4;
            rel[tid] = p0s[l*4 + c] - pos[(size_t)(bofs + sidx[r])*3 + c];
        }
        __syncthreads();

        // ---- C: pos-MLP -> t1 (bf16 split tiles)
#pragma unroll
        for (int e = 0; e < 8; e++) {
            int i = tid + e*512;              // 4096 pairs
            int r = i >> 5, kp = i & 31;
            int pp = kp*2;
            float r0v = rel[r*3+0], r1v = rel[r*3+1], r2v = rel[r*3+2];
            float a0 = b_p1s[pp];
            a0 = fmaf(r0v, w_p1s[pp],        a0);
            a0 = fmaf(r1v, w_p1s[64 + pp],   a0);
            a0 = fmaf(r2v, w_p1s[128 + pp],  a0);
            float a1 = b_p1s[pp+1];
            a1 = fmaf(r0v, w_p1s[pp+1],      a1);
            a1 = fmaf(r1v, w_p1s[64 + pp+1], a1);
            a1 = fmaf(r2v, w_p1s[128 + pp+1],a1);
            a0 = fmaxf(a0, 0.0f); a1 = fmaxf(a1, 0.0f);
            u32 hi, lo;
            split2(a0, a1, hi, lo);
            t1hi[r*H2P + kp] = hi;
            t1lo[r*H2P + kp] = lo;
        }
        __syncthreads();

        // ---- D: p2 on MMA + qk gather in C-frag positions -> h2
        {
            u32 pahi[16], palo[16];
            int rowA = mtp*16 + g4;
#pragma unroll
            for (int ks = 0; ks < 4; ks++) {
                int c = ks*8 + t4;
                pahi[ks*4+0] = t1hi[rowA*H2P + c];
                pahi[ks*4+1] = t1hi[(rowA+8)*H2P + c];
                pahi[ks*4+2] = t1hi[rowA*H2P + c + 4];
                pahi[ks*4+3] = t1hi[(rowA+8)*H2P + c + 4];
                palo[ks*4+0] = t1lo[rowA*H2P + c];
                palo[ks*4+1] = t1lo[(rowA+8)*H2P + c];
                palo[ks*4+2] = t1lo[rowA*H2P + c + 4];
                palo[ks*4+3] = t1lo[(rowA+8)*H2P + c + 4];
            }
            float cP[16];
#pragma unroll
            for (int z = 0; z < 16; z++) cP[z] = 0.0f;
#pragma unroll
            for (int ntl = 0; ntl < 4; ntl++) {
                int nsw = (nh*32 + ntl*8 + g4) ^ (t4 << 3);
#pragma unroll
                for (int ks = 0; ks < 4; ks++) {
                    int kp0 = ks*8 + t4;
                    u32 bh0 = w2phi[kp0*64 + nsw];
                    u32 bh1 = w2phi[(kp0+4)*64 + nsw];
                    u32 bl0 = w2plo[kp0*64 + nsw];
                    u32 bl1 = w2plo[(kp0+4)*64 + nsw];
                    mma16816(&cP[ntl*4], &pahi[ks*4], bh0, bh1);
                    mma16816(&cP[ntl*4], &pahi[ks*4], bl0, bl1);
                    mma16816(&cP[ntl*4], &palo[ks*4], bh0, bh1);
                }
            }
            int r1 = mtp*16 + g4, r2 = r1 + 8;
            const float* krow1 = g_qkv + (size_t)(bofs + sidx[r1])*192 + 64;
            const float* krow2 = g_qkv + (size_t)(bofs + sidx[r2])*192 + 64;
#pragma unroll
            for (int ntl = 0; ntl < 4; ntl++) {
                int cb = nh*32 + ntl*8 + t4*2;
                float2 k1 = *(const float2*)&krow1[cb];
                float2 k2 = *(const float2*)&krow2[cb];
                float2 q1 = *(const float2*)&qs[mtp*64 + cb];
                float bb0 = b_p2s[cb], bb1 = b_p2s[cb+1];
                float h10 = (q1.x - k1.x) + cP[ntl*4+0] + bb0;
                float h11 = (q1.y - k1.y) + cP[ntl*4+1] + bb1;
                float h20 = (q1.x - k2.x) + cP[ntl*4+2] + bb0;
                float h21 = (q1.y - k2.y) + cP[ntl*4+3] + bb1;
                int kp = cb >> 1;
                u32 hi, lo;
                split2(h10, h11, hi, lo);
                h2hi[r1*H2P + kp] = hi; h2lo[r1*H2P + kp] = lo;
                split2(h20, h21, hi, lo);
                h2hi[r2*H2P + kp] = hi; h2lo[r2*H2P + kp] = lo;
            }
        }
        __syncthreads();

        // ---- E: load A1 fragments (h2) for this warp's m-tile
        u32 ahi[16], alo[16];
        {
            int rowA = mt*16 + g4;
#pragma unroll
            for (int ks = 0; ks < 4; ks++) {
                int c = ks*8 + t4;
                ahi[ks*4+0] = h2hi[rowA*H2P + c];
                ahi[ks*4+1] = h2hi[(rowA+8)*H2P + c];
                ahi[ks*4+2] = h2hi[rowA*H2P + c + 4];
                ahi[ks*4+3] = h2hi[(rowA+8)*H2P + c + 4];
                alo[ks*4+0] = h2lo[rowA*H2P + c];
                alo[ks*4+1] = h2lo[(rowA+8)*H2P + c];
                alo[ks*4+2] = h2lo[rowA*H2P + c + 4];
                alo[ks*4+3] = h2lo[(rowA+8)*H2P + c + 4];
            }
        }

        // ---- F: chunked attn MLP on tensor cores (sync-free)
        float C2[32];
#pragma unroll
        for (int z = 0; z < 32; z++) C2[z] = 0.0f;

#pragma unroll
        for (int jc = 0; jc < 4; jc++) {
            u32 s2hi[8], s2lo[8];
#pragma unroll
            for (int u = 0; u < 2; u++) {
                float cA[4] = {0,0,0,0}, cB[4] = {0,0,0,0};
                int nbase = jc*64 + hf*32 + u*16;
                int nswA = (nbase + g4) ^ (t4 << 3);
                int nswB = (nbase + 8 + g4) ^ (t4 << 3);
#pragma unroll
                for (int ks = 0; ks < 4; ks++) {
                    int kp0 = ks*8 + t4;
                    u32 bh0 = w1hi[kp0*256 + nswA];
                    u32 bh1 = w1hi[(kp0+4)*256 + nswA];
                    u32 bl0 = w1lo[kp0*256 + nswA];
                    u32 bl1 = w1lo[(kp0+4)*256 + nswA];
                    mma16816(cA, &ahi[ks*4], bh0, bh1);
                    mma16816(cA, &ahi[ks*4], bl0, bl1);
                    mma16816(cA, &alo[ks*4], bh0, bh1);
                    u32 ch0 = w1hi[kp0*256 + nswB];
                    u32 ch1 = w1hi[(kp0+4)*256 + nswB];
                    u32 cl0 = w1lo[kp0*256 + nswB];
                    u32 cl1 = w1lo[(kp0+4)*256 + nswB];
                    mma16816(cB, &ahi[ks*4], ch0, ch1);
                    mma16816(cB, &ahi[ks*4], cl0, cl1);
                    mma16816(cB, &alo[ks*4], ch0, ch1);
                }
                int cb = nbase + t4*2;
                float bA0 = b_a1s[cb],   bA1 = b_a1s[cb+1];
                float bB0 = b_a1s[cb+8], bB1 = b_a1s[cb+9];
                float sA0 = fmaxf(cA[0] + bA0, 0.0f);
                float sA1 = fmaxf(cA[1] + bA1, 0.0f);
                float sA2 = fmaxf(cA[2] + bA0, 0.0f);
                float sA3 = fmaxf(cA[3] + bA1, 0.0f);
                float sB0 = fmaxf(cB[0] + bB0, 0.0f);
                float sB1 = fmaxf(cB[1] + bB1, 0.0f);
                float sB2 = fmaxf(cB[2] + bB0, 0.0f);
                float sB3 = fmaxf(cB[3] + bB1, 0.0f);
                split2(sA0, sA1, s2hi[u*4+0], s2lo[u*4+0]);
                split2(sA2, sA3, s2hi[u*4+1], s2lo[u*4+1]);
                split2(sB0, sB1, s2hi[u*4+2], s2lo[u*4+2]);
                split2(sB2, sB3, s2hi[u*4+3], s2lo[u*4+3]);
            }
#pragma unroll
            for (int nt = 0; nt < 8; nt++) {
#pragma unroll
                for (int u = 0; u < 2; u++) {
                    int kp = jc*32 + hf*16 + u*8 + t4;
                    int nsw = (nt*8 + g4) ^ (t4 << 3);
                    u32 bh0 = w2hi[kp*64 + nsw];
                    u32 bh1 = w2hi[(kp+4)*64 + nsw];
                    u32 bl0 = w2lo[kp*64 + nsw];
                    u32 bl1 = w2lo[(kp+4)*64 + nsw];
                    mma16816(&C2[nt*4], &s2hi[u*4], bh0, bh1);
                    mma16816(&C2[nt*4], &s2hi[u*4], bl0, bl1);
                    mma16816(&C2[nt*4], &s2lo[u*4], bh0, bh1);
                }
            }
        }

        // ---- cross-half reduction of scores (stage in t1 region)
        if (hf) {
            float* sp = stage + mt*1056 + lane*33;
#pragma unroll
            for (int z = 0; z < 32; z++) sp[z] = C2[z];
        }
        __syncthreads();
        if (!hf) {
            float* sp = stage + mt*1056 + lane*33;
#pragma unroll
            for (int nt = 0; nt < 8; nt++) {
                int cb = nt*8 + t4*2;
                float v0 = C2[nt*4+0] + sp[nt*4+0] + b_a2s[cb];
                float v1 = C2[nt*4+1] + sp[nt*4+1] + b_a2s[cb+1];
                float v2 = C2[nt*4+2] + sp[nt*4+2] + b_a2s[cb];
                float v3 = C2[nt*4+3] + sp[nt*4+3] + b_a2s[cb+1];
                scores[(mt*16 + g4)*SCP + cb]         = v0;
                scores[(mt*16 + g4)*SCP + cb + 1]     = v1;
                scores[(mt*16 + g4 + 8)*SCP + cb]     = v2;
                scores[(mt*16 + g4 + 8)*SCP + cb + 1] = v3;
            }
        }
        __syncthreads();

        // ---- G: softmax over K + weighted v-sum (v from L2)
        {
            int l = tid >> 6, d = tid & 63;
            float vreg[16];
#pragma unroll
            for (int k = 0; k < 16; k++)
                vreg[k] = g_qkv[(size_t)(bofs + sidx[l*16 + k])*192 + 128 + d];
            float mx = -3.0e38f;
#pragma unroll
            for (int k = 0; k < 16; k++)
                mx = fmaxf(mx, scores[(l*16 + k)*SCP + d]);
            float ssum = 0.0f, a = 0.0f;
#pragma unroll
            for (int k = 0; k < 16; k++) {
                float e = __expf(scores[(l*16 + k)*SCP + d] - mx);
                ssum += e;
                a = fmaf(e, vreg[k], a);
            }
            aggs[tid] = a / ssum;
        }
        __syncthreads();

        // ---- H: fc (w_fc via L1/L2) + BN partials
        {
            int l = tid >> 6, d = tid & 63;
            float y = b_fcs[d];
#pragma unroll 8
            for (int c = 0; c < 64; c++)
                y = fmaf(aggs[l*64 + c], w_fc[c*64 + d], y);
            g_y[(size_t)(pbase + l)*64 + d] = y;
            accY += y;
            accY2 = fmaf(y, y, accY2);
        }
        __syncthreads();
    }

    // ---- reduce BN partials (t1 region as scratch)
    float* red = (float*)t1hi;
    red[tid] = accY;
    __syncthreads();
    if (tid < 64) {
        float s = 0.0f;
#pragma unroll
        for (int q = 0; q < 8; q++) s += red[q*64 + tid];
        g_part[blockIdx.x*128 + tid] = s;
    }
    __syncthreads();
    red[tid] = accY2;
    __syncthreads();
    if (tid < 64) {
        float s = 0.0f;
#pragma unroll
        for (int q = 0; q < 8; q++) s += red[q*64 + tid];
        g_part[blockIdx.x*128 + 64 + tid] = s;
    }
}

// ---------------- kernel 4: finish BN statistics ----------------------------
__global__ void bnstats_kernel() {
    __shared__ float sred[2048];
    int tid = threadIdx.x;            // 1024
    int d = tid & 63, q = tid >> 6;   // 16 groups
    float s = 0.0f, s2 = 0.0f;
    for (int blk = q; blk < ATTN_GRID; blk += 16) {
        s  += g_part[blk*128 + d];
        s2 += g_part[blk*128 + 64 + d];
    }
    sred[tid] = s; sred[1024 + tid] = s2;
    __syncthreads();
    if (tid < 64) {
        float ts = 0.0f, ts2 = 0.0f;
#pragma unroll
        for (int k = 0; k < 16; k++) {
            ts  += sred[k*64 + d];
            ts2 += sred[1024 + k*64 + d];
        }
        float mean = ts / (float)NPTS;
        float var  = ts2 / (float)NPTS - mean*mean;
        g_mv[d]      = mean;
        g_mv[64 + d] = rsqrtf(var + 1e-5f);
    }
}

// ---------------- kernel 5: BN apply + relu + residual ----------------------
__global__ void final_kernel(const float* __restrict__ x,
                             const float* __restrict__ gamma,
                             const float* __restrict__ beta,
                             float* __restrict__ out) {
    int i = blockIdx.x * blockDim.x + threadIdx.x;
    if (i < NPTS*DD) {
        int d = i & 63;
        float yv = (g_y[i] - g_mv[d]) * g_mv[64 + d] * gamma[d] + beta[d];
        out[i] = fmaxf(yv, 0.0f) + x[i];
    }
}

// ---------------- launch -----------------------------------------------------
extern "C" void kernel_launch(void* const* d_in, const int* in_sizes, int n_in,
                              void* d_out, int out_size) {
    const float* x     = (const float*)d_in[0];
    const float* pos   = (const float*)d_in[1];
    const float* w_qkv = (const float*)d_in[2];
    const float* b_qkv = (const float*)d_in[3];
    const float* w_p1  = (const float*)d_in[4];
    const float* b_p1  = (const float*)d_in[5];
    const float* w_p2  = (const float*)d_in[6];
    const float* b_p2  = (const float*)d_in[7];
    const float* w_a1  = (const float*)d_in[8];
    const float* b_a1  = (const float*)d_in[9];
    const float* w_a2  = (const float*)d_in[10];
    const float* b_a2  = (const float*)d_in[11];
    const float* w_fc  = (const float*)d_in[12];
    const float* b_fc  = (const float*)d_in[13];
    const float* gamma = (const float*)d_in[14];
    const float* beta  = (const float*)d_in[15];
    float* out = (float*)d_out;

    const int smem_qkv  = (64*192 + 64*64) * 4;
    const int smem_attn = (8192*4 + 2048*2 + 4608*4
                           + 512 + 32 + 384 + 512
                           + 64 + 64 + 256 + 64 + 64 + 192 + 128) * 4;  // 230272 B

    cudaFuncSetAttribute(qkv_kernel,  cudaFuncAttributeMaxDynamicSharedMemorySize, smem_qkv);
    cudaFuncSetAttribute(attn_kernel, cudaFuncAttributeMaxDynamicSharedMemorySize, smem_attn);

    bincount_kernel<<<NPTS/256, 256>>>(pos);            // 0
    binprefix_kernel<<<1, 1024>>>();                    // 1
    binscatter_kernel<<<NPTS/256, 256>>>(pos);          // 2
    knn_kernel<<<NPTS/8, 256>>>(pos);                   // 3 <- ncu capture slot
    qkv_kernel<<<NPTS/64, 192, smem_qkv>>>(x, w_qkv, b_qkv);
    attn_kernel<<<ATTN_GRID, 512, smem_attn>>>(x ? pos : pos, w_p1, b_p1, w_p2, b_p2,
                                               w_a1, b_a1, w_a2, b_a2, w_fc, b_fc);
    bnstats_kernel<<<1, 1024>>>();
    final_kernel<<<(NPTS*DD + 255)/256, 256>>>(x, gamma, beta, out);
}